// round 14
// baseline (speedup 1.0000x reference)
#include <cuda_runtime.h>
#include <math.h>
#include <stdint.h>

// Problem dims
#define NB 16
#define NP 8192
#define NG 512
#define NK 32
#define ND 384
#define NL 12
#define NH 6
#define BGc (NB*NG)      /* 8192 */
#define M1  (BGc*NK)     /* 262144 */

// ---------------- scratch layout ----------------
constexpr size_t O_PK  = 0;
constexpr size_t O_F   = O_PK  + (size_t)M1*128;
constexpr size_t O_H3  = O_F   + (size_t)M1*256;
constexpr size_t O_F4  = O_H3  + (size_t)M1*512;
constexpr size_t O_FG  = O_F4  + (size_t)M1*384;
constexpr size_t O_X   = O_FG  + (size_t)BGc*256;
constexpr size_t O_XIN = O_X   + (size_t)BGc*384;
constexpr size_t O_HLN = O_XIN + (size_t)BGc*384;
constexpr size_t O_OB  = O_HLN + (size_t)BGc*384;
constexpr size_t O_POS = O_OB  + (size_t)BGc*384;
constexpr size_t O_QKV = O_POS + (size_t)BGc*384;
constexpr size_t O_SC  = O_QKV + (size_t)BGc*1152;
constexpr size_t O_FF  = O_SC  + (size_t)96*512*512;
constexpr size_t O_CTR = O_FF  + (size_t)BGc*1536;
constexpr size_t O_ST  = O_CTR + (size_t)BGc*3;
constexpr size_t SCRATCH_TOTAL = O_ST + 4096;

__device__ float g_scratch[SCRATCH_TOTAL];

// packed weight sub-offsets (words, within O_PK)
constexpr size_t PK_QKV_HI  = 0;
constexpr size_t PK_QKV_LO  = PK_QKV_HI + (size_t)12*384*1152/2;
constexpr size_t PK_FC1_HI  = PK_QKV_LO + (size_t)12*384*1152/2;
constexpr size_t PK_FC1_LO  = PK_FC1_HI + (size_t)12*384*1536/2;
constexpr size_t PK_FC2_HI  = PK_FC1_LO + (size_t)12*384*1536/2;
constexpr size_t PK_FC2_LO  = PK_FC2_HI + (size_t)12*1536*384/2;
constexpr size_t PK_PROJ_HI = PK_FC2_LO + (size_t)12*1536*384/2;
constexpr size_t PK_PROJ_LO = PK_PROJ_HI + (size_t)12*384*384/2;
constexpr size_t PK_W2_HI   = PK_PROJ_LO + (size_t)12*384*384/2;
constexpr size_t PK_W2_LO   = PK_W2_HI + (size_t)128*256/2;
constexpr size_t PK_W3_HI   = PK_W2_LO + (size_t)128*256/2;
constexpr size_t PK_W3_LO   = PK_W3_HI + (size_t)512*512/2;
constexpr size_t PK_W4_HI   = PK_W3_LO + (size_t)512*512/2;
constexpr size_t PK_W4_LO   = PK_W4_HI + (size_t)512*384/2;

__device__ __forceinline__ float gelu_f(float x) {
    return 0.5f * x * (1.0f + erff(x * 0.70710678118654752f));
}

// ---------------- bf16 helpers ----------------
__device__ __forceinline__ void bf16x2_split(float x0, float x1, uint32_t& hi, uint32_t& lo) {
    uint32_t h;
    asm("cvt.rn.bf16x2.f32 %0, %1, %2;" : "=r"(h) : "f"(x1), "f"(x0));
    float h0 = __uint_as_float(h << 16);
    float h1 = __uint_as_float(h & 0xffff0000u);
    float r0 = x0 - h0, r1 = x1 - h1;
    asm("cvt.rn.bf16x2.f32 %0, %1, %2;" : "=r"(lo) : "f"(r1), "f"(r0));
    hi = h;
}

__device__ __forceinline__ void mma_bf16(float* d, const uint32_t* a, uint32_t b0, uint32_t b1) {
    asm volatile(
        "mma.sync.aligned.m16n8k16.row.col.f32.bf16.bf16.f32 "
        "{%0,%1,%2,%3}, {%4,%5,%6,%7}, {%8,%9}, {%0,%1,%2,%3};"
        : "+f"(d[0]), "+f"(d[1]), "+f"(d[2]), "+f"(d[3])
        : "r"(a[0]), "r"(a[1]), "r"(a[2]), "r"(a[3]), "r"(b0), "r"(b1));
}

#define AW 24
#define BUFW (4 * 128 * AW)
static constexpr int GE_SMEM   = 2 * BUFW * 4;                 /* 98304 B (NT=128) */
static constexpr int GE_SMEM64 = 2 * (6144 + 2 * 64 * AW) * 4; /* 73728 B (NT=64) */
static constexpr int QK_SMEM = BUFW * 4;
static constexpr int AV_SMEM = (3 * 128 * AW + 2 * 64 * AW) * 4;

// ---------------- merged weight prep ----------------
struct WJob { const float* W; uint32_t hi; uint32_t lo; int K; int N; int L; };
struct WJobs { WJob j[7]; };

__global__ void wprep_all_kernel(WJobs jobs, uint32_t* __restrict__ PK) {
    const WJob& jb = jobs.j[blockIdx.z];
    if ((int)blockIdx.y >= jb.L) return;
    const int K = jb.K, N = jb.N;
    int units = (K >> 5) * 2 * N;
    int u = blockIdx.x * 256 + threadIdx.x;
    if (u >= units) return;
    size_t lw = (size_t)blockIdx.y * K * N;
    size_t lp = lw >> 1;
    int n = u % N;
    int rem = u / N;
    int half = rem & 1;
    int kb = rem >> 1;
    const float* src = jb.W + lw + (size_t)(kb * 32 + half * 16) * N + n;
    uint32_t hw[8], lwd[8];
#pragma unroll
    for (int w = 0; w < 8; w++) {
        uint32_t h, l;
        bf16x2_split(src[(size_t)(2 * w) * N], src[(size_t)(2 * w + 1) * N], h, l);
        int slot = (w & 3) * 2 + (w >> 2);
        hw[slot] = h; lwd[slot] = l;
    }
    size_t off = lp + (size_t)kb * N * 16 + (size_t)half * N * 8 + (size_t)n * 8;
    uint32_t* Phi = PK + jb.hi;
    uint32_t* Plo = PK + jb.lo;
    *(uint4*)(Phi + off)     = *(uint4*)hw;
    *(uint4*)(Phi + off + 4) = *(uint4*)(hw + 4);
    *(uint4*)(Plo + off)     = *(uint4*)lwd;
    *(uint4*)(Plo + off + 4) = *(uint4*)(lwd + 4);
}

// ============ BF16x3 mma.sync GEMM, double-buffered, register-prefetched ============
template <int AMODE, int EPI, int NT>
__global__ void __launch_bounds__(256) mmagemm_kernel(
    const float* __restrict__ A,
    const uint32_t* __restrict__ PWhi, const uint32_t* __restrict__ PWlo,
    const float* __restrict__ bias, const float* __restrict__ res,
    float* __restrict__ C, int M, int N, int K,
    const float* __restrict__ q0, const float* __restrict__ q1,
    float* __restrict__ gout,
    const float* __restrict__ e1w, const float* __restrict__ e1b) {
    extern __shared__ uint32_t sm[];
    constexpr int NTT = NT / 16;
    constexpr int BUFN = 6144 + 2 * NT * AW;
    constexpr int NBV = (NT == 128) ? 4 : 2;

    const int tid = threadIdx.x;
    const int warp = tid >> 5, lane = tid & 31;
    const int row0 = blockIdx.y << 7, col0 = blockIdx.x * NT;
    const int wr = (warp & 3) << 5;
    const int wc = (warp >> 2) * (NT / 2);

    float d[2][NTT][4];
#pragma unroll
    for (int mt = 0; mt < 2; mt++)
#pragma unroll
        for (int nt = 0; nt < NTT; nt++)
#pragma unroll
            for (int i = 0; i < 4; i++) d[mt][nt][i] = 0.f;

    const int arow = tid >> 1;
    const int akoff = (tid & 1) << 4;
    const int grow = row0 + arow;
    const int lg = lane >> 2;
    const int lt = lane & 3;

    // AMODE 3: row coordinates are loop-invariant
    float nx0 = 0.f, nx1 = 0.f, nx2 = 0.f;
    if (AMODE == 3) {
        nx0 = A[(size_t)grow * 3];
        nx1 = A[(size_t)grow * 3 + 1];
        nx2 = A[(size_t)grow * 3 + 2];
    }

    // prefetch registers
    float av[16];
    uint4 pb[NBV];

    auto loadA = [&](int kb) {
        const int kg = (kb << 5) + akoff;
        if (AMODE == 3) {
#pragma unroll
            for (int c = 0; c < 16; c++) {
                float h = fmaf(nx2, e1w[256 + kg + c],
                          fmaf(nx1, e1w[128 + kg + c],
                          fmaf(nx0, e1w[kg + c], e1b[kg + c])));
                av[c] = fmaxf(fmaf(h, q0[kg + c], q1[kg + c]), 0.f);
            }
        } else {
            const float* src = A + (size_t)grow * K + kg;
#pragma unroll
            for (int i = 0; i < 4; i++) *(float4*)&av[i * 4] = *(const float4*)&src[i * 4];
        }
    };
    auto loadB = [&](int kb) {
        if (NT == 128) {
            const int bn = tid & 127;
            const int bkhalf = tid >> 7;
            size_t off = (size_t)kb * ((size_t)N * 16) + (size_t)bkhalf * N * 8 +
                         (size_t)(col0 + bn) * 8;
            pb[0] = *(const uint4*)(PWhi + off);
            pb[1] = *(const uint4*)(PWhi + off + 4);
            pb[2] = *(const uint4*)(PWlo + off);
            pb[3] = *(const uint4*)(PWlo + off + 4);
        } else {
            const int bn = tid & 63;
            const int bkhalf = (tid >> 6) & 1;
            const int bq = tid >> 7;
            size_t off = (size_t)kb * ((size_t)N * 16) + (size_t)bkhalf * N * 8 +
                         (size_t)(col0 + bn) * 8 + bq * 4;
            pb[0] = *(const uint4*)(PWhi + off);
            pb[1] = *(const uint4*)(PWlo + off);
        }
    };
    auto store = [&](int kb, uint32_t* base) {
        uint32_t* Ahi = base;
        uint32_t* Alo = base + 3072;
        uint32_t* Bhi = base + 6144;
        uint32_t* Blo = base + 6144 + NT * AW;
        {
            const int kg = (kb << 5) + akoff;
            if (AMODE == 1) {
#pragma unroll
                for (int c = 0; c < 16; c++)
                    av[c] = fmaxf(fmaf(av[c], q0[kg + c], q1[kg + c]), 0.f);
            }
            uint32_t* ah = Ahi + arow * AW + (akoff >> 4) * 8;
            uint32_t* al = Alo + arow * AW + (akoff >> 4) * 8;
#pragma unroll
            for (int u = 0; u < 4; u++) {
                uint32_t h1, l1, h2, l2;
                bf16x2_split(av[2 * u], av[2 * u + 1], h1, l1);
                bf16x2_split(av[2 * u + 8], av[2 * u + 9], h2, l2);
                *(uint2*)(ah + 2 * u) = make_uint2(h1, h2);
                *(uint2*)(al + 2 * u) = make_uint2(l1, l2);
            }
        }
        if (NT == 128) {
            const int bn = tid & 127;
            const int bkhalf = tid >> 7;
            uint32_t* bh = Bhi + bn * AW + bkhalf * 8;
            uint32_t* bl = Blo + bn * AW + bkhalf * 8;
            *(uint4*)bh       = pb[0];
            *(uint4*)(bh + 4) = pb[1];
            *(uint4*)bl       = pb[2];
            *(uint4*)(bl + 4) = pb[3];
        } else {
            const int bn = tid & 63;
            const int bkhalf = (tid >> 6) & 1;
            const int bq = tid >> 7;
            *(uint4*)(Bhi + bn * AW + bkhalf * 8 + bq * 4) = pb[0];
            *(uint4*)(Blo + bn * AW + bkhalf * 8 + bq * 4) = pb[1];
        }
    };

    auto compute = [&](const uint32_t* base) {
        const uint32_t* Ahi = base;
        const uint32_t* Alo = base + 3072;
        const uint32_t* Bhi = base + 6144;
        const uint32_t* Blo = base + 6144 + NT * AW;
#pragma unroll
        for (int b16 = 0; b16 < 2; b16++) {
            const int bo = b16 * 8 + 2 * lt;
            uint32_t ah[2][4], al[2][4];
#pragma unroll
            for (int mt = 0; mt < 2; mt++) {
                const int r1 = wr + mt * 16 + lg;
                uint2 t0 = *(const uint2*)(Ahi + r1 * AW + bo);
                uint2 t1 = *(const uint2*)(Ahi + (r1 + 8) * AW + bo);
                ah[mt][0] = t0.x; ah[mt][1] = t1.x; ah[mt][2] = t0.y; ah[mt][3] = t1.y;
                uint2 s0 = *(const uint2*)(Alo + r1 * AW + bo);
                uint2 s1 = *(const uint2*)(Alo + (r1 + 8) * AW + bo);
                al[mt][0] = s0.x; al[mt][1] = s1.x; al[mt][2] = s0.y; al[mt][3] = s1.y;
            }
#pragma unroll
            for (int nt = 0; nt < NTT; nt++) {
                const int n = wc + nt * 8 + lg;
                uint2 bh = *(const uint2*)(Bhi + n * AW + bo);
                uint2 bl = *(const uint2*)(Blo + n * AW + bo);
#pragma unroll
                for (int mt = 0; mt < 2; mt++) {
                    mma_bf16(d[mt][nt], ah[mt], bh.x, bh.y);
                    mma_bf16(d[mt][nt], al[mt], bh.x, bh.y);
                    mma_bf16(d[mt][nt], ah[mt], bl.x, bl.y);
                }
            }
        }
    };

    const int nblk = K >> 5;
    loadA(0); loadB(0);
    store(0, sm);
    __syncthreads();
    for (int kb = 0; kb < nblk; kb++) {
        if (kb + 1 < nblk) { loadA(kb + 1); loadB(kb + 1); }
        compute(sm + (kb & 1) * BUFN);
        if (kb + 1 < nblk) store(kb + 1, sm + ((kb + 1) & 1) * BUFN);
        __syncthreads();
    }

    const int g = (row0 + wr) >> 5;

    if (EPI <= 3 || EPI == 5) {
#pragma unroll
        for (int mt = 0; mt < 2; mt++) {
            const int r1 = row0 + wr + mt * 16 + lg;
            const int r2 = r1 + 8;
#pragma unroll
            for (int nt = 0; nt < NTT; nt++) {
                const int c = col0 + wc + nt * 8 + lt * 2;
                float v0 = d[mt][nt][0], v1 = d[mt][nt][1];
                float v2 = d[mt][nt][2], v3 = d[mt][nt][3];
                if (bias) {
                    float b0 = bias[c], b1 = bias[c + 1];
                    v0 += b0; v1 += b1; v2 += b0; v3 += b1;
                }
                if (EPI == 1) {
                    v0 += res[(size_t)r1 * N + c];
                    v1 += res[(size_t)r1 * N + c + 1];
                    v2 += res[(size_t)r2 * N + c];
                    v3 += res[(size_t)r2 * N + c + 1];
                } else if (EPI == 3) {
                    float g0 = res[(size_t)g * N + c];
                    float g1 = res[(size_t)g * N + c + 1];
                    v0 += g0; v1 += g1; v2 += g0; v3 += g1;
                } else if (EPI == 2) {
                    v0 = gelu_f(v0); v1 = gelu_f(v1); v2 = gelu_f(v2); v3 = gelu_f(v3);
                }
                C[(size_t)r1 * N + c]     = v0;
                C[(size_t)r1 * N + c + 1] = v1;
                C[(size_t)r2 * N + c]     = v2;
                C[(size_t)r2 * N + c + 1] = v3;
            }
        }
    }

    if (EPI >= 4) {
#pragma unroll
        for (int nt = 0; nt < NTT; nt++) {
            const int c = col0 + wc + nt * 8 + lt * 2;
            float m0v = fmaxf(fmaxf(d[0][nt][0], d[0][nt][2]),
                              fmaxf(d[1][nt][0], d[1][nt][2]));
            float m1v = fmaxf(fmaxf(d[0][nt][1], d[0][nt][3]),
                              fmaxf(d[1][nt][1], d[1][nt][3]));
#pragma unroll
            for (int o = 4; o <= 16; o <<= 1) {
                m0v = fmaxf(m0v, __shfl_xor_sync(0xFFFFFFFFu, m0v, o));
                m1v = fmaxf(m1v, __shfl_xor_sync(0xFFFFFFFFu, m1v, o));
            }
            if (lane < 4) {
                if (bias) { m0v += bias[c]; m1v += bias[c + 1]; }
                float* gp = (EPI == 5) ? gout : C;
                gp[(size_t)g * N + c]     = m0v;
                gp[(size_t)g * N + c + 1] = m1v;
            }
        }
    }
}

// ============ attention QK ============
__global__ void __launch_bounds__(256) attn_qk_mma(const float* __restrict__ qkv,
                                                   float* __restrict__ S) {
    extern __shared__ uint32_t sm[];
    uint32_t* Ahi = sm;
    uint32_t* Alo = sm + 3072;
    uint32_t* Bhi = sm + 6144;
    uint32_t* Blo = sm + 9216;
    const int z = blockIdx.z;
    const int b = z / NH, h = z - b * NH;
    const float* Qb = qkv + (size_t)b * NG * 1152 + h * 64;
    const float* Kb = Qb + 384;
    const int m0 = blockIdx.y << 7, n0 = blockIdx.x << 7;
    const int tid = threadIdx.x;
    const int warp = tid >> 5, lane = tid & 31;
    const int wr = (warp & 3) << 5, wc = (warp >> 2) << 6;
    const int arow = tid >> 1, akoff = (tid & 1) << 4;
    const int lg = lane >> 2, lt = lane & 3;

    float d[2][8][4];
#pragma unroll
    for (int mt = 0; mt < 2; mt++)
#pragma unroll
        for (int nt = 0; nt < 8; nt++)
#pragma unroll
            for (int i = 0; i < 4; i++) d[mt][nt][i] = 0.f;

#pragma unroll
    for (int kb = 0; kb < 2; kb++) {
        const int kg = (kb << 5) + akoff;
        {
            const float* src = Qb + (size_t)(m0 + arow) * 1152 + kg;
            uint32_t* ah = Ahi + arow * AW + (akoff >> 4) * 8;
            uint32_t* al = Alo + arow * AW + (akoff >> 4) * 8;
            float v[16];
#pragma unroll
            for (int i = 0; i < 4; i++) *(float4*)&v[i * 4] = *(const float4*)&src[i * 4];
#pragma unroll
            for (int u = 0; u < 4; u++) {
                uint32_t h1, l1, h2, l2;
                bf16x2_split(v[2 * u], v[2 * u + 1], h1, l1);
                bf16x2_split(v[2 * u + 8], v[2 * u + 9], h2, l2);
                *(uint2*)(ah + 2 * u) = make_uint2(h1, h2);
                *(uint2*)(al + 2 * u) = make_uint2(l1, l2);
            }
        }
        {
            const float* src = Kb + (size_t)(n0 + arow) * 1152 + kg;
            uint32_t* bh = Bhi + arow * AW + (akoff >> 4) * 8;
            uint32_t* bl = Blo + arow * AW + (akoff >> 4) * 8;
            float v[16];
#pragma unroll
            for (int i = 0; i < 4; i++) *(float4*)&v[i * 4] = *(const float4*)&src[i * 4];
#pragma unroll
            for (int u = 0; u < 4; u++) {
                uint32_t h1, l1, h2, l2;
                bf16x2_split(v[2 * u], v[2 * u + 1], h1, l1);
                bf16x2_split(v[2 * u + 8], v[2 * u + 9], h2, l2);
                *(uint2*)(bh + 2 * u) = make_uint2(h1, h2);
                *(uint2*)(bl + 2 * u) = make_uint2(l1, l2);
            }
        }
        __syncthreads();
#pragma unroll
        for (int b16 = 0; b16 < 2; b16++) {
            const int bo = b16 * 8 + 2 * lt;
            uint32_t ah[2][4], al[2][4];
#pragma unroll
            for (int mt = 0; mt < 2; mt++) {
                const int r1 = wr + mt * 16 + lg;
                uint2 t0 = *(const uint2*)(Ahi + r1 * AW + bo);
                uint2 t1 = *(const uint2*)(Ahi + (r1 + 8) * AW + bo);
                ah[mt][0] = t0.x; ah[mt][1] = t1.x; ah[mt][2] = t0.y; ah[mt][3] = t1.y;
                uint2 s0 = *(const uint2*)(Alo + r1 * AW + bo);
                uint2 s1 = *(const uint2*)(Alo + (r1 + 8) * AW + bo);
                al[mt][0] = s0.x; al[mt][1] = s1.x; al[mt][2] = s0.y; al[mt][3] = s1.y;
            }
#pragma unroll
            for (int nt = 0; nt < 8; nt++) {
                const int n = wc + nt * 8 + lg;
                uint2 bh = *(const uint2*)(Bhi + n * AW + bo);
                uint2 bl = *(const uint2*)(Blo + n * AW + bo);
#pragma unroll
                for (int mt = 0; mt < 2; mt++) {
                    mma_bf16(d[mt][nt], ah[mt], bh.x, bh.y);
                    mma_bf16(d[mt][nt], al[mt], bh.x, bh.y);
                    mma_bf16(d[mt][nt], ah[mt], bl.x, bl.y);
                }
            }
        }
        __syncthreads();
    }
    float* out = S + (size_t)z * 512 * 512;
#pragma unroll
    for (int mt = 0; mt < 2; mt++) {
        const int r1 = m0 + wr + mt * 16 + lg;
        const int r2 = r1 + 8;
#pragma unroll
        for (int nt = 0; nt < 8; nt++) {
            const int c = n0 + wc + nt * 8 + lt * 2;
            out[(size_t)r1 * 512 + c]     = d[mt][nt][0] * 0.125f;
            out[(size_t)r1 * 512 + c + 1] = d[mt][nt][1] * 0.125f;
            out[(size_t)r2 * 512 + c]     = d[mt][nt][2] * 0.125f;
            out[(size_t)r2 * 512 + c + 1] = d[mt][nt][3] * 0.125f;
        }
    }
}

// ============ softmax: one warp per 512-col row ============
__global__ void __launch_bounds__(256) softmax_kernel(float* __restrict__ S) {
    const int warp = threadIdx.x >> 5, lane = threadIdx.x & 31;
    const size_t row = (size_t)blockIdx.x * 8 + warp;
    float* p = S + row * 512;
    float v[16];
#pragma unroll
    for (int j = 0; j < 4; j++)
        *(float4*)&v[j * 4] = *(const float4*)&p[lane * 4 + j * 128];
    float m = v[0];
#pragma unroll
    for (int j = 1; j < 16; j++) m = fmaxf(m, v[j]);
#pragma unroll
    for (int o = 16; o; o >>= 1) m = fmaxf(m, __shfl_xor_sync(0xFFFFFFFFu, m, o));
    float s = 0.f;
#pragma unroll
    for (int j = 0; j < 16; j++) { v[j] = expf(v[j] - m); s += v[j]; }
#pragma unroll
    for (int o = 16; o; o >>= 1) s += __shfl_xor_sync(0xFFFFFFFFu, s, o);
    float inv = 1.0f / s;
#pragma unroll
    for (int j = 0; j < 16; j++) v[j] *= inv;
#pragma unroll
    for (int j = 0; j < 4; j++)
        *(float4*)&p[lane * 4 + j * 128] = *(float4*)&v[j * 4];
}

// ============ attention AV ============
__global__ void __launch_bounds__(256) attn_av_mma(const float* __restrict__ S,
                                                   const float* __restrict__ qkv,
                                                   float* __restrict__ O) {
    extern __shared__ uint32_t sm[];
    uint32_t* Ahi = sm;
    uint32_t* Alo = sm + 3072;
    uint32_t* Bhi = sm + 6144;
    uint32_t* Blo = sm + 6144 + 64 * AW;
    const int z = blockIdx.y;
    const int b = z / NH, h = z - b * NH;
    const float* A = S + (size_t)z * 512 * 512;
    const float* Vb = qkv + (size_t)b * NG * 1152 + 768 + h * 64;
    const int m0 = blockIdx.x << 7;
    const int tid = threadIdx.x;
    const int warp = tid >> 5, lane = tid & 31;
    const int wr = (warp & 3) << 5, wc = (warp >> 2) << 5;
    const int arow = tid >> 1, akoff = (tid & 1) << 4;
    const int bn = tid & 63, bhalf = (tid >> 6) & 1, brep = tid >> 7;
    const int lg = lane >> 2, lt = lane & 3;

    float d[2][4][4];
#pragma unroll
    for (int mt = 0; mt < 2; mt++)
#pragma unroll
        for (int nt = 0; nt < 4; nt++)
#pragma unroll
            for (int i = 0; i < 4; i++) d[mt][nt][i] = 0.f;

    for (int kb = 0; kb < 16; kb++) {
        const int kbase = kb << 5;
        {
            const float* src = A + (size_t)(m0 + arow) * 512 + kbase + akoff;
            uint32_t* ah = Ahi + arow * AW + (akoff >> 4) * 8;
            uint32_t* al = Alo + arow * AW + (akoff >> 4) * 8;
            float v[16];
#pragma unroll
            for (int i = 0; i < 4; i++) *(float4*)&v[i * 4] = *(const float4*)&src[i * 4];
#pragma unroll
            for (int u = 0; u < 4; u++) {
                uint32_t h1, l1, h2, l2;
                bf16x2_split(v[2 * u], v[2 * u + 1], h1, l1);
                bf16x2_split(v[2 * u + 8], v[2 * u + 9], h2, l2);
                *(uint2*)(ah + 2 * u) = make_uint2(h1, h2);
                *(uint2*)(al + 2 * u) = make_uint2(l1, l2);
            }
        }
        {
            uint32_t* bh = Bhi + bn * AW + bhalf * 8;
            uint32_t* bl = Blo + bn * AW + bhalf * 8;
#pragma unroll
            for (int p = 0; p < 4; p++) {
                const int k0 = kbase + bhalf * 16 + brep * 8 + 2 * p;
                float v0 = Vb[(size_t)k0 * 1152 + bn];
                float v1 = Vb[(size_t)(k0 + 1) * 1152 + bn];
                uint32_t hh, ll;
                bf16x2_split(v0, v1, hh, ll);
                bh[2 * p + brep] = hh;
                bl[2 * p + brep] = ll;
            }
        }
        __syncthreads();
#pragma unroll
        for (int b16 = 0; b16 < 2; b16++) {
            const int bo = b16 * 8 + 2 * lt;
            uint32_t ah[2][4], al[2][4];
#pragma unroll
            for (int mt = 0; mt < 2; mt++) {
                const int r1 = wr + mt * 16 + lg;
                uint2 t0 = *(const uint2*)(Ahi + r1 * AW + bo);
                uint2 t1 = *(const uint2*)(Ahi + (r1 + 8) * AW + bo);
                ah[mt][0] = t0.x; ah[mt][1] = t1.x; ah[mt][2] = t0.y; ah[mt][3] = t1.y;
                uint2 s0 = *(const uint2*)(Alo + r1 * AW + bo);
                uint2 s1 = *(const uint2*)(Alo + (r1 + 8) * AW + bo);
                al[mt][0] = s0.x; al[mt][1] = s1.x; al[mt][2] = s0.y; al[mt][3] = s1.y;
            }
#pragma unroll
            for (int nt = 0; nt < 4; nt++) {
                const int n = wc + nt * 8 + lg;
                uint2 bh = *(const uint2*)(Bhi + n * AW + bo);
                uint2 bl = *(const uint2*)(Blo + n * AW + bo);
#pragma unroll
                for (int mt = 0; mt < 2; mt++) {
                    mma_bf16(d[mt][nt], ah[mt], bh.x, bh.y);
                    mma_bf16(d[mt][nt], al[mt], bh.x, bh.y);
                    mma_bf16(d[mt][nt], ah[mt], bl.x, bl.y);
                }
            }
        }
        __syncthreads();
    }
    float* Ob = O + (size_t)b * NG * 384 + h * 64;
#pragma unroll
    for (int mt = 0; mt < 2; mt++) {
        const int r1 = m0 + wr + mt * 16 + lg;
        const int r2 = r1 + 8;
#pragma unroll
        for (int nt = 0; nt < 4; nt++) {
            const int c = wc + nt * 8 + lt * 2;
            Ob[(size_t)r1 * 384 + c]     = d[mt][nt][0];
            Ob[(size_t)r1 * 384 + c + 1] = d[mt][nt][1];
            Ob[(size_t)r2 * 384 + c]     = d[mt][nt][2];
            Ob[(size_t)r2 * 384 + c + 1] = d[mt][nt][3];
        }
    }
}

// ---------------- zero ----------------
__global__ void zero_kernel(float* p, int n) {
    int i = blockIdx.x * blockDim.x + threadIdx.x;
    if (i < n) p[i] = 0.0f;
}

// ---------------- FPS ----------------
__global__ void __launch_bounds__(1024) fps_kernel(const float* __restrict__ pts,
                                                   float* __restrict__ ctr,
                                                   float* __restrict__ ctr_out) {
    int b = blockIdx.x;
    int tid = threadIdx.x, wid = tid >> 5, lane = tid & 31;
    const float* P = pts + (size_t)b * NP * 3;
    float px[8], py[8], pz[8], dl[8];
#pragma unroll
    for (int t = 0; t < 8; t++) {
        int j = tid + t * 1024;
        px[t] = P[j * 3 + 0]; py[t] = P[j * 3 + 1]; pz[t] = P[j * 3 + 2];
        dl[t] = 1e10f;
    }
    __shared__ float lastp[3];
    __shared__ float wv_s[32];
    __shared__ int   wi_s[32];
    if (tid == 0) {
        lastp[0] = P[0]; lastp[1] = P[1]; lastp[2] = P[2];
        size_t co = (size_t)b * NG * 3;
        ctr[co] = P[0]; ctr[co + 1] = P[1]; ctr[co + 2] = P[2];
        ctr_out[co] = P[0]; ctr_out[co + 1] = P[1]; ctr_out[co + 2] = P[2];
    }
    __syncthreads();
    for (int s = 1; s < NG; s++) {
        float lx = lastp[0], ly = lastp[1], lz = lastp[2];
        float bv = -1.0f; int bi = 0;
#pragma unroll
        for (int t = 0; t < 8; t++) {
            float dx = __fsub_rn(px[t], lx);
            float dy = __fsub_rn(py[t], ly);
            float dz = __fsub_rn(pz[t], lz);
            float d = __fadd_rn(__fadd_rn(__fmul_rn(dx, dx), __fmul_rn(dy, dy)),
                                __fmul_rn(dz, dz));
            float nd = fminf(dl[t], d);
            dl[t] = nd;
            if (nd > bv) { bv = nd; bi = tid + t * 1024; }
        }
#pragma unroll
        for (int o = 16; o; o >>= 1) {
            float v2 = __shfl_xor_sync(0xFFFFFFFFu, bv, o);
            int   i2 = __shfl_xor_sync(0xFFFFFFFFu, bi, o);
            if (v2 > bv || (v2 == bv && i2 < bi)) { bv = v2; bi = i2; }
        }
        if (lane == 0) { wv_s[wid] = bv; wi_s[wid] = bi; }
        __syncthreads();
        if (wid == 0) {
            bv = wv_s[lane]; bi = wi_s[lane];
#pragma unroll
            for (int o = 16; o; o >>= 1) {
                float v2 = __shfl_xor_sync(0xFFFFFFFFu, bv, o);
                int   i2 = __shfl_xor_sync(0xFFFFFFFFu, bi, o);
                if (v2 > bv || (v2 == bv && i2 < bi)) { bv = v2; bi = i2; }
            }
            if (lane == 0) {
                float qx = P[bi * 3], qy = P[bi * 3 + 1], qz = P[bi * 3 + 2];
                lastp[0] = qx; lastp[1] = qy; lastp[2] = qz;
                size_t co = ((size_t)b * NG + s) * 3;
                ctr[co] = qx; ctr[co + 1] = qy; ctr[co + 2] = qz;
                ctr_out[co] = qx; ctr_out[co + 1] = qy; ctr_out[co + 2] = qz;
            }
        }
        __syncthreads();
    }
}

// ---------------- KNN: tournament argmin ----------------
__device__ __forceinline__ unsigned long long knn_key(float v, int idx) {
    uint32_t b = __float_as_uint(v);
    b = (b & 0x80000000u) ? ~b : (b | 0x80000000u);
    return ((unsigned long long)b << 32) | (uint32_t)idx;
}

__global__ void __launch_bounds__(256) knn_kernel(const float* __restrict__ pts,
                                                  const float* __restrict__ ctr,
                                                  float* __restrict__ nbr_out) {
    int bg = blockIdx.x;
    int b = bg >> 9;
    const float* P = pts + (size_t)b * NP * 3;
    float cx = ctr[bg * 3 + 0], cy = ctr[bg * 3 + 1], cz = ctr[bg * 3 + 2];
    float c2 = __fadd_rn(__fadd_rn(__fmul_rn(cx, cx), __fmul_rn(cy, cy)), __fmul_rn(cz, cz));
    __shared__ float d2s[NP];
    int tid = threadIdx.x;
    for (int j = tid; j < NP; j += 256) {
        float px = P[j * 3], py = P[j * 3 + 1], pz = P[j * 3 + 2];
        float p2 = __fadd_rn(__fadd_rn(__fmul_rn(px, px), __fmul_rn(py, py)), __fmul_rn(pz, pz));
        float dot = __fmaf_rn(cz, pz, __fmaf_rn(cy, py, __fmul_rn(cx, px)));
        d2s[j] = __fsub_rn(__fadd_rn(c2, p2), __fmul_rn(2.0f, dot));
    }
    __syncthreads();

    unsigned long long mykey = ~0ull;
#pragma unroll
    for (int t = 0; t < 32; t++) {
        int j = tid + t * 256;
        unsigned long long k = knn_key(d2s[j], j);
        if (k < mykey) mykey = k;
    }

    __shared__ unsigned long long wmin[8];
    __shared__ unsigned long long winner;
    __shared__ int chosen[NK];
    const int warp = tid >> 5, lane = tid & 31;

    for (int sel = 0; sel < NK; sel++) {
        unsigned long long k = mykey;
#pragma unroll
        for (int o = 16; o; o >>= 1) {
            unsigned long long k2 = __shfl_xor_sync(0xFFFFFFFFu, k, o);
            if (k2 < k) k = k2;
        }
        if (lane == 0) wmin[warp] = k;
        __syncthreads();
        if (tid == 0) {
            unsigned long long w = wmin[0];
#pragma unroll
            for (int i = 1; i < 8; i++) if (wmin[i] < w) w = wmin[i];
            winner = w;
            chosen[sel] = (int)(w & 0xffffffffu);
        }
        __syncthreads();
        int widx = (int)(winner & 0xffffffffu);
        if ((widx & 255) == tid) {
            d2s[widx] = 3.4e38f;
            mykey = ~0ull;
#pragma unroll
            for (int t = 0; t < 32; t++) {
                int j = tid + t * 256;
                unsigned long long kk = knn_key(d2s[j], j);
                if (kk < mykey) mykey = kk;
            }
        }
    }
    __syncthreads();
    if (tid < NK) {
        int j = chosen[tid];
        size_t o = ((size_t)bg * NK + tid) * 3;
        nbr_out[o + 0] = P[j * 3 + 0] - cx;
        nbr_out[o + 1] = P[j * 3 + 1] - cy;
        nbr_out[o + 2] = P[j * 3 + 2] - cz;
    }
}

// ---------------- nbr moments (analytic BN1) ----------------
__global__ void __launch_bounds__(256) moments_kernel(const float* __restrict__ nbr,
                                                      float* __restrict__ mom) {
    int t = blockIdx.x * 256 + threadIdx.x;
    float s[9];
#pragma unroll
    for (int i = 0; i < 9; i++) s[i] = 0.f;
    for (int r = t; r < M1; r += 65536) {
        float a = nbr[(size_t)r * 3], b = nbr[(size_t)r * 3 + 1], c = nbr[(size_t)r * 3 + 2];
        s[0] += a; s[1] += b; s[2] += c;
        s[3] += a * a; s[4] += b * b; s[5] += c * c;
        s[6] += a * b; s[7] += a * c; s[8] += b * c;
    }
#pragma unroll
    for (int i = 0; i < 9; i++)
#pragma unroll
        for (int o = 16; o; o >>= 1) s[i] += __shfl_xor_sync(0xFFFFFFFFu, s[i], o);
    __shared__ float sh[8][9];
    int wid = threadIdx.x >> 5, lane = threadIdx.x & 31;
    if (lane == 0)
#pragma unroll
        for (int i = 0; i < 9; i++) sh[wid][i] = s[i];
    __syncthreads();
    if (threadIdx.x < 9) {
        float a = 0.f;
#pragma unroll
        for (int w = 0; w < 8; w++) a += sh[w][threadIdx.x];
        atomicAdd(&mom[threadIdx.x], a);
    }
}

__global__ void bnfin1_kernel(const float* __restrict__ mom,
                              const float* __restrict__ w1, const float* __restrict__ b1,
                              const float* __restrict__ g, const float* __restrict__ bb,
                              float* __restrict__ scale, float* __restrict__ shift) {
    int c = threadIdx.x;
    float inv = 1.0f / (float)M1;
    float m0 = mom[0] * inv, m1 = mom[1] * inv, m2 = mom[2] * inv;
    float C00 = mom[3] * inv - m0 * m0;
    float C11 = mom[4] * inv - m1 * m1;
    float C22 = mom[5] * inv - m2 * m2;
    float C01 = mom[6] * inv - m0 * m1;
    float C02 = mom[7] * inv - m0 * m2;
    float C12 = mom[8] * inv - m1 * m2;
    float w0 = w1[c], wv1 = w1[128 + c], wv2 = w1[256 + c];
    float var = C00 * w0 * w0 + C11 * wv1 * wv1 + C22 * wv2 * wv2 +
                2.0f * (C01 * w0 * wv1 + C02 * w0 * wv2 + C12 * wv1 * wv2);
    float mean = m0 * w0 + m1 * wv1 + m2 * wv2 + b1[c];
    float r = rsqrtf(var + 1e-5f);
    float sc = g[c] * r;
    scale[c] = sc;
    shift[c] = bb[c] - mean * sc;
}

// ---------------- BN stats (h3) ----------------
__global__ void bnstats_kernel(const float* __restrict__ h, int C,
                               float* __restrict__ s1, float* __restrict__ s2) {
    int c = threadIdx.x;
    size_t r0 = (size_t)blockIdx.x * 512;
    const float* p = h + r0 * C + c;
    float a = 0.f, q = 0.f;
    for (int r = 0; r < 512; r++) {
        float v = p[(size_t)r * C];
        a += v; q += v * v;
    }
    atomicAdd(&s1[c], a);
    atomicAdd(&s2[c], q);
}

__global__ void bnfin_kernel(const float* __restrict__ s1, const float* __restrict__ s2,
                             float invM, const float* __restrict__ g, const float* __restrict__ b,
                             float* __restrict__ scale, float* __restrict__ shift) {
    int c = threadIdx.x;
    float mean = s1[c] * invM;
    float var = s2[c] * invM - mean * mean;
    float r = rsqrtf(var + 1e-5f);
    float sc = g[c] * r;
    scale[c] = sc;
    shift[c] = b[c] - mean * sc;
}

// ---------------- layernorm: one warp per 384-col row ----------------
__global__ void __launch_bounds__(256) ln_kernel(const float* __restrict__ in,
                                                 float* __restrict__ out,
                                                 const float* __restrict__ gg,
                                                 const float* __restrict__ bb) {
    const int warp = threadIdx.x >> 5, lane = threadIdx.x & 31;
    const size_t row = (size_t)blockIdx.x * 8 + warp;
    const float* p = in + row * 384;
    float v[12];
#pragma unroll
    for (int j = 0; j < 3; j++)
        *(float4*)&v[j * 4] = *(const float4*)&p[lane * 4 + j * 128];
    float s = 0.f;
#pragma unroll
    for (int j = 0; j < 12; j++) s += v[j];
#pragma unroll
    for (int o = 16; o; o >>= 1) s += __shfl_xor_sync(0xFFFFFFFFu, s, o);
    float mean = s * (1.0f / 384.0f);
    float q = 0.f;
#pragma unroll
    for (int j = 0; j < 12; j++) { v[j] -= mean; q += v[j] * v[j]; }
#pragma unroll
    for (int o = 16; o; o >>= 1) q += __shfl_xor_sync(0xFFFFFFFFu, q, o);
    float rstd = rsqrtf(q * (1.0f / 384.0f) + 1e-5f);
    float* op = out + row * 384;
#pragma unroll
    for (int j = 0; j < 3; j++) {
        float4 gv = *(const float4*)&gg[lane * 4 + j * 128];
        float4 bv = *(const float4*)&bb[lane * 4 + j * 128];
        float4 o4;
        o4.x = v[j * 4 + 0] * rstd * gv.x + bv.x;
        o4.y = v[j * 4 + 1] * rstd * gv.y + bv.y;
        o4.z = v[j * 4 + 2] * rstd * gv.z + bv.z;
        o4.w = v[j * 4 + 3] * rstd * gv.w + bv.w;
        *(float4*)&op[lane * 4 + j * 128] = o4;
    }
}

// xin = x + pos; out = LN(xin); one warp per row
__global__ void __launch_bounds__(256) ln_add_kernel(const float* __restrict__ x,
                                                     const float* __restrict__ pos,
                                                     float* __restrict__ xin,
                                                     float* __restrict__ out,
                                                     const float* __restrict__ gg,
                                                     const float* __restrict__ bb) {
    const int warp = threadIdx.x >> 5, lane = threadIdx.x & 31;
    const size_t row = (size_t)blockIdx.x * 8 + warp;
    const float* p = x + row * 384;
    const float* pp = pos + row * 384;
    float v[12];
#pragma unroll
    for (int j = 0; j < 3; j++) {
        float4 a = *(const float4*)&p[lane * 4 + j * 128];
        float4 b = *(const float4*)&pp[lane * 4 + j * 128];
        a.x += b.x; a.y += b.y; a.z += b.z; a.w += b.w;
        *(float4*)&v[j * 4] = a;
        *(float4*)&xin[row * 384 + lane * 4 + j * 128] = a;
    }
    float s = 0.f;
#pragma unroll
    for (int j = 0; j < 12; j++) s += v[j];
#pragma unroll
    for (int o = 16; o; o >>= 1) s += __shfl_xor_sync(0xFFFFFFFFu, s, o);
    float mean = s * (1.0f / 384.0f);
    float q = 0.f;
#pragma unroll
    for (int j = 0; j < 12; j++) { v[j] -= mean; q += v[j] * v[j]; }
#pragma unroll
    for (int o = 16; o; o >>= 1) q += __shfl_xor_sync(0xFFFFFFFFu, q, o);
    float rstd = rsqrtf(q * (1.0f / 384.0f) + 1e-5f);
    float* op = out + row * 384;
#pragma unroll
    for (int j = 0; j < 3; j++) {
        float4 gv = *(const float4*)&gg[lane * 4 + j * 128];
        float4 bv = *(const float4*)&bb[lane * 4 + j * 128];
        float4 o4;
        o4.x = v[j * 4 + 0] * rstd * gv.x + bv.x;
        o4.y = v[j * 4 + 1] * rstd * gv.y + bv.y;
        o4.z = v[j * 4 + 2] * rstd * gv.z + bv.z;
        o4.w = v[j * 4 + 3] * rstd * gv.w + bv.w;
        *(float4*)&op[lane * 4 + j * 128] = o4;
    }
}

// ---------------- pos embed ----------------
__global__ void __launch_bounds__(128) pos_kernel(const float* __restrict__ ctr,
                                                  const float* __restrict__ pw1,
                                                  const float* __restrict__ pb1,
                                                  const float* __restrict__ pw2,
                                                  const float* __restrict__ pb2,
                                                  float* __restrict__ pos) {
    int row = blockIdx.x;
    int tid = threadIdx.x;
    float cx = ctr[row * 3], cy = ctr[row * 3 + 1], cz = ctr[row * 3 + 2];
    __shared__ float t[128];
    float u = cx * pw1[tid] + cy * pw1[128 + tid] + cz * pw1[256 + tid] + pb1[tid];
    t[tid] = gelu_f(u);
    __syncthreads();
    for (int j = tid; j < 384; j += 128) {
        float s = pb2[j];
#pragma unroll 8
        for (int k = 0; k < 128; k++) s = fmaf(t[k], pw2[k * 384 + j], s);
        pos[(size_t)row * 384 + j] = s;
    }
}

// ---------------- host ----------------
extern "C" void kernel_launch(void* const* d_in, const int* in_sizes, int n_in,
                              void* d_out, int out_size) {
    const float* pts   = (const float*)d_in[0];
    const float* w1    = (const float*)d_in[1];
    const float* b1    = (const float*)d_in[2];
    const float* bn1g  = (const float*)d_in[3];
    const float* bn1b  = (const float*)d_in[4];
    const float* w2    = (const float*)d_in[5];
    const float* b2    = (const float*)d_in[6];
    const float* w3    = (const float*)d_in[7];
    const float* b3    = (const float*)d_in[8];
    const float* bn2g  = (const float*)d_in[9];
    const float* bn2b  = (const float*)d_in[10];
    const float* w4    = (const float*)d_in[11];
    const float* b4    = (const float*)d_in[12];
    const float* pw1   = (const float*)d_in[13];
    const float* pb1   = (const float*)d_in[14];
    const float* pw2   = (const float*)d_in[15];
    const float* pb2   = (const float*)d_in[16];
    const float* ln1g  = (const float*)d_in[17];
    const float* ln1b  = (const float*)d_in[18];
    const float* qkvw  = (const float*)d_in[19];
    const float* projw = (const float*)d_in[20];
    const float* projb = (const float*)d_in[21];
    const float* ln2g  = (const float*)d_in[22];
    const float* ln2b  = (const float*)d_in[23];
    const float* fc1w  = (const float*)d_in[24];
    const float* fc1b  = (const float*)d_in[25];
    const float* fc2w  = (const float*)d_in[26];
    const float* fc2b  = (const float*)d_in[27];
    const float* nfg   = (const float*)d_in[28];
    const float* nfb   = (const float*)d_in[29];

    static float* S = nullptr;
    if (!S) {
        cudaGetSymbolAddress((void**)&S, g_scratch);
        cudaFuncSetAttribute(mmagemm_kernel<3, 5, 128>, cudaFuncAttributeMaxDynamicSharedMemorySize, GE_SMEM);
        cudaFuncSetAttribute(mmagemm_kernel<0, 0, 128>, cudaFuncAttributeMaxDynamicSharedMemorySize, GE_SMEM);
        cudaFuncSetAttribute(mmagemm_kernel<0, 3, 128>, cudaFuncAttributeMaxDynamicSharedMemorySize, GE_SMEM);
        cudaFuncSetAttribute(mmagemm_kernel<1, 4, 128>, cudaFuncAttributeMaxDynamicSharedMemorySize, GE_SMEM);
        cudaFuncSetAttribute(mmagemm_kernel<0, 2, 128>, cudaFuncAttributeMaxDynamicSharedMemorySize, GE_SMEM);
        cudaFuncSetAttribute(mmagemm_kernel<0, 1, 64>,  cudaFuncAttributeMaxDynamicSharedMemorySize, GE_SMEM64);
        cudaFuncSetAttribute(attn_qk_mma, cudaFuncAttributeMaxDynamicSharedMemorySize, QK_SMEM);
        cudaFuncSetAttribute(attn_av_mma, cudaFuncAttributeMaxDynamicSharedMemorySize, AV_SMEM);
    }

    uint32_t* PK = (uint32_t*)(S + O_PK);
    float* f    = S + O_F;
    float* h3   = S + O_H3;
    float* fg   = S + O_FG;
    float* x    = S + O_X;
    float* xin  = S + O_XIN;
    float* hln  = S + O_HLN;
    float* ob   = S + O_OB;
    float* pos  = S + O_POS;
    float* qkv  = S + O_QKV;
    float* sc   = S + O_SC;
    float* ff   = S + O_FF;
    float* ctr  = S + O_CTR;
    float* st   = S + O_ST;
    float* mom = st;
    float* s1b = st + 256, *s2b = st + 768;
    float* scale1 = st + 1280, *shift1 = st + 1408;
    float* scale2 = st + 1536, *shift2 = st + 2048;

    float* out     = (float*)d_out;
    float* out_x   = out;
    float* out_nbr = out + (size_t)BGc * 384;
    float* out_ctr = out_nbr + (size_t)BGc * NK * 3;

    zero_kernel<<<16, 256>>>(st, 4096);

    WJobs jobs;
    jobs.j[0] = { qkvw,  (uint32_t)PK_QKV_HI,  (uint32_t)PK_QKV_LO,  384, 1152, 12 };
    jobs.j[1] = { fc1w,  (uint32_t)PK_FC1_HI,  (uint32_t)PK_FC1_LO,  384, 1536, 12 };
    jobs.j[2] = { fc2w,  (uint32_t)PK_FC2_HI,  (uint32_t)PK_FC2_LO,  1536, 384, 12 };
    jobs.j[3] = { projw, (uint32_t)PK_PROJ_HI, (uint32_t)PK_PROJ_LO, 384, 384, 12 };
    jobs.j[4] = { w2,    (uint32_t)PK_W2_HI,   (uint32_t)PK_W2_LO,   128, 256, 1 };
    jobs.j[5] = { w3,    (uint32_t)PK_W3_HI,   (uint32_t)PK_W3_LO,   512, 512, 1 };
    jobs.j[6] = { w4,    (uint32_t)PK_W4_HI,   (uint32_t)PK_W4_LO,   512, 384, 1 };
    wprep_all_kernel<<<dim3(144, 12, 7), 256>>>(jobs, PK);

    fps_kernel<<<NB, 1024>>>(pts, ctr, out_ctr);
    knn_kernel<<<BGc, 256>>>(pts, ctr, out_nbr);

    moments_kernel<<<256, 256>>>(out_nbr, mom);
    bnfin1_kernel<<<1, 128>>>(mom, w1, b1, bn1g, bn1b, scale1, shift1);

    mmagemm_kernel<3, 5, 128><<<dim3(2, 2048), 256, GE_SMEM>>>(
        out_nbr, PK + PK_W2_HI, PK + PK_W2_LO, b2, nullptr, f,
        M1, 256, 128, scale1, shift1, fg, w1, b1);
    mmagemm_kernel<0, 0, 128><<<dim3(4, 64), 256, GE_SMEM>>>(
        fg, PK + PK_W3_HI, PK + PK_W3_LO, b3, nullptr, ff,
        BGc, 512, 256, nullptr, nullptr, nullptr, nullptr, nullptr);
    mmagemm_kernel<0, 3, 128><<<dim3(4, 2048), 256, GE_SMEM>>>(
        f, PK + PK_W3_HI + 8 * 512 * 16, PK + PK_W3_LO + 8 * 512 * 16, nullptr, ff, h3,
        M1, 512, 256, nullptr, nullptr, nullptr, nullptr, nullptr);
    bnstats_kernel<<<M1 / 512, 512>>>(h3, 512, s1b, s2b);
    bnfin_kernel<<<1, 512>>>(s1b, s2b, 1.0f / (float)M1, bn2g, bn2b, scale2, shift2);
    mmagemm_kernel<1, 4, 128><<<dim3(3, 2048), 256, GE_SMEM>>>(
        h3, PK + PK_W4_HI, PK + PK_W4_LO, b4, nullptr, x,
        M1, 384, 512, scale2, shift2, nullptr, nullptr, nullptr);

    pos_kernel<<<BGc, 128>>>(ctr, pw1, pb1, pw2, pb2, pos);

    for (int l = 0; l < NL; l++) {
        ln_add_kernel<<<BGc / 8, 256>>>(x, pos, xin, hln, ln1g + l * 384, ln1b + l * 384);
        mmagemm_kernel<0, 0, 128><<<dim3(9, 64), 256, GE_SMEM>>>(
            hln, PK + PK_QKV_HI + (size_t)l * (384 * 1152 / 2),
            PK + PK_QKV_LO + (size_t)l * (384 * 1152 / 2), nullptr, nullptr, qkv,
            BGc, 1152, 384, nullptr, nullptr, nullptr, nullptr, nullptr);
        attn_qk_mma<<<dim3(4, 4, NB * NH), 256, QK_SMEM>>>(qkv, sc);
        softmax_kernel<<<NB * NH * 512 / 8, 256>>>(sc);
        attn_av_mma<<<dim3(4, NB * NH), 256, AV_SMEM>>>(sc, qkv, ob);
        mmagemm_kernel<0, 1, 64><<<dim3(6, 64), 256, GE_SMEM64>>>(
            ob, PK + PK_PROJ_HI + (size_t)l * (384 * 384 / 2),
            PK + PK_PROJ_LO + (size_t)l * (384 * 384 / 2), projb + l * 384, xin, x,
            BGc, 384, 384, nullptr, nullptr, nullptr, nullptr, nullptr);
        ln_kernel<<<BGc / 8, 256>>>(x, hln, ln2g + l * 384, ln2b + l * 384);
        mmagemm_kernel<0, 2, 128><<<dim3(12, 64), 256, GE_SMEM>>>(
            hln, PK + PK_FC1_HI + (size_t)l * (384 * 1536 / 2),
            PK + PK_FC1_LO + (size_t)l * (384 * 1536 / 2), fc1b + l * 1536, nullptr, ff,
            BGc, 1536, 384, nullptr, nullptr, nullptr, nullptr, nullptr);
        mmagemm_kernel<0, 1, 64><<<dim3(6, 64), 256, GE_SMEM64>>>(
            ff, PK + PK_FC2_HI + (size_t)l * (1536 * 384 / 2),
            PK + PK_FC2_LO + (size_t)l * (1536 * 384 / 2), fc2b + l * 384, x, x,
            BGc, 384, 1536, nullptr, nullptr, nullptr, nullptr, nullptr);
    }
    ln_kernel<<<BGc / 8, 256>>>(x, out_x, nfg, nfb);
}

// round 15
// speedup vs baseline: 1.0139x; 1.0139x over previous
#include <cuda_runtime.h>
#include <math.h>
#include <stdint.h>

// Problem dims
#define NB 16
#define NP 8192
#define NG 512
#define NK 32
#define ND 384
#define NL 12
#define NH 6
#define BGc (NB*NG)      /* 8192 */
#define M1  (BGc*NK)     /* 262144 */

// ---------------- scratch layout ----------------
constexpr size_t O_PK  = 0;
constexpr size_t O_F   = O_PK  + (size_t)M1*128;
constexpr size_t O_H3  = O_F   + (size_t)M1*256;
constexpr size_t O_F4  = O_H3  + (size_t)M1*512;
constexpr size_t O_FG  = O_F4  + (size_t)M1*384;
constexpr size_t O_X   = O_FG  + (size_t)BGc*256;
constexpr size_t O_XIN = O_X   + (size_t)BGc*384;
constexpr size_t O_HLN = O_XIN + (size_t)BGc*384;
constexpr size_t O_OB  = O_HLN + (size_t)BGc*384;
constexpr size_t O_POS = O_OB  + (size_t)BGc*384;
constexpr size_t O_QKV = O_POS + (size_t)BGc*384;
constexpr size_t O_SC  = O_QKV + (size_t)BGc*1152;
constexpr size_t O_FF  = O_SC  + (size_t)96*512*512;
constexpr size_t O_CTR = O_FF  + (size_t)BGc*1536;
constexpr size_t O_ST  = O_CTR + (size_t)BGc*3;
constexpr size_t SCRATCH_TOTAL = O_ST + 4096;

__device__ float g_scratch[SCRATCH_TOTAL];

// packed weight sub-offsets (words, within O_PK)
constexpr size_t PK_QKV_HI  = 0;
constexpr size_t PK_QKV_LO  = PK_QKV_HI + (size_t)12*384*1152/2;
constexpr size_t PK_FC1_HI  = PK_QKV_LO + (size_t)12*384*1152/2;
constexpr size_t PK_FC1_LO  = PK_FC1_HI + (size_t)12*384*1536/2;
constexpr size_t PK_FC2_HI  = PK_FC1_LO + (size_t)12*384*1536/2;
constexpr size_t PK_FC2_LO  = PK_FC2_HI + (size_t)12*1536*384/2;
constexpr size_t PK_PROJ_HI = PK_FC2_LO + (size_t)12*1536*384/2;
constexpr size_t PK_PROJ_LO = PK_PROJ_HI + (size_t)12*384*384/2;
constexpr size_t PK_W2_HI   = PK_PROJ_LO + (size_t)12*384*384/2;
constexpr size_t PK_W2_LO   = PK_W2_HI + (size_t)128*256/2;
constexpr size_t PK_W3_HI   = PK_W2_LO + (size_t)128*256/2;
constexpr size_t PK_W3_LO   = PK_W3_HI + (size_t)512*512/2;
constexpr size_t PK_W4_HI   = PK_W3_LO + (size_t)512*512/2;
constexpr size_t PK_W4_LO   = PK_W4_HI + (size_t)512*384/2;

__device__ __forceinline__ float gelu_f(float x) {
    return 0.5f * x * (1.0f + erff(x * 0.70710678118654752f));
}

// ---------------- bf16 helpers ----------------
__device__ __forceinline__ void bf16x2_split(float x0, float x1, uint32_t& hi, uint32_t& lo) {
    uint32_t h;
    asm("cvt.rn.bf16x2.f32 %0, %1, %2;" : "=r"(h) : "f"(x1), "f"(x0));
    float h0 = __uint_as_float(h << 16);
    float h1 = __uint_as_float(h & 0xffff0000u);
    float r0 = x0 - h0, r1 = x1 - h1;
    asm("cvt.rn.bf16x2.f32 %0, %1, %2;" : "=r"(lo) : "f"(r1), "f"(r0));
    hi = h;
}

__device__ __forceinline__ void mma_bf16(float* d, const uint32_t* a, uint32_t b0, uint32_t b1) {
    asm volatile(
        "mma.sync.aligned.m16n8k16.row.col.f32.bf16.bf16.f32 "
        "{%0,%1,%2,%3}, {%4,%5,%6,%7}, {%8,%9}, {%0,%1,%2,%3};"
        : "+f"(d[0]), "+f"(d[1]), "+f"(d[2]), "+f"(d[3])
        : "r"(a[0]), "r"(a[1]), "r"(a[2]), "r"(a[3]), "r"(b0), "r"(b1));
}

// cp.async (baseline sm_80+ PTX)
__device__ __forceinline__ void cp_async16(uint32_t smem_addr, const void* gptr) {
    asm volatile("cp.async.cg.shared.global [%0], [%1], 16;"
                 :: "r"(smem_addr), "l"(gptr) : "memory");
}
#define CP_COMMIT() asm volatile("cp.async.commit_group;" ::: "memory")
#define CP_WAIT0()  asm volatile("cp.async.wait_group 0;" ::: "memory")

#define AW 24
#define BUFW (4 * 128 * AW)
static constexpr int GE_SMEM   = 2 * BUFW * 4;                 /* 98304 B (NT=128) */
static constexpr int GE_SMEM64 = 2 * (6144 + 2 * 64 * AW) * 4; /* 73728 B (NT=64) */
static constexpr int QK_SMEM = BUFW * 4;
static constexpr int AV_SMEM = (3 * 128 * AW + 2 * 64 * AW) * 4;

// ---------------- merged weight prep ----------------
struct WJob { const float* W; uint32_t hi; uint32_t lo; int K; int N; int L; };
struct WJobs { WJob j[7]; };

__global__ void wprep_all_kernel(WJobs jobs, uint32_t* __restrict__ PK) {
    const WJob& jb = jobs.j[blockIdx.z];
    if ((int)blockIdx.y >= jb.L) return;
    const int K = jb.K, N = jb.N;
    int units = (K >> 5) * 2 * N;
    int u = blockIdx.x * 256 + threadIdx.x;
    if (u >= units) return;
    size_t lw = (size_t)blockIdx.y * K * N;
    size_t lp = lw >> 1;
    int n = u % N;
    int rem = u / N;
    int half = rem & 1;
    int kb = rem >> 1;
    const float* src = jb.W + lw + (size_t)(kb * 32 + half * 16) * N + n;
    uint32_t hw[8], lwd[8];
#pragma unroll
    for (int w = 0; w < 8; w++) {
        uint32_t h, l;
        bf16x2_split(src[(size_t)(2 * w) * N], src[(size_t)(2 * w + 1) * N], h, l);
        int slot = (w & 3) * 2 + (w >> 2);
        hw[slot] = h; lwd[slot] = l;
    }
    size_t off = lp + (size_t)kb * N * 16 + (size_t)half * N * 8 + (size_t)n * 8;
    uint32_t* Phi = PK + jb.hi;
    uint32_t* Plo = PK + jb.lo;
    *(uint4*)(Phi + off)     = *(uint4*)hw;
    *(uint4*)(Phi + off + 4) = *(uint4*)(hw + 4);
    *(uint4*)(Plo + off)     = *(uint4*)lwd;
    *(uint4*)(Plo + off + 4) = *(uint4*)(lwd + 4);
}

// ============ BF16x3 mma.sync GEMM, double-buffered, cp.async B-staging ============
template <int AMODE, int EPI, int NT>
__global__ void __launch_bounds__(256) mmagemm_kernel(
    const float* __restrict__ A,
    const uint32_t* __restrict__ PWhi, const uint32_t* __restrict__ PWlo,
    const float* __restrict__ bias, const float* __restrict__ res,
    float* __restrict__ C, int M, int N, int K,
    const float* __restrict__ q0, const float* __restrict__ q1,
    float* __restrict__ gout,
    const float* __restrict__ e1w, const float* __restrict__ e1b) {
    extern __shared__ uint32_t sm[];
    constexpr int NTT = NT / 16;
    constexpr int BUFN = 6144 + 2 * NT * AW;

    const int tid = threadIdx.x;
    const int warp = tid >> 5, lane = tid & 31;
    const int row0 = blockIdx.y << 7, col0 = blockIdx.x * NT;
    const int wr = (warp & 3) << 5;
    const int wc = (warp >> 2) * (NT / 2);

    float d[2][NTT][4];
#pragma unroll
    for (int mt = 0; mt < 2; mt++)
#pragma unroll
        for (int nt = 0; nt < NTT; nt++)
#pragma unroll
            for (int i = 0; i < 4; i++) d[mt][nt][i] = 0.f;

    const int arow = tid >> 1;
    const int akoff = (tid & 1) << 4;
    const int grow = row0 + arow;
    const int lg = lane >> 2;
    const int lt = lane & 3;

    // B staging via cp.async (no registers)
    auto stageB = [&](int kb, uint32_t* base) {
        uint32_t* Bhi = base + 6144;
        uint32_t* Blo = base + 6144 + NT * AW;
        if (NT == 128) {
            const int bn = tid & 127;
            const int bkhalf = tid >> 7;
            size_t off = (size_t)kb * ((size_t)N * 16) + (size_t)bkhalf * N * 8 +
                         (size_t)(col0 + bn) * 8;
            uint32_t bh = (uint32_t)__cvta_generic_to_shared(Bhi + bn * AW + bkhalf * 8);
            uint32_t bl = (uint32_t)__cvta_generic_to_shared(Blo + bn * AW + bkhalf * 8);
            cp_async16(bh,      PWhi + off);
            cp_async16(bh + 16, PWhi + off + 4);
            cp_async16(bl,      PWlo + off);
            cp_async16(bl + 16, PWlo + off + 4);
        } else {
            const int bn = tid & 63;
            const int bkhalf = (tid >> 6) & 1;
            const int bq = tid >> 7;
            size_t off = (size_t)kb * ((size_t)N * 16) + (size_t)bkhalf * N * 8 +
                         (size_t)(col0 + bn) * 8 + bq * 4;
            uint32_t bh = (uint32_t)__cvta_generic_to_shared(Bhi + bn * AW + bkhalf * 8 + bq * 4);
            uint32_t bl = (uint32_t)__cvta_generic_to_shared(Blo + bn * AW + bkhalf * 8 + bq * 4);
            cp_async16(bh, PWhi + off);
            cp_async16(bl, PWlo + off);
        }
        CP_COMMIT();
    };

    // A staging (load + bf16 split + STS)
    auto stageA = [&](int kb, uint32_t* base) {
        uint32_t* Ahi = base;
        uint32_t* Alo = base + 3072;
        const int kbase = kb << 5;
        float v[16];
        const int kg = kbase + akoff;
        if (AMODE == 3) {
            float x0 = A[(size_t)grow * 3], x1 = A[(size_t)grow * 3 + 1],
                  x2 = A[(size_t)grow * 3 + 2];
#pragma unroll
            for (int c = 0; c < 16; c++) {
                float h = fmaf(x2, e1w[256 + kg + c],
                          fmaf(x1, e1w[128 + kg + c],
                          fmaf(x0, e1w[kg + c], e1b[kg + c])));
                v[c] = fmaxf(fmaf(h, q0[kg + c], q1[kg + c]), 0.f);
            }
        } else {
            const float* src = A + (size_t)grow * K + kg;
#pragma unroll
            for (int i = 0; i < 4; i++) *(float4*)&v[i * 4] = *(const float4*)&src[i * 4];
            if (AMODE == 1) {
#pragma unroll
                for (int c = 0; c < 16; c++)
                    v[c] = fmaxf(fmaf(v[c], q0[kg + c], q1[kg + c]), 0.f);
            }
        }
        uint32_t* ah = Ahi + arow * AW + (akoff >> 4) * 8;
        uint32_t* al = Alo + arow * AW + (akoff >> 4) * 8;
#pragma unroll
        for (int u = 0; u < 4; u++) {
            uint32_t h1, l1, h2, l2;
            bf16x2_split(v[2 * u], v[2 * u + 1], h1, l1);
            bf16x2_split(v[2 * u + 8], v[2 * u + 9], h2, l2);
            *(uint2*)(ah + 2 * u) = make_uint2(h1, h2);
            *(uint2*)(al + 2 * u) = make_uint2(l1, l2);
        }
    };

    auto compute = [&](const uint32_t* base) {
        const uint32_t* Ahi = base;
        const uint32_t* Alo = base + 3072;
        const uint32_t* Bhi = base + 6144;
        const uint32_t* Blo = base + 6144 + NT * AW;
#pragma unroll
        for (int b16 = 0; b16 < 2; b16++) {
            const int bo = b16 * 8 + 2 * lt;
            uint32_t ah[2][4], al[2][4];
#pragma unroll
            for (int mt = 0; mt < 2; mt++) {
                const int r1 = wr + mt * 16 + lg;
                uint2 t0 = *(const uint2*)(Ahi + r1 * AW + bo);
                uint2 t1 = *(const uint2*)(Ahi + (r1 + 8) * AW + bo);
                ah[mt][0] = t0.x; ah[mt][1] = t1.x; ah[mt][2] = t0.y; ah[mt][3] = t1.y;
                uint2 s0 = *(const uint2*)(Alo + r1 * AW + bo);
                uint2 s1 = *(const uint2*)(Alo + (r1 + 8) * AW + bo);
                al[mt][0] = s0.x; al[mt][1] = s1.x; al[mt][2] = s0.y; al[mt][3] = s1.y;
            }
#pragma unroll
            for (int nt = 0; nt < NTT; nt++) {
                const int n = wc + nt * 8 + lg;
                uint2 bh = *(const uint2*)(Bhi + n * AW + bo);
                uint2 bl = *(const uint2*)(Blo + n * AW + bo);
#pragma unroll
                for (int mt = 0; mt < 2; mt++) {
                    mma_bf16(d[mt][nt], ah[mt], bh.x, bh.y);
                    mma_bf16(d[mt][nt], al[mt], bh.x, bh.y);
                    mma_bf16(d[mt][nt], ah[mt], bl.x, bl.y);
                }
            }
        }
    };

    const int nblk = K >> 5;
    stageB(0, sm);
    stageA(0, sm);
    CP_WAIT0();
    __syncthreads();
    for (int kb = 0; kb < nblk; kb++) {
        uint32_t* nxt = sm + ((kb + 1) & 1) * BUFN;
        if (kb + 1 < nblk) stageB(kb + 1, nxt);   // async, overlaps compute
        compute(sm + (kb & 1) * BUFN);
        if (kb + 1 < nblk) stageA(kb + 1, nxt);
        CP_WAIT0();
        __syncthreads();
    }

    const int g = (row0 + wr) >> 5;

    if (EPI <= 3 || EPI == 5) {
#pragma unroll
        for (int mt = 0; mt < 2; mt++) {
            const int r1 = row0 + wr + mt * 16 + lg;
            const int r2 = r1 + 8;
#pragma unroll
            for (int nt = 0; nt < NTT; nt++) {
                const int c = col0 + wc + nt * 8 + lt * 2;
                float v0 = d[mt][nt][0], v1 = d[mt][nt][1];
                float v2 = d[mt][nt][2], v3 = d[mt][nt][3];
                if (bias) {
                    float b0 = bias[c], b1 = bias[c + 1];
                    v0 += b0; v1 += b1; v2 += b0; v3 += b1;
                }
                if (EPI == 1) {
                    v0 += res[(size_t)r1 * N + c];
                    v1 += res[(size_t)r1 * N + c + 1];
                    v2 += res[(size_t)r2 * N + c];
                    v3 += res[(size_t)r2 * N + c + 1];
                } else if (EPI == 3) {
                    float g0 = res[(size_t)g * N + c];
                    float g1 = res[(size_t)g * N + c + 1];
                    v0 += g0; v1 += g1; v2 += g0; v3 += g1;
                } else if (EPI == 2) {
                    v0 = gelu_f(v0); v1 = gelu_f(v1); v2 = gelu_f(v2); v3 = gelu_f(v3);
                }
                C[(size_t)r1 * N + c]     = v0;
                C[(size_t)r1 * N + c + 1] = v1;
                C[(size_t)r2 * N + c]     = v2;
                C[(size_t)r2 * N + c + 1] = v3;
            }
        }
    }

    if (EPI >= 4) {
#pragma unroll
        for (int nt = 0; nt < NTT; nt++) {
            const int c = col0 + wc + nt * 8 + lt * 2;
            float m0v = fmaxf(fmaxf(d[0][nt][0], d[0][nt][2]),
                              fmaxf(d[1][nt][0], d[1][nt][2]));
            float m1v = fmaxf(fmaxf(d[0][nt][1], d[0][nt][3]),
                              fmaxf(d[1][nt][1], d[1][nt][3]));
#pragma unroll
            for (int o = 4; o <= 16; o <<= 1) {
                m0v = fmaxf(m0v, __shfl_xor_sync(0xFFFFFFFFu, m0v, o));
                m1v = fmaxf(m1v, __shfl_xor_sync(0xFFFFFFFFu, m1v, o));
            }
            if (lane < 4) {
                if (bias) { m0v += bias[c]; m1v += bias[c + 1]; }
                float* gp = (EPI == 5) ? gout : C;
                gp[(size_t)g * N + c]     = m0v;
                gp[(size_t)g * N + c + 1] = m1v;
            }
        }
    }
}

// ============ attention QK ============
__global__ void __launch_bounds__(256) attn_qk_mma(const float* __restrict__ qkv,
                                                   float* __restrict__ S) {
    extern __shared__ uint32_t sm[];
    uint32_t* Ahi = sm;
    uint32_t* Alo = sm + 3072;
    uint32_t* Bhi = sm + 6144;
    uint32_t* Blo = sm + 9216;
    const int z = blockIdx.z;
    const int b = z / NH, h = z - b * NH;
    const float* Qb = qkv + (size_t)b * NG * 1152 + h * 64;
    const float* Kb = Qb + 384;
    const int m0 = blockIdx.y << 7, n0 = blockIdx.x << 7;
    const int tid = threadIdx.x;
    const int warp = tid >> 5, lane = tid & 31;
    const int wr = (warp & 3) << 5, wc = (warp >> 2) << 6;
    const int arow = tid >> 1, akoff = (tid & 1) << 4;
    const int lg = lane >> 2, lt = lane & 3;

    float d[2][8][4];
#pragma unroll
    for (int mt = 0; mt < 2; mt++)
#pragma unroll
        for (int nt = 0; nt < 8; nt++)
#pragma unroll
            for (int i = 0; i < 4; i++) d[mt][nt][i] = 0.f;

#pragma unroll
    for (int kb = 0; kb < 2; kb++) {
        const int kg = (kb << 5) + akoff;
        {
            const float* src = Qb + (size_t)(m0 + arow) * 1152 + kg;
            uint32_t* ah = Ahi + arow * AW + (akoff >> 4) * 8;
            uint32_t* al = Alo + arow * AW + (akoff >> 4) * 8;
            float v[16];
#pragma unroll
            for (int i = 0; i < 4; i++) *(float4*)&v[i * 4] = *(const float4*)&src[i * 4];
#pragma unroll
            for (int u = 0; u < 4; u++) {
                uint32_t h1, l1, h2, l2;
                bf16x2_split(v[2 * u], v[2 * u + 1], h1, l1);
                bf16x2_split(v[2 * u + 8], v[2 * u + 9], h2, l2);
                *(uint2*)(ah + 2 * u) = make_uint2(h1, h2);
                *(uint2*)(al + 2 * u) = make_uint2(l1, l2);
            }
        }
        {
            const float* src = Kb + (size_t)(n0 + arow) * 1152 + kg;
            uint32_t* bh = Bhi + arow * AW + (akoff >> 4) * 8;
            uint32_t* bl = Blo + arow * AW + (akoff >> 4) * 8;
            float v[16];
#pragma unroll
            for (int i = 0; i < 4; i++) *(float4*)&v[i * 4] = *(const float4*)&src[i * 4];
#pragma unroll
            for (int u = 0; u < 4; u++) {
                uint32_t h1, l1, h2, l2;
                bf16x2_split(v[2 * u], v[2 * u + 1], h1, l1);
                bf16x2_split(v[2 * u + 8], v[2 * u + 9], h2, l2);
                *(uint2*)(bh + 2 * u) = make_uint2(h1, h2);
                *(uint2*)(bl + 2 * u) = make_uint2(l1, l2);
            }
        }
        __syncthreads();
#pragma unroll
        for (int b16 = 0; b16 < 2; b16++) {
            const int bo = b16 * 8 + 2 * lt;
            uint32_t ah[2][4], al[2][4];
#pragma unroll
            for (int mt = 0; mt < 2; mt++) {
                const int r1 = wr + mt * 16 + lg;
                uint2 t0 = *(const uint2*)(Ahi + r1 * AW + bo);
                uint2 t1 = *(const uint2*)(Ahi + (r1 + 8) * AW + bo);
                ah[mt][0] = t0.x; ah[mt][1] = t1.x; ah[mt][2] = t0.y; ah[mt][3] = t1.y;
                uint2 s0 = *(const uint2*)(Alo + r1 * AW + bo);
                uint2 s1 = *(const uint2*)(Alo + (r1 + 8) * AW + bo);
                al[mt][0] = s0.x; al[mt][1] = s1.x; al[mt][2] = s0.y; al[mt][3] = s1.y;
            }
#pragma unroll
            for (int nt = 0; nt < 8; nt++) {
                const int n = wc + nt * 8 + lg;
                uint2 bh = *(const uint2*)(Bhi + n * AW + bo);
                uint2 bl = *(const uint2*)(Blo + n * AW + bo);
#pragma unroll
                for (int mt = 0; mt < 2; mt++) {
                    mma_bf16(d[mt][nt], ah[mt], bh.x, bh.y);
                    mma_bf16(d[mt][nt], al[mt], bh.x, bh.y);
                    mma_bf16(d[mt][nt], ah[mt], bl.x, bl.y);
                }
            }
        }
        __syncthreads();
    }
    float* out = S + (size_t)z * 512 * 512;
#pragma unroll
    for (int mt = 0; mt < 2; mt++) {
        const int r1 = m0 + wr + mt * 16 + lg;
        const int r2 = r1 + 8;
#pragma unroll
        for (int nt = 0; nt < 8; nt++) {
            const int c = n0 + wc + nt * 8 + lt * 2;
            out[(size_t)r1 * 512 + c]     = d[mt][nt][0] * 0.125f;
            out[(size_t)r1 * 512 + c + 1] = d[mt][nt][1] * 0.125f;
            out[(size_t)r2 * 512 + c]     = d[mt][nt][2] * 0.125f;
            out[(size_t)r2 * 512 + c + 1] = d[mt][nt][3] * 0.125f;
        }
    }
}

// ============ softmax: one warp per 512-col row ============
__global__ void __launch_bounds__(256) softmax_kernel(float* __restrict__ S) {
    const int warp = threadIdx.x >> 5, lane = threadIdx.x & 31;
    const size_t row = (size_t)blockIdx.x * 8 + warp;
    float* p = S + row * 512;
    float v[16];
#pragma unroll
    for (int j = 0; j < 4; j++)
        *(float4*)&v[j * 4] = *(const float4*)&p[lane * 4 + j * 128];
    float m = v[0];
#pragma unroll
    for (int j = 1; j < 16; j++) m = fmaxf(m, v[j]);
#pragma unroll
    for (int o = 16; o; o >>= 1) m = fmaxf(m, __shfl_xor_sync(0xFFFFFFFFu, m, o));
    float s = 0.f;
#pragma unroll
    for (int j = 0; j < 16; j++) { v[j] = expf(v[j] - m); s += v[j]; }
#pragma unroll
    for (int o = 16; o; o >>= 1) s += __shfl_xor_sync(0xFFFFFFFFu, s, o);
    float inv = 1.0f / s;
#pragma unroll
    for (int j = 0; j < 16; j++) v[j] *= inv;
#pragma unroll
    for (int j = 0; j < 4; j++)
        *(float4*)&p[lane * 4 + j * 128] = *(float4*)&v[j * 4];
}

// ============ attention AV ============
__global__ void __launch_bounds__(256) attn_av_mma(const float* __restrict__ S,
                                                   const float* __restrict__ qkv,
                                                   float* __restrict__ O) {
    extern __shared__ uint32_t sm[];
    uint32_t* Ahi = sm;
    uint32_t* Alo = sm + 3072;
    uint32_t* Bhi = sm + 6144;
    uint32_t* Blo = sm + 6144 + 64 * AW;
    const int z = blockIdx.y;
    const int b = z / NH, h = z - b * NH;
    const float* A = S + (size_t)z * 512 * 512;
    const float* Vb = qkv + (size_t)b * NG * 1152 + 768 + h * 64;
    const int m0 = blockIdx.x << 7;
    const int tid = threadIdx.x;
    const int warp = tid >> 5, lane = tid & 31;
    const int wr = (warp & 3) << 5, wc = (warp >> 2) << 5;
    const int arow = tid >> 1, akoff = (tid & 1) << 4;
    const int bn = tid & 63, bhalf = (tid >> 6) & 1, brep = tid >> 7;
    const int lg = lane >> 2, lt = lane & 3;

    float d[2][4][4];
#pragma unroll
    for (int mt = 0; mt < 2; mt++)
#pragma unroll
        for (int nt = 0; nt < 4; nt++)
#pragma unroll
            for (int i = 0; i < 4; i++) d[mt][nt][i] = 0.f;

    for (int kb = 0; kb < 16; kb++) {
        const int kbase = kb << 5;
        {
            const float* src = A + (size_t)(m0 + arow) * 512 + kbase + akoff;
            uint32_t* ah = Ahi + arow * AW + (akoff >> 4) * 8;
            uint32_t* al = Alo + arow * AW + (akoff >> 4) * 8;
            float v[16];
#pragma unroll
            for (int i = 0; i < 4; i++) *(float4*)&v[i * 4] = *(const float4*)&src[i * 4];
#pragma unroll
            for (int u = 0; u < 4; u++) {
                uint32_t h1, l1, h2, l2;
                bf16x2_split(v[2 * u], v[2 * u + 1], h1, l1);
                bf16x2_split(v[2 * u + 8], v[2 * u + 9], h2, l2);
                *(uint2*)(ah + 2 * u) = make_uint2(h1, h2);
                *(uint2*)(al + 2 * u) = make_uint2(l1, l2);
            }
        }
        {
            uint32_t* bh = Bhi + bn * AW + bhalf * 8;
            uint32_t* bl = Blo + bn * AW + bhalf * 8;
#pragma unroll
            for (int p = 0; p < 4; p++) {
                const int k0 = kbase + bhalf * 16 + brep * 8 + 2 * p;
                float v0 = Vb[(size_t)k0 * 1152 + bn];
                float v1 = Vb[(size_t)(k0 + 1) * 1152 + bn];
                uint32_t hh, ll;
                bf16x2_split(v0, v1, hh, ll);
                bh[2 * p + brep] = hh;
                bl[2 * p + brep] = ll;
            }
        }
        __syncthreads();
#pragma unroll
        for (int b16 = 0; b16 < 2; b16++) {
            const int bo = b16 * 8 + 2 * lt;
            uint32_t ah[2][4], al[2][4];
#pragma unroll
            for (int mt = 0; mt < 2; mt++) {
                const int r1 = wr + mt * 16 + lg;
                uint2 t0 = *(const uint2*)(Ahi + r1 * AW + bo);
                uint2 t1 = *(const uint2*)(Ahi + (r1 + 8) * AW + bo);
                ah[mt][0] = t0.x; ah[mt][1] = t1.x; ah[mt][2] = t0.y; ah[mt][3] = t1.y;
                uint2 s0 = *(const uint2*)(Alo + r1 * AW + bo);
                uint2 s1 = *(const uint2*)(Alo + (r1 + 8) * AW + bo);
                al[mt][0] = s0.x; al[mt][1] = s1.x; al[mt][2] = s0.y; al[mt][3] = s1.y;
            }
#pragma unroll
            for (int nt = 0; nt < 4; nt++) {
                const int n = wc + nt * 8 + lg;
                uint2 bh = *(const uint2*)(Bhi + n * AW + bo);
                uint2 bl = *(const uint2*)(Blo + n * AW + bo);
#pragma unroll
                for (int mt = 0; mt < 2; mt++) {
                    mma_bf16(d[mt][nt], ah[mt], bh.x, bh.y);
                    mma_bf16(d[mt][nt], al[mt], bh.x, bh.y);
                    mma_bf16(d[mt][nt], ah[mt], bl.x, bl.y);
                }
            }
        }
        __syncthreads();
    }
    float* Ob = O + (size_t)b * NG * 384 + h * 64;
#pragma unroll
    for (int mt = 0; mt < 2; mt++) {
        const int r1 = m0 + wr + mt * 16 + lg;
        const int r2 = r1 + 8;
#pragma unroll
        for (int nt = 0; nt < 4; nt++) {
            const int c = wc + nt * 8 + lt * 2;
            Ob[(size_t)r1 * 384 + c]     = d[mt][nt][0];
            Ob[(size_t)r1 * 384 + c + 1] = d[mt][nt][1];
            Ob[(size_t)r2 * 384 + c]     = d[mt][nt][2];
            Ob[(size_t)r2 * 384 + c + 1] = d[mt][nt][3];
        }
    }
}

// ---------------- zero ----------------
__global__ void zero_kernel(float* p, int n) {
    int i = blockIdx.x * blockDim.x + threadIdx.x;
    if (i < n) p[i] = 0.0f;
}

// ---------------- FPS ----------------
__global__ void __launch_bounds__(1024) fps_kernel(const float* __restrict__ pts,
                                                   float* __restrict__ ctr,
                                                   float* __restrict__ ctr_out) {
    int b = blockIdx.x;
    int tid = threadIdx.x, wid = tid >> 5, lane = tid & 31;
    const float* P = pts + (size_t)b * NP * 3;
    float px[8], py[8], pz[8], dl[8];
#pragma unroll
    for (int t = 0; t < 8; t++) {
        int j = tid + t * 1024;
        px[t] = P[j * 3 + 0]; py[t] = P[j * 3 + 1]; pz[t] = P[j * 3 + 2];
        dl[t] = 1e10f;
    }
    __shared__ float lastp[3];
    __shared__ float wv_s[32];
    __shared__ int   wi_s[32];
    if (tid == 0) {
        lastp[0] = P[0]; lastp[1] = P[1]; lastp[2] = P[2];
        size_t co = (size_t)b * NG * 3;
        ctr[co] = P[0]; ctr[co + 1] = P[1]; ctr[co + 2] = P[2];
        ctr_out[co] = P[0]; ctr_out[co + 1] = P[1]; ctr_out[co + 2] = P[2];
    }
    __syncthreads();
    for (int s = 1; s < NG; s++) {
        float lx = lastp[0], ly = lastp[1], lz = lastp[2];
        float bv = -1.0f; int bi = 0;
#pragma unroll
        for (int t = 0; t < 8; t++) {
            float dx = __fsub_rn(px[t], lx);
            float dy = __fsub_rn(py[t], ly);
            float dz = __fsub_rn(pz[t], lz);
            float d = __fadd_rn(__fadd_rn(__fmul_rn(dx, dx), __fmul_rn(dy, dy)),
                                __fmul_rn(dz, dz));
            float nd = fminf(dl[t], d);
            dl[t] = nd;
            if (nd > bv) { bv = nd; bi = tid + t * 1024; }
        }
#pragma unroll
        for (int o = 16; o; o >>= 1) {
            float v2 = __shfl_xor_sync(0xFFFFFFFFu, bv, o);
            int   i2 = __shfl_xor_sync(0xFFFFFFFFu, bi, o);
            if (v2 > bv || (v2 == bv && i2 < bi)) { bv = v2; bi = i2; }
        }
        if (lane == 0) { wv_s[wid] = bv; wi_s[wid] = bi; }
        __syncthreads();
        if (wid == 0) {
            bv = wv_s[lane]; bi = wi_s[lane];
#pragma unroll
            for (int o = 16; o; o >>= 1) {
                float v2 = __shfl_xor_sync(0xFFFFFFFFu, bv, o);
                int   i2 = __shfl_xor_sync(0xFFFFFFFFu, bi, o);
                if (v2 > bv || (v2 == bv && i2 < bi)) { bv = v2; bi = i2; }
            }
            if (lane == 0) {
                float qx = P[bi * 3], qy = P[bi * 3 + 1], qz = P[bi * 3 + 2];
                lastp[0] = qx; lastp[1] = qy; lastp[2] = qz;
                size_t co = ((size_t)b * NG + s) * 3;
                ctr[co] = qx; ctr[co + 1] = qy; ctr[co + 2] = qz;
                ctr_out[co] = qx; ctr_out[co + 1] = qy; ctr_out[co + 2] = qz;
            }
        }
        __syncthreads();
    }
}

// ---------------- KNN: tournament argmin ----------------
__device__ __forceinline__ unsigned long long knn_key(float v, int idx) {
    uint32_t b = __float_as_uint(v);
    b = (b & 0x80000000u) ? ~b : (b | 0x80000000u);
    return ((unsigned long long)b << 32) | (uint32_t)idx;
}

__global__ void __launch_bounds__(256) knn_kernel(const float* __restrict__ pts,
                                                  const float* __restrict__ ctr,
                                                  float* __restrict__ nbr_out) {
    int bg = blockIdx.x;
    int b = bg >> 9;
    const float* P = pts + (size_t)b * NP * 3;
    float cx = ctr[bg * 3 + 0], cy = ctr[bg * 3 + 1], cz = ctr[bg * 3 + 2];
    float c2 = __fadd_rn(__fadd_rn(__fmul_rn(cx, cx), __fmul_rn(cy, cy)), __fmul_rn(cz, cz));
    __shared__ float d2s[NP];
    int tid = threadIdx.x;
    for (int j = tid; j < NP; j += 256) {
        float px = P[j * 3], py = P[j * 3 + 1], pz = P[j * 3 + 2];
        float p2 = __fadd_rn(__fadd_rn(__fmul_rn(px, px), __fmul_rn(py, py)), __fmul_rn(pz, pz));
        float dot = __fmaf_rn(cz, pz, __fmaf_rn(cy, py, __fmul_rn(cx, px)));
        d2s[j] = __fsub_rn(__fadd_rn(c2, p2), __fmul_rn(2.0f, dot));
    }
    __syncthreads();

    unsigned long long mykey = ~0ull;
#pragma unroll
    for (int t = 0; t < 32; t++) {
        int j = tid + t * 256;
        unsigned long long k = knn_key(d2s[j], j);
        if (k < mykey) mykey = k;
    }

    __shared__ unsigned long long wmin[8];
    __shared__ unsigned long long winner;
    __shared__ int chosen[NK];
    const int warp = tid >> 5, lane = tid & 31;

    for (int sel = 0; sel < NK; sel++) {
        unsigned long long k = mykey;
#pragma unroll
        for (int o = 16; o; o >>= 1) {
            unsigned long long k2 = __shfl_xor_sync(0xFFFFFFFFu, k, o);
            if (k2 < k) k = k2;
        }
        if (lane == 0) wmin[warp] = k;
        __syncthreads();
        if (tid == 0) {
            unsigned long long w = wmin[0];
#pragma unroll
            for (int i = 1; i < 8; i++) if (wmin[i] < w) w = wmin[i];
            winner = w;
            chosen[sel] = (int)(w & 0xffffffffu);
        }
        __syncthreads();
        int widx = (int)(winner & 0xffffffffu);
        if ((widx & 255) == tid) {
            d2s[widx] = 3.4e38f;
            mykey = ~0ull;
#pragma unroll
            for (int t = 0; t < 32; t++) {
                int j = tid + t * 256;
                unsigned long long kk = knn_key(d2s[j], j);
                if (kk < mykey) mykey = kk;
            }
        }
    }
    __syncthreads();
    if (tid < NK) {
        int j = chosen[tid];
        size_t o = ((size_t)bg * NK + tid) * 3;
        nbr_out[o + 0] = P[j * 3 + 0] - cx;
        nbr_out[o + 1] = P[j * 3 + 1] - cy;
        nbr_out[o + 2] = P[j * 3 + 2] - cz;
    }
}

// ---------------- nbr moments (analytic BN1) ----------------
__global__ void __launch_bounds__(256) moments_kernel(const float* __restrict__ nbr,
                                                      float* __restrict__ mom) {
    int t = blockIdx.x * 256 + threadIdx.x;
    float s[9];
#pragma unroll
    for (int i = 0; i < 9; i++) s[i] = 0.f;
    for (int r = t; r < M1; r += 65536) {
        float a = nbr[(size_t)r * 3], b = nbr[(size_t)r * 3 + 1], c = nbr[(size_t)r * 3 + 2];
        s[0] += a; s[1] += b; s[2] += c;
        s[3] += a * a; s[4] += b * b; s[5] += c * c;
        s[6] += a * b; s[7] += a * c; s[8] += b * c;
    }
#pragma unroll
    for (int i = 0; i < 9; i++)
#pragma unroll
        for (int o = 16; o; o >>= 1) s[i] += __shfl_xor_sync(0xFFFFFFFFu, s[i], o);
    __shared__ float sh[8][9];
    int wid = threadIdx.x >> 5, lane = threadIdx.x & 31;
    if (lane == 0)
#pragma unroll
        for (int i = 0; i < 9; i++) sh[wid][i] = s[i];
    __syncthreads();
    if (threadIdx.x < 9) {
        float a = 0.f;
#pragma unroll
        for (int w = 0; w < 8; w++) a += sh[w][threadIdx.x];
        atomicAdd(&mom[threadIdx.x], a);
    }
}

__global__ void bnfin1_kernel(const float* __restrict__ mom,
                              const float* __restrict__ w1, const float* __restrict__ b1,
                              const float* __restrict__ g, const float* __restrict__ bb,
                              float* __restrict__ scale, float* __restrict__ shift) {
    int c = threadIdx.x;
    float inv = 1.0f / (float)M1;
    float m0 = mom[0] * inv, m1 = mom[1] * inv, m2 = mom[2] * inv;
    float C00 = mom[3] * inv - m0 * m0;
    float C11 = mom[4] * inv - m1 * m1;
    float C22 = mom[5] * inv - m2 * m2;
    float C01 = mom[6] * inv - m0 * m1;
    float C02 = mom[7] * inv - m0 * m2;
    float C12 = mom[8] * inv - m1 * m2;
    float w0 = w1[c], wv1 = w1[128 + c], wv2 = w1[256 + c];
    float var = C00 * w0 * w0 + C11 * wv1 * wv1 + C22 * wv2 * wv2 +
                2.0f * (C01 * w0 * wv1 + C02 * w0 * wv2 + C12 * wv1 * wv2);
    float mean = m0 * w0 + m1 * wv1 + m2 * wv2 + b1[c];
    float r = rsqrtf(var + 1e-5f);
    float sc = g[c] * r;
    scale[c] = sc;
    shift[c] = bb[c] - mean * sc;
}

// ---------------- BN stats (h3) ----------------
__global__ void bnstats_kernel(const float* __restrict__ h, int C,
                               float* __restrict__ s1, float* __restrict__ s2) {
    int c = threadIdx.x;
    size_t r0 = (size_t)blockIdx.x * 512;
    const float* p = h + r0 * C + c;
    float a = 0.f, q = 0.f;
    for (int r = 0; r < 512; r++) {
        float v = p[(size_t)r * C];
        a += v; q += v * v;
    }
    atomicAdd(&s1[c], a);
    atomicAdd(&s2[c], q);
}

__global__ void bnfin_kernel(const float* __restrict__ s1, const float* __restrict__ s2,
                             float invM, const float* __restrict__ g, const float* __restrict__ b,
                             float* __restrict__ scale, float* __restrict__ shift) {
    int c = threadIdx.x;
    float mean = s1[c] * invM;
    float var = s2[c] * invM - mean * mean;
    float r = rsqrtf(var + 1e-5f);
    float sc = g[c] * r;
    scale[c] = sc;
    shift[c] = b[c] - mean * sc;
}

// ---------------- layernorm: one warp per 384-col row ----------------
__global__ void __launch_bounds__(256) ln_kernel(const float* __restrict__ in,
                                                 float* __restrict__ out,
                                                 const float* __restrict__ gg,
                                                 const float* __restrict__ bb) {
    const int warp = threadIdx.x >> 5, lane = threadIdx.x & 31;
    const size_t row = (size_t)blockIdx.x * 8 + warp;
    const float* p = in + row * 384;
    float v[12];
#pragma unroll
    for (int j = 0; j < 3; j++)
        *(float4*)&v[j * 4] = *(const float4*)&p[lane * 4 + j * 128];
    float s = 0.f;
#pragma unroll
    for (int j = 0; j < 12; j++) s += v[j];
#pragma unroll
    for (int o = 16; o; o >>= 1) s += __shfl_xor_sync(0xFFFFFFFFu, s, o);
    float mean = s * (1.0f / 384.0f);
    float q = 0.f;
#pragma unroll
    for (int j = 0; j < 12; j++) { v[j] -= mean; q += v[j] * v[j]; }
#pragma unroll
    for (int o = 16; o; o >>= 1) q += __shfl_xor_sync(0xFFFFFFFFu, q, o);
    float rstd = rsqrtf(q * (1.0f / 384.0f) + 1e-5f);
    float* op = out + row * 384;
#pragma unroll
    for (int j = 0; j < 3; j++) {
        float4 gv = *(const float4*)&gg[lane * 4 + j * 128];
        float4 bv = *(const float4*)&bb[lane * 4 + j * 128];
        float4 o4;
        o4.x = v[j * 4 + 0] * rstd * gv.x + bv.x;
        o4.y = v[j * 4 + 1] * rstd * gv.y + bv.y;
        o4.z = v[j * 4 + 2] * rstd * gv.z + bv.z;
        o4.w = v[j * 4 + 3] * rstd * gv.w + bv.w;
        *(float4*)&op[lane * 4 + j * 128] = o4;
    }
}

// xin = x + pos; out = LN(xin); one warp per row
__global__ void __launch_bounds__(256) ln_add_kernel(const float* __restrict__ x,
                                                     const float* __restrict__ pos,
                                                     float* __restrict__ xin,
                                                     float* __restrict__ out,
                                                     const float* __restrict__ gg,
                                                     const float* __restrict__ bb) {
    const int warp = threadIdx.x >> 5, lane = threadIdx.x & 31;
    const size_t row = (size_t)blockIdx.x * 8 + warp;
    const float* p = x + row * 384;
    const float* pp = pos + row * 384;
    float v[12];
#pragma unroll
    for (int j = 0; j < 3; j++) {
        float4 a = *(const float4*)&p[lane * 4 + j * 128];
        float4 b = *(const float4*)&pp[lane * 4 + j * 128];
        a.x += b.x; a.y += b.y; a.z += b.z; a.w += b.w;
        *(float4*)&v[j * 4] = a;
        *(float4*)&xin[row * 384 + lane * 4 + j * 128] = a;
    }
    float s = 0.f;
#pragma unroll
    for (int j = 0; j < 12; j++) s += v[j];
#pragma unroll
    for (int o = 16; o; o >>= 1) s += __shfl_xor_sync(0xFFFFFFFFu, s, o);
    float mean = s * (1.0f / 384.0f);
    float q = 0.f;
#pragma unroll
    for (int j = 0; j < 12; j++) { v[j] -= mean; q += v[j] * v[j]; }
#pragma unroll
    for (int o = 16; o; o >>= 1) q += __shfl_xor_sync(0xFFFFFFFFu, q, o);
    float rstd = rsqrtf(q * (1.0f / 384.0f) + 1e-5f);
    float* op = out + row * 384;
#pragma unroll
    for (int j = 0; j < 3; j++) {
        float4 gv = *(const float4*)&gg[lane * 4 + j * 128];
        float4 bv = *(const float4*)&bb[lane * 4 + j * 128];
        float4 o4;
        o4.x = v[j * 4 + 0] * rstd * gv.x + bv.x;
        o4.y = v[j * 4 + 1] * rstd * gv.y + bv.y;
        o4.z = v[j * 4 + 2] * rstd * gv.z + bv.z;
        o4.w = v[j * 4 + 3] * rstd * gv.w + bv.w;
        *(float4*)&op[lane * 4 + j * 128] = o4;
    }
}

// ---------------- pos embed ----------------
__global__ void __launch_bounds__(128) pos_kernel(const float* __restrict__ ctr,
                                                  const float* __restrict__ pw1,
                                                  const float* __restrict__ pb1,
                                                  const float* __restrict__ pw2,
                                                  const float* __restrict__ pb2,
                                                  float* __restrict__ pos) {
    int row = blockIdx.x;
    int tid = threadIdx.x;
    float cx = ctr[row * 3], cy = ctr[row * 3 + 1], cz = ctr[row * 3 + 2];
    __shared__ float t[128];
    float u = cx * pw1[tid] + cy * pw1[128 + tid] + cz * pw1[256 + tid] + pb1[tid];
    t[tid] = gelu_f(u);
    __syncthreads();
    for (int j = tid; j < 384; j += 128) {
        float s = pb2[j];
#pragma unroll 8
        for (int k = 0; k < 128; k++) s = fmaf(t[k], pw2[k * 384 + j], s);
        pos[(size_t)row * 384 + j] = s;
    }
}

// ---------------- host ----------------
extern "C" void kernel_launch(void* const* d_in, const int* in_sizes, int n_in,
                              void* d_out, int out_size) {
    const float* pts   = (const float*)d_in[0];
    const float* w1    = (const float*)d_in[1];
    const float* b1    = (const float*)d_in[2];
    const float* bn1g  = (const float*)d_in[3];
    const float* bn1b  = (const float*)d_in[4];
    const float* w2    = (const float*)d_in[5];
    const float* b2    = (const float*)d_in[6];
    const float* w3    = (const float*)d_in[7];
    const float* b3    = (const float*)d_in[8];
    const float* bn2g  = (const float*)d_in[9];
    const float* bn2b  = (const float*)d_in[10];
    const float* w4    = (const float*)d_in[11];
    const float* b4    = (const float*)d_in[12];
    const float* pw1   = (const float*)d_in[13];
    const float* pb1   = (const float*)d_in[14];
    const float* pw2   = (const float*)d_in[15];
    const float* pb2   = (const float*)d_in[16];
    const float* ln1g  = (const float*)d_in[17];
    const float* ln1b  = (const float*)d_in[18];
    const float* qkvw  = (const float*)d_in[19];
    const float* projw = (const float*)d_in[20];
    const float* projb = (const float*)d_in[21];
    const float* ln2g  = (const float*)d_in[22];
    const float* ln2b  = (const float*)d_in[23];
    const float* fc1w  = (const float*)d_in[24];
    const float* fc1b  = (const float*)d_in[25];
    const float* fc2w  = (const float*)d_in[26];
    const float* fc2b  = (const float*)d_in[27];
    const float* nfg   = (const float*)d_in[28];
    const float* nfb   = (const float*)d_in[29];

    static float* S = nullptr;
    if (!S) {
        cudaGetSymbolAddress((void**)&S, g_scratch);
        cudaFuncSetAttribute(mmagemm_kernel<3, 5, 128>, cudaFuncAttributeMaxDynamicSharedMemorySize, GE_SMEM);
        cudaFuncSetAttribute(mmagemm_kernel<0, 0, 128>, cudaFuncAttributeMaxDynamicSharedMemorySize, GE_SMEM);
        cudaFuncSetAttribute(mmagemm_kernel<0, 3, 128>, cudaFuncAttributeMaxDynamicSharedMemorySize, GE_SMEM);
        cudaFuncSetAttribute(mmagemm_kernel<1, 4, 128>, cudaFuncAttributeMaxDynamicSharedMemorySize, GE_SMEM);
        cudaFuncSetAttribute(mmagemm_kernel<0, 2, 128>, cudaFuncAttributeMaxDynamicSharedMemorySize, GE_SMEM);
        cudaFuncSetAttribute(mmagemm_kernel<0, 1, 64>,  cudaFuncAttributeMaxDynamicSharedMemorySize, GE_SMEM64);
        cudaFuncSetAttribute(attn_qk_mma, cudaFuncAttributeMaxDynamicSharedMemorySize, QK_SMEM);
        cudaFuncSetAttribute(attn_av_mma, cudaFuncAttributeMaxDynamicSharedMemorySize, AV_SMEM);
    }

    uint32_t* PK = (uint32_t*)(S + O_PK);
    float* f    = S + O_F;
    float* h3   = S + O_H3;
    float* fg   = S + O_FG;
    float* x    = S + O_X;
    float* xin  = S + O_XIN;
    float* hln  = S + O_HLN;
    float* ob   = S + O_OB;
    float* pos  = S + O_POS;
    float* qkv  = S + O_QKV;
    float* sc   = S + O_SC;
    float* ff   = S + O_FF;
    float* ctr  = S + O_CTR;
    float* st   = S + O_ST;
    float* mom = st;
    float* s1b = st + 256, *s2b = st + 768;
    float* scale1 = st + 1280, *shift1 = st + 1408;
    float* scale2 = st + 1536, *shift2 = st + 2048;

    float* out     = (float*)d_out;
    float* out_x   = out;
    float* out_nbr = out + (size_t)BGc * 384;
    float* out_ctr = out_nbr + (size_t)BGc * NK * 3;

    zero_kernel<<<16, 256>>>(st, 4096);

    WJobs jobs;
    jobs.j[0] = { qkvw,  (uint32_t)PK_QKV_HI,  (uint32_t)PK_QKV_LO,  384, 1152, 12 };
    jobs.j[1] = { fc1w,  (uint32_t)PK_FC1_HI,  (uint32_t)PK_FC1_LO,  384, 1536, 12 };
    jobs.j[2] = { fc2w,  (uint32_t)PK_FC2_HI,  (uint32_t)PK_FC2_LO,  1536, 384, 12 };
    jobs.j[3] = { projw, (uint32_t)PK_PROJ_HI, (uint32_t)PK_PROJ_LO, 384, 384, 12 };
    jobs.j[4] = { w2,    (uint32_t)PK_W2_HI,   (uint32_t)PK_W2_LO,   128, 256, 1 };
    jobs.j[5] = { w3,    (uint32_t)PK_W3_HI,   (uint32_t)PK_W3_LO,   512, 512, 1 };
    jobs.j[6] = { w4,    (uint32_t)PK_W4_HI,   (uint32_t)PK_W4_LO,   512, 384, 1 };
    wprep_all_kernel<<<dim3(144, 12, 7), 256>>>(jobs, PK);

    fps_kernel<<<NB, 1024>>>(pts, ctr, out_ctr);
    knn_kernel<<<BGc, 256>>>(pts, ctr, out_nbr);

    moments_kernel<<<256, 256>>>(out_nbr, mom);
    bnfin1_kernel<<<1, 128>>>(mom, w1, b1, bn1g, bn1b, scale1, shift1);

    mmagemm_kernel<3, 5, 128><<<dim3(2, 2048), 256, GE_SMEM>>>(
        out_nbr, PK + PK_W2_HI, PK + PK_W2_LO, b2, nullptr, f,
        M1, 256, 128, scale1, shift1, fg, w1, b1);
    mmagemm_kernel<0, 0, 128><<<dim3(4, 64), 256, GE_SMEM>>>(
        fg, PK + PK_W3_HI, PK + PK_W3_LO, b3, nullptr, ff,
        BGc, 512, 256, nullptr, nullptr, nullptr, nullptr, nullptr);
    mmagemm_kernel<0, 3, 128><<<dim3(4, 2048), 256, GE_SMEM>>>(
        f, PK + PK_W3_HI + 8 * 512 * 16, PK + PK_W3_LO + 8 * 512 * 16, nullptr, ff, h3,
        M1, 512, 256, nullptr, nullptr, nullptr, nullptr, nullptr);
    bnstats_kernel<<<M1 / 512, 512>>>(h3, 512, s1b, s2b);
    bnfin_kernel<<<1, 512>>>(s1b, s2b, 1.0f / (float)M1, bn2g, bn2b, scale2, shift2);
    mmagemm_kernel<1, 4, 128><<<dim3(3, 2048), 256, GE_SMEM>>>(
        h3, PK + PK_W4_HI, PK + PK_W4_LO, b4, nullptr, x,
        M1, 384, 512, scale2, shift2, nullptr, nullptr, nullptr);

    pos_kernel<<<BGc, 128>>>(ctr, pw1, pb1, pw2, pb2, pos);

    for (int l = 0; l < NL; l++) {
        ln_add_kernel<<<BGc / 8, 256>>>(x, pos, xin, hln, ln1g + l * 384, ln1b + l * 384);
        mmagemm_kernel<0, 0, 128><<<dim3(9, 64), 256, GE_SMEM>>>(
            hln, PK + PK_QKV_HI + (size_t)l * (384 * 1152 / 2),
            PK + PK_QKV_LO + (size_t)l * (384 * 1152 / 2), nullptr, nullptr, qkv,
            BGc, 1152, 384, nullptr, nullptr, nullptr, nullptr, nullptr);
        attn_qk_mma<<<dim3(4, 4, NB * NH), 256, QK_SMEM>>>(qkv, sc);
        softmax_kernel<<<NB * NH * 512 / 8, 256>>>(sc);
        attn_av_mma<<<dim3(4, NB * NH), 256, AV_SMEM>>>(sc, qkv, ob);
        mmagemm_kernel<0, 1, 64><<<dim3(6, 64), 256, GE_SMEM64>>>(
            ob, PK + PK_PROJ_HI + (size_t)l * (384 * 384 / 2),
            PK + PK_PROJ_LO + (size_t)l * (384 * 384 / 2), projb + l * 384, xin, x,
            BGc, 384, 384, nullptr, nullptr, nullptr, nullptr, nullptr);
        ln_kernel<<<BGc / 8, 256>>>(x, hln, ln2g + l * 384, ln2b + l * 384);
        mmagemm_kernel<0, 2, 128><<<dim3(12, 64), 256, GE_SMEM>>>(
            hln, PK + PK_FC1_HI + (size_t)l * (384 * 1536 / 2),
            PK + PK_FC1_LO + (size_t)l * (384 * 1536 / 2), fc1b + l * 1536, nullptr, ff,
            BGc, 1536, 384, nullptr, nullptr, nullptr, nullptr, nullptr);
        mmagemm_kernel<0, 1, 64><<<dim3(6, 64), 256, GE_SMEM64>>>(
            ff, PK + PK_FC2_HI + (size_t)l * (1536 * 384 / 2),
            PK + PK_FC2_LO + (size_t)l * (1536 * 384 / 2), fc2b + l * 384, x, x,
            BGc, 384, 1536, nullptr, nullptr, nullptr, nullptr, nullptr);
    }
    ln_kernel<<<BGc / 8, 256>>>(x, out_x, nfg, nfb);
}

// round 16
// speedup vs baseline: 1.0547x; 1.0403x over previous
#include <cuda_runtime.h>
#include <math.h>
#include <stdint.h>

// Problem dims
#define NB 16
#define NP 8192
#define NG 512
#define NK 32
#define ND 384
#define NL 12
#define NH 6
#define BGc (NB*NG)      /* 8192 */
#define M1  (BGc*NK)     /* 262144 */

// ---------------- scratch layout ----------------
constexpr size_t O_PK  = 0;
constexpr size_t O_F   = O_PK  + (size_t)M1*128;
constexpr size_t O_H3  = O_F   + (size_t)M1*256;
constexpr size_t O_F4  = O_H3  + (size_t)M1*512;
constexpr size_t O_FG  = O_F4  + (size_t)M1*384;
constexpr size_t O_X   = O_FG  + (size_t)BGc*256;
constexpr size_t O_XIN = O_X   + (size_t)BGc*384;
constexpr size_t O_HLN = O_XIN + (size_t)BGc*384;
constexpr size_t O_OB  = O_HLN + (size_t)BGc*384;
constexpr size_t O_POS = O_OB  + (size_t)BGc*384;
constexpr size_t O_QKV = O_POS + (size_t)BGc*384;
constexpr size_t O_SC  = O_QKV + (size_t)BGc*1152;
constexpr size_t O_FF  = O_SC  + (size_t)96*512*512;
constexpr size_t O_CTR = O_FF  + (size_t)BGc*1536;
constexpr size_t O_ST  = O_CTR + (size_t)BGc*3;
constexpr size_t SCRATCH_TOTAL = O_ST + 4096;

__device__ float g_scratch[SCRATCH_TOTAL];

// packed weight sub-offsets (words, within O_PK)
constexpr size_t PK_QKV_HI  = 0;
constexpr size_t PK_QKV_LO  = PK_QKV_HI + (size_t)12*384*1152/2;
constexpr size_t PK_FC1_HI  = PK_QKV_LO + (size_t)12*384*1152/2;
constexpr size_t PK_FC1_LO  = PK_FC1_HI + (size_t)12*384*1536/2;
constexpr size_t PK_FC2_HI  = PK_FC1_LO + (size_t)12*384*1536/2;
constexpr size_t PK_FC2_LO  = PK_FC2_HI + (size_t)12*1536*384/2;
constexpr size_t PK_PROJ_HI = PK_FC2_LO + (size_t)12*1536*384/2;
constexpr size_t PK_PROJ_LO = PK_PROJ_HI + (size_t)12*384*384/2;
constexpr size_t PK_W2_HI   = PK_PROJ_LO + (size_t)12*384*384/2;
constexpr size_t PK_W2_LO   = PK_W2_HI + (size_t)128*256/2;
constexpr size_t PK_W3_HI   = PK_W2_LO + (size_t)128*256/2;
constexpr size_t PK_W3_LO   = PK_W3_HI + (size_t)512*512/2;
constexpr size_t PK_W4_HI   = PK_W3_LO + (size_t)512*512/2;
constexpr size_t PK_W4_LO   = PK_W4_HI + (size_t)512*384/2;

__device__ __forceinline__ float gelu_f(float x) {
    return 0.5f * x * (1.0f + erff(x * 0.70710678118654752f));
}

// ---------------- bf16 helpers ----------------
__device__ __forceinline__ void bf16x2_split(float x0, float x1, uint32_t& hi, uint32_t& lo) {
    uint32_t h;
    asm("cvt.rn.bf16x2.f32 %0, %1, %2;" : "=r"(h) : "f"(x1), "f"(x0));
    float h0 = __uint_as_float(h << 16);
    float h1 = __uint_as_float(h & 0xffff0000u);
    float r0 = x0 - h0, r1 = x1 - h1;
    asm("cvt.rn.bf16x2.f32 %0, %1, %2;" : "=r"(lo) : "f"(r1), "f"(r0));
    hi = h;
}

__device__ __forceinline__ void mma_bf16(float* d, const uint32_t* a, uint32_t b0, uint32_t b1) {
    asm volatile(
        "mma.sync.aligned.m16n8k16.row.col.f32.bf16.bf16.f32 "
        "{%0,%1,%2,%3}, {%4,%5,%6,%7}, {%8,%9}, {%0,%1,%2,%3};"
        : "+f"(d[0]), "+f"(d[1]), "+f"(d[2]), "+f"(d[3])
        : "r"(a[0]), "r"(a[1]), "r"(a[2]), "r"(a[3]), "r"(b0), "r"(b1));
}

#define AW 24
#define BUFW (4 * 128 * AW)
static constexpr int GE_SMEM   = 2 * BUFW * 4;                 /* 98304 B (NT=128) */
static constexpr int GE_SMEM64 = 2 * (6144 + 2 * 64 * AW) * 4; /* 73728 B (NT=64) */
static constexpr int QK_SMEM = BUFW * 4;
static constexpr int AV_SMEM = (3 * 128 * AW + 2 * 64 * AW) * 4;

// ---------------- merged weight prep ----------------
struct WJob { const float* W; uint32_t hi; uint32_t lo; int K; int N; int L; };
struct WJobs { WJob j[7]; };

__global__ void wprep_all_kernel(WJobs jobs, uint32_t* __restrict__ PK) {
    const WJob& jb = jobs.j[blockIdx.z];
    if ((int)blockIdx.y >= jb.L) return;
    const int K = jb.K, N = jb.N;
    int units = (K >> 5) * 2 * N;
    int u = blockIdx.x * 256 + threadIdx.x;
    if (u >= units) return;
    size_t lw = (size_t)blockIdx.y * K * N;
    size_t lp = lw >> 1;
    int n = u % N;
    int rem = u / N;
    int half = rem & 1;
    int kb = rem >> 1;
    const float* src = jb.W + lw + (size_t)(kb * 32 + half * 16) * N + n;
    uint32_t hw[8], lwd[8];
#pragma unroll
    for (int w = 0; w < 8; w++) {
        uint32_t h, l;
        bf16x2_split(src[(size_t)(2 * w) * N], src[(size_t)(2 * w + 1) * N], h, l);
        int slot = (w & 3) * 2 + (w >> 2);
        hw[slot] = h; lwd[slot] = l;
    }
    size_t off = lp + (size_t)kb * N * 16 + (size_t)half * N * 8 + (size_t)n * 8;
    uint32_t* Phi = PK + jb.hi;
    uint32_t* Plo = PK + jb.lo;
    *(uint4*)(Phi + off)     = *(uint4*)hw;
    *(uint4*)(Phi + off + 4) = *(uint4*)(hw + 4);
    *(uint4*)(Plo + off)     = *(uint4*)lwd;
    *(uint4*)(Plo + off + 4) = *(uint4*)(lwd + 4);
}

// ============ BF16x3 mma.sync GEMM, double-buffered, packed-B (R13 structure) ============
// EPI 0: +bias; 1: +bias+res[r]; 2: gelu(+bias); 3: +res[(r>>5)];
// EPI 4: group-max only; 5: +bias write C AND group-max -> gout;
// EPI 6: like 3, plus fused BN column stats -> atomicAdd((float*)q0/q1)
template <int AMODE, int EPI, int NT>
__global__ void __launch_bounds__(256) mmagemm_kernel(
    const float* __restrict__ A,
    const uint32_t* __restrict__ PWhi, const uint32_t* __restrict__ PWlo,
    const float* __restrict__ bias, const float* __restrict__ res,
    float* __restrict__ C, int M, int N, int K,
    const float* __restrict__ q0, const float* __restrict__ q1,
    float* __restrict__ gout,
    const float* __restrict__ e1w, const float* __restrict__ e1b) {
    extern __shared__ uint32_t sm[];
    constexpr int NTT = NT / 16;
    constexpr int BUFN = 6144 + 2 * NT * AW;

    const int tid = threadIdx.x;
    const int warp = tid >> 5, lane = tid & 31;
    const int row0 = blockIdx.y << 7, col0 = blockIdx.x * NT;
    const int wr = (warp & 3) << 5;
    const int wc = (warp >> 2) * (NT / 2);

    float d[2][NTT][4];
#pragma unroll
    for (int mt = 0; mt < 2; mt++)
#pragma unroll
        for (int nt = 0; nt < NTT; nt++)
#pragma unroll
            for (int i = 0; i < 4; i++) d[mt][nt][i] = 0.f;

    const int arow = tid >> 1;
    const int akoff = (tid & 1) << 4;
    const int grow = row0 + arow;
    const int lg = lane >> 2;
    const int lt = lane & 3;

    auto stage = [&](int kb, uint32_t* base) {
        uint32_t* Ahi = base;
        uint32_t* Alo = base + 3072;
        uint32_t* Bhi = base + 6144;
        uint32_t* Blo = base + 6144 + NT * AW;
        const int kbase = kb << 5;
        {
            float v[16];
            const int kg = kbase + akoff;
            if (AMODE == 3) {
                float x0 = A[(size_t)grow * 3], x1 = A[(size_t)grow * 3 + 1],
                      x2 = A[(size_t)grow * 3 + 2];
#pragma unroll
                for (int c = 0; c < 16; c++) {
                    float h = fmaf(x2, e1w[256 + kg + c],
                              fmaf(x1, e1w[128 + kg + c],
                              fmaf(x0, e1w[kg + c], e1b[kg + c])));
                    v[c] = fmaxf(fmaf(h, q0[kg + c], q1[kg + c]), 0.f);
                }
            } else {
                const float* src = A + (size_t)grow * K + kg;
#pragma unroll
                for (int i = 0; i < 4; i++) *(float4*)&v[i * 4] = *(const float4*)&src[i * 4];
                if (AMODE == 1) {
#pragma unroll
                    for (int c = 0; c < 16; c++)
                        v[c] = fmaxf(fmaf(v[c], q0[kg + c], q1[kg + c]), 0.f);
                }
            }
            uint32_t* ah = Ahi + arow * AW + (akoff >> 4) * 8;
            uint32_t* al = Alo + arow * AW + (akoff >> 4) * 8;
#pragma unroll
            for (int u = 0; u < 4; u++) {
                uint32_t h1, l1, h2, l2;
                bf16x2_split(v[2 * u], v[2 * u + 1], h1, l1);
                bf16x2_split(v[2 * u + 8], v[2 * u + 9], h2, l2);
                *(uint2*)(ah + 2 * u) = make_uint2(h1, h2);
                *(uint2*)(al + 2 * u) = make_uint2(l1, l2);
            }
        }
        if (NT == 128) {
            const int bn = tid & 127;
            const int bkhalf = tid >> 7;
            size_t off = (size_t)kb * ((size_t)N * 16) + (size_t)bkhalf * N * 8 +
                         (size_t)(col0 + bn) * 8;
            const uint32_t* ph = PWhi + off;
            const uint32_t* pl = PWlo + off;
            uint32_t* bh = Bhi + bn * AW + bkhalf * 8;
            uint32_t* bl = Blo + bn * AW + bkhalf * 8;
            *(uint4*)bh       = *(const uint4*)ph;
            *(uint4*)(bh + 4) = *(const uint4*)(ph + 4);
            *(uint4*)bl       = *(const uint4*)pl;
            *(uint4*)(bl + 4) = *(const uint4*)(pl + 4);
        } else {
            const int bn = tid & 63;
            const int bkhalf = (tid >> 6) & 1;
            const int bq = tid >> 7;
            size_t off = (size_t)kb * ((size_t)N * 16) + (size_t)bkhalf * N * 8 +
                         (size_t)(col0 + bn) * 8 + bq * 4;
            uint32_t* bh = Bhi + bn * AW + bkhalf * 8 + bq * 4;
            uint32_t* bl = Blo + bn * AW + bkhalf * 8 + bq * 4;
            *(uint4*)bh = *(const uint4*)(PWhi + off);
            *(uint4*)bl = *(const uint4*)(PWlo + off);
        }
    };

    auto compute = [&](const uint32_t* base) {
        const uint32_t* Ahi = base;
        const uint32_t* Alo = base + 3072;
        const uint32_t* Bhi = base + 6144;
        const uint32_t* Blo = base + 6144 + NT * AW;
#pragma unroll
        for (int b16 = 0; b16 < 2; b16++) {
            const int bo = b16 * 8 + 2 * lt;
            uint32_t ah[2][4], al[2][4];
#pragma unroll
            for (int mt = 0; mt < 2; mt++) {
                const int r1 = wr + mt * 16 + lg;
                uint2 t0 = *(const uint2*)(Ahi + r1 * AW + bo);
                uint2 t1 = *(const uint2*)(Ahi + (r1 + 8) * AW + bo);
                ah[mt][0] = t0.x; ah[mt][1] = t1.x; ah[mt][2] = t0.y; ah[mt][3] = t1.y;
                uint2 s0 = *(const uint2*)(Alo + r1 * AW + bo);
                uint2 s1 = *(const uint2*)(Alo + (r1 + 8) * AW + bo);
                al[mt][0] = s0.x; al[mt][1] = s1.x; al[mt][2] = s0.y; al[mt][3] = s1.y;
            }
#pragma unroll
            for (int nt = 0; nt < NTT; nt++) {
                const int n = wc + nt * 8 + lg;
                uint2 bh = *(const uint2*)(Bhi + n * AW + bo);
                uint2 bl = *(const uint2*)(Blo + n * AW + bo);
#pragma unroll
                for (int mt = 0; mt < 2; mt++) {
                    mma_bf16(d[mt][nt], ah[mt], bh.x, bh.y);
                    mma_bf16(d[mt][nt], al[mt], bh.x, bh.y);
                    mma_bf16(d[mt][nt], ah[mt], bl.x, bl.y);
                }
            }
        }
    };

    const int nblk = K >> 5;
    stage(0, sm);
    __syncthreads();
    for (int kb = 0; kb < nblk; kb++) {
        compute(sm + (kb & 1) * BUFN);
        if (kb + 1 < nblk) stage(kb + 1, sm + ((kb + 1) & 1) * BUFN);
        __syncthreads();
    }

    const int g = (row0 + wr) >> 5;

    if (EPI <= 3 || EPI == 5 || EPI == 6) {
#pragma unroll
        for (int mt = 0; mt < 2; mt++) {
            const int r1 = row0 + wr + mt * 16 + lg;
            const int r2 = r1 + 8;
#pragma unroll
            for (int nt = 0; nt < NTT; nt++) {
                const int c = col0 + wc + nt * 8 + lt * 2;
                float v0 = d[mt][nt][0], v1 = d[mt][nt][1];
                float v2 = d[mt][nt][2], v3 = d[mt][nt][3];
                if (bias) {
                    float b0 = bias[c], b1 = bias[c + 1];
                    v0 += b0; v1 += b1; v2 += b0; v3 += b1;
                }
                if (EPI == 1) {
                    v0 += res[(size_t)r1 * N + c];
                    v1 += res[(size_t)r1 * N + c + 1];
                    v2 += res[(size_t)r2 * N + c];
                    v3 += res[(size_t)r2 * N + c + 1];
                } else if (EPI == 3 || EPI == 6) {
                    float g0 = res[(size_t)g * N + c];
                    float g1 = res[(size_t)g * N + c + 1];
                    v0 += g0; v1 += g1; v2 += g0; v3 += g1;
                } else if (EPI == 2) {
                    v0 = gelu_f(v0); v1 = gelu_f(v1); v2 = gelu_f(v2); v3 = gelu_f(v3);
                }
                C[(size_t)r1 * N + c]     = v0;
                C[(size_t)r1 * N + c + 1] = v1;
                C[(size_t)r2 * N + c]     = v2;
                C[(size_t)r2 * N + c + 1] = v3;
                if (EPI == 6) {
                    // fused BN column stats: sum / sumsq over this 16-row slice
                    float ss0 = v0 + v2,           ss1 = v1 + v3;
                    float qq0 = v0 * v0 + v2 * v2, qq1 = v1 * v1 + v3 * v3;
#pragma unroll
                    for (int o = 4; o <= 16; o <<= 1) {
                        ss0 += __shfl_xor_sync(0xFFFFFFFFu, ss0, o);
                        ss1 += __shfl_xor_sync(0xFFFFFFFFu, ss1, o);
                        qq0 += __shfl_xor_sync(0xFFFFFFFFu, qq0, o);
                        qq1 += __shfl_xor_sync(0xFFFFFFFFu, qq1, o);
                    }
                    if (lane < 4) {
                        float* s1p = (float*)q0;
                        float* s2p = (float*)q1;
                        atomicAdd(s1p + c,     ss0);
                        atomicAdd(s1p + c + 1, ss1);
                        atomicAdd(s2p + c,     qq0);
                        atomicAdd(s2p + c + 1, qq1);
                    }
                }
            }
        }
    }

    if (EPI == 4 || EPI == 5) {
#pragma unroll
        for (int nt = 0; nt < NTT; nt++) {
            const int c = col0 + wc + nt * 8 + lt * 2;
            float m0v = fmaxf(fmaxf(d[0][nt][0], d[0][nt][2]),
                              fmaxf(d[1][nt][0], d[1][nt][2]));
            float m1v = fmaxf(fmaxf(d[0][nt][1], d[0][nt][3]),
                              fmaxf(d[1][nt][1], d[1][nt][3]));
#pragma unroll
            for (int o = 4; o <= 16; o <<= 1) {
                m0v = fmaxf(m0v, __shfl_xor_sync(0xFFFFFFFFu, m0v, o));
                m1v = fmaxf(m1v, __shfl_xor_sync(0xFFFFFFFFu, m1v, o));
            }
            if (lane < 4) {
                if (bias) { m0v += bias[c]; m1v += bias[c + 1]; }
                float* gp = (EPI == 5) ? gout : C;
                gp[(size_t)g * N + c]     = m0v;
                gp[(size_t)g * N + c + 1] = m1v;
            }
        }
    }
}

// ============ attention QK ============
__global__ void __launch_bounds__(256) attn_qk_mma(const float* __restrict__ qkv,
                                                   float* __restrict__ S) {
    extern __shared__ uint32_t sm[];
    uint32_t* Ahi = sm;
    uint32_t* Alo = sm + 3072;
    uint32_t* Bhi = sm + 6144;
    uint32_t* Blo = sm + 9216;
    const int z = blockIdx.z;
    const int b = z / NH, h = z - b * NH;
    const float* Qb = qkv + (size_t)b * NG * 1152 + h * 64;
    const float* Kb = Qb + 384;
    const int m0 = blockIdx.y << 7, n0 = blockIdx.x << 7;
    const int tid = threadIdx.x;
    const int warp = tid >> 5, lane = tid & 31;
    const int wr = (warp & 3) << 5, wc = (warp >> 2) << 6;
    const int arow = tid >> 1, akoff = (tid & 1) << 4;
    const int lg = lane >> 2, lt = lane & 3;

    float d[2][8][4];
#pragma unroll
    for (int mt = 0; mt < 2; mt++)
#pragma unroll
        for (int nt = 0; nt < 8; nt++)
#pragma unroll
            for (int i = 0; i < 4; i++) d[mt][nt][i] = 0.f;

#pragma unroll
    for (int kb = 0; kb < 2; kb++) {
        const int kg = (kb << 5) + akoff;
        {
            const float* src = Qb + (size_t)(m0 + arow) * 1152 + kg;
            uint32_t* ah = Ahi + arow * AW + (akoff >> 4) * 8;
            uint32_t* al = Alo + arow * AW + (akoff >> 4) * 8;
            float v[16];
#pragma unroll
            for (int i = 0; i < 4; i++) *(float4*)&v[i * 4] = *(const float4*)&src[i * 4];
#pragma unroll
            for (int u = 0; u < 4; u++) {
                uint32_t h1, l1, h2, l2;
                bf16x2_split(v[2 * u], v[2 * u + 1], h1, l1);
                bf16x2_split(v[2 * u + 8], v[2 * u + 9], h2, l2);
                *(uint2*)(ah + 2 * u) = make_uint2(h1, h2);
                *(uint2*)(al + 2 * u) = make_uint2(l1, l2);
            }
        }
        {
            const float* src = Kb + (size_t)(n0 + arow) * 1152 + kg;
            uint32_t* bh = Bhi + arow * AW + (akoff >> 4) * 8;
            uint32_t* bl = Blo + arow * AW + (akoff >> 4) * 8;
            float v[16];
#pragma unroll
            for (int i = 0; i < 4; i++) *(float4*)&v[i * 4] = *(const float4*)&src[i * 4];
#pragma unroll
            for (int u = 0; u < 4; u++) {
                uint32_t h1, l1, h2, l2;
                bf16x2_split(v[2 * u], v[2 * u + 1], h1, l1);
                bf16x2_split(v[2 * u + 8], v[2 * u + 9], h2, l2);
                *(uint2*)(bh + 2 * u) = make_uint2(h1, h2);
                *(uint2*)(bl + 2 * u) = make_uint2(l1, l2);
            }
        }
        __syncthreads();
#pragma unroll
        for (int b16 = 0; b16 < 2; b16++) {
            const int bo = b16 * 8 + 2 * lt;
            uint32_t ah[2][4], al[2][4];
#pragma unroll
            for (int mt = 0; mt < 2; mt++) {
                const int r1 = wr + mt * 16 + lg;
                uint2 t0 = *(const uint2*)(Ahi + r1 * AW + bo);
                uint2 t1 = *(const uint2*)(Ahi + (r1 + 8) * AW + bo);
                ah[mt][0] = t0.x; ah[mt][1] = t1.x; ah[mt][2] = t0.y; ah[mt][3] = t1.y;
                uint2 s0 = *(const uint2*)(Alo + r1 * AW + bo);
                uint2 s1 = *(const uint2*)(Alo + (r1 + 8) * AW + bo);
                al[mt][0] = s0.x; al[mt][1] = s1.x; al[mt][2] = s0.y; al[mt][3] = s1.y;
            }
#pragma unroll
            for (int nt = 0; nt < 8; nt++) {
                const int n = wc + nt * 8 + lg;
                uint2 bh = *(const uint2*)(Bhi + n * AW + bo);
                uint2 bl = *(const uint2*)(Blo + n * AW + bo);
#pragma unroll
                for (int mt = 0; mt < 2; mt++) {
                    mma_bf16(d[mt][nt], ah[mt], bh.x, bh.y);
                    mma_bf16(d[mt][nt], al[mt], bh.x, bh.y);
                    mma_bf16(d[mt][nt], ah[mt], bl.x, bl.y);
                }
            }
        }
        __syncthreads();
    }
    float* out = S + (size_t)z * 512 * 512;
#pragma unroll
    for (int mt = 0; mt < 2; mt++) {
        const int r1 = m0 + wr + mt * 16 + lg;
        const int r2 = r1 + 8;
#pragma unroll
        for (int nt = 0; nt < 8; nt++) {
            const int c = n0 + wc + nt * 8 + lt * 2;
            out[(size_t)r1 * 512 + c]     = d[mt][nt][0] * 0.125f;
            out[(size_t)r1 * 512 + c + 1] = d[mt][nt][1] * 0.125f;
            out[(size_t)r2 * 512 + c]     = d[mt][nt][2] * 0.125f;
            out[(size_t)r2 * 512 + c + 1] = d[mt][nt][3] * 0.125f;
        }
    }
}

// ============ softmax: one warp per 512-col row ============
__global__ void __launch_bounds__(256) softmax_kernel(float* __restrict__ S) {
    const int warp = threadIdx.x >> 5, lane = threadIdx.x & 31;
    const size_t row = (size_t)blockIdx.x * 8 + warp;
    float* p = S + row * 512;
    float v[16];
#pragma unroll
    for (int j = 0; j < 4; j++)
        *(float4*)&v[j * 4] = *(const float4*)&p[lane * 4 + j * 128];
    float m = v[0];
#pragma unroll
    for (int j = 1; j < 16; j++) m = fmaxf(m, v[j]);
#pragma unroll
    for (int o = 16; o; o >>= 1) m = fmaxf(m, __shfl_xor_sync(0xFFFFFFFFu, m, o));
    float s = 0.f;
#pragma unroll
    for (int j = 0; j < 16; j++) { v[j] = expf(v[j] - m); s += v[j]; }
#pragma unroll
    for (int o = 16; o; o >>= 1) s += __shfl_xor_sync(0xFFFFFFFFu, s, o);
    float inv = 1.0f / s;
#pragma unroll
    for (int j = 0; j < 16; j++) v[j] *= inv;
#pragma unroll
    for (int j = 0; j < 4; j++)
        *(float4*)&p[lane * 4 + j * 128] = *(float4*)&v[j * 4];
}

// ============ attention AV ============
__global__ void __launch_bounds__(256) attn_av_mma(const float* __restrict__ S,
                                                   const float* __restrict__ qkv,
                                                   float* __restrict__ O) {
    extern __shared__ uint32_t sm[];
    uint32_t* Ahi = sm;
    uint32_t* Alo = sm + 3072;
    uint32_t* Bhi = sm + 6144;
    uint32_t* Blo = sm + 6144 + 64 * AW;
    const int z = blockIdx.y;
    const int b = z / NH, h = z - b * NH;
    const float* A = S + (size_t)z * 512 * 512;
    const float* Vb = qkv + (size_t)b * NG * 1152 + 768 + h * 64;
    const int m0 = blockIdx.x << 7;
    const int tid = threadIdx.x;
    const int warp = tid >> 5, lane = tid & 31;
    const int wr = (warp & 3) << 5, wc = (warp >> 2) << 5;
    const int arow = tid >> 1, akoff = (tid & 1) << 4;
    const int bn = tid & 63, bhalf = (tid >> 6) & 1, brep = tid >> 7;
    const int lg = lane >> 2, lt = lane & 3;

    float d[2][4][4];
#pragma unroll
    for (int mt = 0; mt < 2; mt++)
#pragma unroll
        for (int nt = 0; nt < 4; nt++)
#pragma unroll
            for (int i = 0; i < 4; i++) d[mt][nt][i] = 0.f;

    for (int kb = 0; kb < 16; kb++) {
        const int kbase = kb << 5;
        {
            const float* src = A + (size_t)(m0 + arow) * 512 + kbase + akoff;
            uint32_t* ah = Ahi + arow * AW + (akoff >> 4) * 8;
            uint32_t* al = Alo + arow * AW + (akoff >> 4) * 8;
            float v[16];
#pragma unroll
            for (int i = 0; i < 4; i++) *(float4*)&v[i * 4] = *(const float4*)&src[i * 4];
#pragma unroll
            for (int u = 0; u < 4; u++) {
                uint32_t h1, l1, h2, l2;
                bf16x2_split(v[2 * u], v[2 * u + 1], h1, l1);
                bf16x2_split(v[2 * u + 8], v[2 * u + 9], h2, l2);
                *(uint2*)(ah + 2 * u) = make_uint2(h1, h2);
                *(uint2*)(al + 2 * u) = make_uint2(l1, l2);
            }
        }
        {
            uint32_t* bh = Bhi + bn * AW + bhalf * 8;
            uint32_t* bl = Blo + bn * AW + bhalf * 8;
#pragma unroll
            for (int p = 0; p < 4; p++) {
                const int k0 = kbase + bhalf * 16 + brep * 8 + 2 * p;
                float v0 = Vb[(size_t)k0 * 1152 + bn];
                float v1 = Vb[(size_t)(k0 + 1) * 1152 + bn];
                uint32_t hh, ll;
                bf16x2_split(v0, v1, hh, ll);
                bh[2 * p + brep] = hh;
                bl[2 * p + brep] = ll;
            }
        }
        __syncthreads();
#pragma unroll
        for (int b16 = 0; b16 < 2; b16++) {
            const int bo = b16 * 8 + 2 * lt;
            uint32_t ah[2][4], al[2][4];
#pragma unroll
            for (int mt = 0; mt < 2; mt++) {
                const int r1 = wr + mt * 16 + lg;
                uint2 t0 = *(const uint2*)(Ahi + r1 * AW + bo);
                uint2 t1 = *(const uint2*)(Ahi + (r1 + 8) * AW + bo);
                ah[mt][0] = t0.x; ah[mt][1] = t1.x; ah[mt][2] = t0.y; ah[mt][3] = t1.y;
                uint2 s0 = *(const uint2*)(Alo + r1 * AW + bo);
                uint2 s1 = *(const uint2*)(Alo + (r1 + 8) * AW + bo);
                al[mt][0] = s0.x; al[mt][1] = s1.x; al[mt][2] = s0.y; al[mt][3] = s1.y;
            }
#pragma unroll
            for (int nt = 0; nt < 4; nt++) {
                const int n = wc + nt * 8 + lg;
                uint2 bh = *(const uint2*)(Bhi + n * AW + bo);
                uint2 bl = *(const uint2*)(Blo + n * AW + bo);
#pragma unroll
                for (int mt = 0; mt < 2; mt++) {
                    mma_bf16(d[mt][nt], ah[mt], bh.x, bh.y);
                    mma_bf16(d[mt][nt], al[mt], bh.x, bh.y);
                    mma_bf16(d[mt][nt], ah[mt], bl.x, bl.y);
                }
            }
        }
        __syncthreads();
    }
    float* Ob = O + (size_t)b * NG * 384 + h * 64;
#pragma unroll
    for (int mt = 0; mt < 2; mt++) {
        const int r1 = m0 + wr + mt * 16 + lg;
        const int r2 = r1 + 8;
#pragma unroll
        for (int nt = 0; nt < 4; nt++) {
            const int c = wc + nt * 8 + lt * 2;
            Ob[(size_t)r1 * 384 + c]     = d[mt][nt][0];
            Ob[(size_t)r1 * 384 + c + 1] = d[mt][nt][1];
            Ob[(size_t)r2 * 384 + c]     = d[mt][nt][2];
            Ob[(size_t)r2 * 384 + c + 1] = d[mt][nt][3];
        }
    }
}

// ---------------- zero ----------------
__global__ void zero_kernel(float* p, int n) {
    int i = blockIdx.x * blockDim.x + threadIdx.x;
    if (i < n) p[i] = 0.0f;
}

// ---------------- FPS ----------------
__global__ void __launch_bounds__(1024) fps_kernel(const float* __restrict__ pts,
                                                   float* __restrict__ ctr,
                                                   float* __restrict__ ctr_out) {
    int b = blockIdx.x;
    int tid = threadIdx.x, wid = tid >> 5, lane = tid & 31;
    const float* P = pts + (size_t)b * NP * 3;
    float px[8], py[8], pz[8], dl[8];
#pragma unroll
    for (int t = 0; t < 8; t++) {
        int j = tid + t * 1024;
        px[t] = P[j * 3 + 0]; py[t] = P[j * 3 + 1]; pz[t] = P[j * 3 + 2];
        dl[t] = 1e10f;
    }
    __shared__ float lastp[3];
    __shared__ float wv_s[32];
    __shared__ int   wi_s[32];
    if (tid == 0) {
        lastp[0] = P[0]; lastp[1] = P[1]; lastp[2] = P[2];
        size_t co = (size_t)b * NG * 3;
        ctr[co] = P[0]; ctr[co + 1] = P[1]; ctr[co + 2] = P[2];
        ctr_out[co] = P[0]; ctr_out[co + 1] = P[1]; ctr_out[co + 2] = P[2];
    }
    __syncthreads();
    for (int s = 1; s < NG; s++) {
        float lx = lastp[0], ly = lastp[1], lz = lastp[2];
        float bv = -1.0f; int bi = 0;
#pragma unroll
        for (int t = 0; t < 8; t++) {
            float dx = __fsub_rn(px[t], lx);
            float dy = __fsub_rn(py[t], ly);
            float dz = __fsub_rn(pz[t], lz);
            float d = __fadd_rn(__fadd_rn(__fmul_rn(dx, dx), __fmul_rn(dy, dy)),
                                __fmul_rn(dz, dz));
            float nd = fminf(dl[t], d);
            dl[t] = nd;
            if (nd > bv) { bv = nd; bi = tid + t * 1024; }
        }
#pragma unroll
        for (int o = 16; o; o >>= 1) {
            float v2 = __shfl_xor_sync(0xFFFFFFFFu, bv, o);
            int   i2 = __shfl_xor_sync(0xFFFFFFFFu, bi, o);
            if (v2 > bv || (v2 == bv && i2 < bi)) { bv = v2; bi = i2; }
        }
        if (lane == 0) { wv_s[wid] = bv; wi_s[wid] = bi; }
        __syncthreads();
        if (wid == 0) {
            bv = wv_s[lane]; bi = wi_s[lane];
#pragma unroll
            for (int o = 16; o; o >>= 1) {
                float v2 = __shfl_xor_sync(0xFFFFFFFFu, bv, o);
                int   i2 = __shfl_xor_sync(0xFFFFFFFFu, bi, o);
                if (v2 > bv || (v2 == bv && i2 < bi)) { bv = v2; bi = i2; }
            }
            if (lane == 0) {
                float qx = P[bi * 3], qy = P[bi * 3 + 1], qz = P[bi * 3 + 2];
                lastp[0] = qx; lastp[1] = qy; lastp[2] = qz;
                size_t co = ((size_t)b * NG + s) * 3;
                ctr[co] = qx; ctr[co + 1] = qy; ctr[co + 2] = qz;
                ctr_out[co] = qx; ctr_out[co + 1] = qy; ctr_out[co + 2] = qz;
            }
        }
        __syncthreads();
    }
}

// ---------------- KNN: tournament argmin ----------------
__device__ __forceinline__ unsigned long long knn_key(float v, int idx) {
    uint32_t b = __float_as_uint(v);
    b = (b & 0x80000000u) ? ~b : (b | 0x80000000u);
    return ((unsigned long long)b << 32) | (uint32_t)idx;
}

__global__ void __launch_bounds__(256) knn_kernel(const float* __restrict__ pts,
                                                  const float* __restrict__ ctr,
                                                  float* __restrict__ nbr_out) {
    int bg = blockIdx.x;
    int b = bg >> 9;
    const float* P = pts + (size_t)b * NP * 3;
    float cx = ctr[bg * 3 + 0], cy = ctr[bg * 3 + 1], cz = ctr[bg * 3 + 2];
    float c2 = __fadd_rn(__fadd_rn(__fmul_rn(cx, cx), __fmul_rn(cy, cy)), __fmul_rn(cz, cz));
    __shared__ float d2s[NP];
    int tid = threadIdx.x;
    for (int j = tid; j < NP; j += 256) {
        float px = P[j * 3], py = P[j * 3 + 1], pz = P[j * 3 + 2];
        float p2 = __fadd_rn(__fadd_rn(__fmul_rn(px, px), __fmul_rn(py, py)), __fmul_rn(pz, pz));
        float dot = __fmaf_rn(cz, pz, __fmaf_rn(cy, py, __fmul_rn(cx, px)));
        d2s[j] = __fsub_rn(__fadd_rn(c2, p2), __fmul_rn(2.0f, dot));
    }
    __syncthreads();

    unsigned long long mykey = ~0ull;
#pragma unroll
    for (int t = 0; t < 32; t++) {
        int j = tid + t * 256;
        unsigned long long k = knn_key(d2s[j], j);
        if (k < mykey) mykey = k;
    }

    __shared__ unsigned long long wmin[8];
    __shared__ unsigned long long winner;
    __shared__ int chosen[NK];
    const int warp = tid >> 5, lane = tid & 31;

    for (int sel = 0; sel < NK; sel++) {
        unsigned long long k = mykey;
#pragma unroll
        for (int o = 16; o; o >>= 1) {
            unsigned long long k2 = __shfl_xor_sync(0xFFFFFFFFu, k, o);
            if (k2 < k) k = k2;
        }
        if (lane == 0) wmin[warp] = k;
        __syncthreads();
        if (tid == 0) {
            unsigned long long w = wmin[0];
#pragma unroll
            for (int i = 1; i < 8; i++) if (wmin[i] < w) w = wmin[i];
            winner = w;
            chosen[sel] = (int)(w & 0xffffffffu);
        }
        __syncthreads();
        int widx = (int)(winner & 0xffffffffu);
        if ((widx & 255) == tid) {
            d2s[widx] = 3.4e38f;
            mykey = ~0ull;
#pragma unroll
            for (int t = 0; t < 32; t++) {
                int j = tid + t * 256;
                unsigned long long kk = knn_key(d2s[j], j);
                if (kk < mykey) mykey = kk;
            }
        }
    }
    __syncthreads();
    if (tid < NK) {
        int j = chosen[tid];
        size_t o = ((size_t)bg * NK + tid) * 3;
        nbr_out[o + 0] = P[j * 3 + 0] - cx;
        nbr_out[o + 1] = P[j * 3 + 1] - cy;
        nbr_out[o + 2] = P[j * 3 + 2] - cz;
    }
}

// ---------------- nbr moments (analytic BN1) ----------------
__global__ void __launch_bounds__(256) moments_kernel(const float* __restrict__ nbr,
                                                      float* __restrict__ mom) {
    int t = blockIdx.x * 256 + threadIdx.x;
    float s[9];
#pragma unroll
    for (int i = 0; i < 9; i++) s[i] = 0.f;
    for (int r = t; r < M1; r += 65536) {
        float a = nbr[(size_t)r * 3], b = nbr[(size_t)r * 3 + 1], c = nbr[(size_t)r * 3 + 2];
        s[0] += a; s[1] += b; s[2] += c;
        s[3] += a * a; s[4] += b * b; s[5] += c * c;
        s[6] += a * b; s[7] += a * c; s[8] += b * c;
    }
#pragma unroll
    for (int i = 0; i < 9; i++)
#pragma unroll
        for (int o = 16; o; o >>= 1) s[i] += __shfl_xor_sync(0xFFFFFFFFu, s[i], o);
    __shared__ float sh[8][9];
    int wid = threadIdx.x >> 5, lane = threadIdx.x & 31;
    if (lane == 0)
#pragma unroll
        for (int i = 0; i < 9; i++) sh[wid][i] = s[i];
    __syncthreads();
    if (threadIdx.x < 9) {
        float a = 0.f;
#pragma unroll
        for (int w = 0; w < 8; w++) a += sh[w][threadIdx.x];
        atomicAdd(&mom[threadIdx.x], a);
    }
}

__global__ void bnfin1_kernel(const float* __restrict__ mom,
                              const float* __restrict__ w1, const float* __restrict__ b1,
                              const float* __restrict__ g, const float* __restrict__ bb,
                              float* __restrict__ scale, float* __restrict__ shift) {
    int c = threadIdx.x;
    float inv = 1.0f / (float)M1;
    float m0 = mom[0] * inv, m1 = mom[1] * inv, m2 = mom[2] * inv;
    float C00 = mom[3] * inv - m0 * m0;
    float C11 = mom[4] * inv - m1 * m1;
    float C22 = mom[5] * inv - m2 * m2;
    float C01 = mom[6] * inv - m0 * m1;
    float C02 = mom[7] * inv - m0 * m2;
    float C12 = mom[8] * inv - m1 * m2;
    float w0 = w1[c], wv1 = w1[128 + c], wv2 = w1[256 + c];
    float var = C00 * w0 * w0 + C11 * wv1 * wv1 + C22 * wv2 * wv2 +
                2.0f * (C01 * w0 * wv1 + C02 * w0 * wv2 + C12 * wv1 * wv2);
    float mean = m0 * w0 + m1 * wv1 + m2 * wv2 + b1[c];
    float r = rsqrtf(var + 1e-5f);
    float sc = g[c] * r;
    scale[c] = sc;
    shift[c] = bb[c] - mean * sc;
}

__global__ void bnfin_kernel(const float* __restrict__ s1, const float* __restrict__ s2,
                             float invM, const float* __restrict__ g, const float* __restrict__ b,
                             float* __restrict__ scale, float* __restrict__ shift) {
    int c = threadIdx.x;
    float mean = s1[c] * invM;
    float var = s2[c] * invM - mean * mean;
    float r = rsqrtf(var + 1e-5f);
    float sc = g[c] * r;
    scale[c] = sc;
    shift[c] = b[c] - mean * sc;
}

// ---------------- layernorm: one warp per 384-col row ----------------
__global__ void __launch_bounds__(256) ln_kernel(const float* __restrict__ in,
                                                 float* __restrict__ out,
                                                 const float* __restrict__ gg,
                                                 const float* __restrict__ bb) {
    const int warp = threadIdx.x >> 5, lane = threadIdx.x & 31;
    const size_t row = (size_t)blockIdx.x * 8 + warp;
    const float* p = in + row * 384;
    float v[12];
#pragma unroll
    for (int j = 0; j < 3; j++)
        *(float4*)&v[j * 4] = *(const float4*)&p[lane * 4 + j * 128];
    float s = 0.f;
#pragma unroll
    for (int j = 0; j < 12; j++) s += v[j];
#pragma unroll
    for (int o = 16; o; o >>= 1) s += __shfl_xor_sync(0xFFFFFFFFu, s, o);
    float mean = s * (1.0f / 384.0f);
    float q = 0.f;
#pragma unroll
    for (int j = 0; j < 12; j++) { v[j] -= mean; q += v[j] * v[j]; }
#pragma unroll
    for (int o = 16; o; o >>= 1) q += __shfl_xor_sync(0xFFFFFFFFu, q, o);
    float rstd = rsqrtf(q * (1.0f / 384.0f) + 1e-5f);
    float* op = out + row * 384;
#pragma unroll
    for (int j = 0; j < 3; j++) {
        float4 gv = *(const float4*)&gg[lane * 4 + j * 128];
        float4 bv = *(const float4*)&bb[lane * 4 + j * 128];
        float4 o4;
        o4.x = v[j * 4 + 0] * rstd * gv.x + bv.x;
        o4.y = v[j * 4 + 1] * rstd * gv.y + bv.y;
        o4.z = v[j * 4 + 2] * rstd * gv.z + bv.z;
        o4.w = v[j * 4 + 3] * rstd * gv.w + bv.w;
        *(float4*)&op[lane * 4 + j * 128] = o4;
    }
}

// xin = x + pos; out = LN(xin); one warp per row
__global__ void __launch_bounds__(256) ln_add_kernel(const float* __restrict__ x,
                                                     const float* __restrict__ pos,
                                                     float* __restrict__ xin,
                                                     float* __restrict__ out,
                                                     const float* __restrict__ gg,
                                                     const float* __restrict__ bb) {
    const int warp = threadIdx.x >> 5, lane = threadIdx.x & 31;
    const size_t row = (size_t)blockIdx.x * 8 + warp;
    const float* p = x + row * 384;
    const float* pp = pos + row * 384;
    float v[12];
#pragma unroll
    for (int j = 0; j < 3; j++) {
        float4 a = *(const float4*)&p[lane * 4 + j * 128];
        float4 b = *(const float4*)&pp[lane * 4 + j * 128];
        a.x += b.x; a.y += b.y; a.z += b.z; a.w += b.w;
        *(float4*)&v[j * 4] = a;
        *(float4*)&xin[row * 384 + lane * 4 + j * 128] = a;
    }
    float s = 0.f;
#pragma unroll
    for (int j = 0; j < 12; j++) s += v[j];
#pragma unroll
    for (int o = 16; o; o >>= 1) s += __shfl_xor_sync(0xFFFFFFFFu, s, o);
    float mean = s * (1.0f / 384.0f);
    float q = 0.f;
#pragma unroll
    for (int j = 0; j < 12; j++) { v[j] -= mean; q += v[j] * v[j]; }
#pragma unroll
    for (int o = 16; o; o >>= 1) q += __shfl_xor_sync(0xFFFFFFFFu, q, o);
    float rstd = rsqrtf(q * (1.0f / 384.0f) + 1e-5f);
    float* op = out + row * 384;
#pragma unroll
    for (int j = 0; j < 3; j++) {
        float4 gv = *(const float4*)&gg[lane * 4 + j * 128];
        float4 bv = *(const float4*)&bb[lane * 4 + j * 128];
        float4 o4;
        o4.x = v[j * 4 + 0] * rstd * gv.x + bv.x;
        o4.y = v[j * 4 + 1] * rstd * gv.y + bv.y;
        o4.z = v[j * 4 + 2] * rstd * gv.z + bv.z;
        o4.w = v[j * 4 + 3] * rstd * gv.w + bv.w;
        *(float4*)&op[lane * 4 + j * 128] = o4;
    }
}

// ---------------- pos embed ----------------
__global__ void __launch_bounds__(128) pos_kernel(const float* __restrict__ ctr,
                                                  const float* __restrict__ pw1,
                                                  const float* __restrict__ pb1,
                                                  const float* __restrict__ pw2,
                                                  const float* __restrict__ pb2,
                                                  float* __restrict__ pos) {
    int row = blockIdx.x;
    int tid = threadIdx.x;
    float cx = ctr[row * 3], cy = ctr[row * 3 + 1], cz = ctr[row * 3 + 2];
    __shared__ float t[128];
    float u = cx * pw1[tid] + cy * pw1[128 + tid] + cz * pw1[256 + tid] + pb1[tid];
    t[tid] = gelu_f(u);
    __syncthreads();
    for (int j = tid; j < 384; j += 128) {
        float s = pb2[j];
#pragma unroll 8
        for (int k = 0; k < 128; k++) s = fmaf(t[k], pw2[k * 384 + j], s);
        pos[(size_t)row * 384 + j] = s;
    }
}

// ---------------- host ----------------
extern "C" void kernel_launch(void* const* d_in, const int* in_sizes, int n_in,
                              void* d_out, int out_size) {
    const float* pts   = (const float*)d_in[0];
    const float* w1    = (const float*)d_in[1];
    const float* b1    = (const float*)d_in[2];
    const float* bn1g  = (const float*)d_in[3];
    const float* bn1b  = (const float*)d_in[4];
    const float* w2    = (const float*)d_in[5];
    const float* b2    = (const float*)d_in[6];
    const float* w3    = (const float*)d_in[7];
    const float* b3    = (const float*)d_in[8];
    const float* bn2g  = (const float*)d_in[9];
    const float* bn2b  = (const float*)d_in[10];
    const float* w4    = (const float*)d_in[11];
    const float* b4    = (const float*)d_in[12];
    const float* pw1   = (const float*)d_in[13];
    const float* pb1   = (const float*)d_in[14];
    const float* pw2   = (const float*)d_in[15];
    const float* pb2   = (const float*)d_in[16];
    const float* ln1g  = (const float*)d_in[17];
    const float* ln1b  = (const float*)d_in[18];
    const float* qkvw  = (const float*)d_in[19];
    const float* projw = (const float*)d_in[20];
    const float* projb = (const float*)d_in[21];
    const float* ln2g  = (const float*)d_in[22];
    const float* ln2b  = (const float*)d_in[23];
    const float* fc1w  = (const float*)d_in[24];
    const float* fc1b  = (const float*)d_in[25];
    const float* fc2w  = (const float*)d_in[26];
    const float* fc2b  = (const float*)d_in[27];
    const float* nfg   = (const float*)d_in[28];
    const float* nfb   = (const float*)d_in[29];

    static float* S = nullptr;
    if (!S) {
        cudaGetSymbolAddress((void**)&S, g_scratch);
        cudaFuncSetAttribute(mmagemm_kernel<3, 5, 128>, cudaFuncAttributeMaxDynamicSharedMemorySize, GE_SMEM);
        cudaFuncSetAttribute(mmagemm_kernel<0, 0, 128>, cudaFuncAttributeMaxDynamicSharedMemorySize, GE_SMEM);
        cudaFuncSetAttribute(mmagemm_kernel<0, 6, 128>, cudaFuncAttributeMaxDynamicSharedMemorySize, GE_SMEM);
        cudaFuncSetAttribute(mmagemm_kernel<1, 4, 128>, cudaFuncAttributeMaxDynamicSharedMemorySize, GE_SMEM);
        cudaFuncSetAttribute(mmagemm_kernel<0, 2, 128>, cudaFuncAttributeMaxDynamicSharedMemorySize, GE_SMEM);
        cudaFuncSetAttribute(mmagemm_kernel<0, 1, 64>,  cudaFuncAttributeMaxDynamicSharedMemorySize, GE_SMEM64);
        cudaFuncSetAttribute(attn_qk_mma, cudaFuncAttributeMaxDynamicSharedMemorySize, QK_SMEM);
        cudaFuncSetAttribute(attn_av_mma, cudaFuncAttributeMaxDynamicSharedMemorySize, AV_SMEM);
    }

    uint32_t* PK = (uint32_t*)(S + O_PK);
    float* f    = S + O_F;
    float* h3   = S + O_H3;
    float* fg   = S + O_FG;
    float* x    = S + O_X;
    float* xin  = S + O_XIN;
    float* hln  = S + O_HLN;
    float* ob   = S + O_OB;
    float* pos  = S + O_POS;
    float* qkv  = S + O_QKV;
    float* sc   = S + O_SC;
    float* ff   = S + O_FF;
    float* ctr  = S + O_CTR;
    float* st   = S + O_ST;
    float* mom = st;
    float* s1b = st + 256, *s2b = st + 768;
    float* scale1 = st + 1280, *shift1 = st + 1408;
    float* scale2 = st + 1536, *shift2 = st + 2048;

    float* out     = (float*)d_out;
    float* out_x   = out;
    float* out_nbr = out + (size_t)BGc * 384;
    float* out_ctr = out_nbr + (size_t)BGc * NK * 3;

    zero_kernel<<<16, 256>>>(st, 4096);

    WJobs jobs;
    jobs.j[0] = { qkvw,  (uint32_t)PK_QKV_HI,  (uint32_t)PK_QKV_LO,  384, 1152, 12 };
    jobs.j[1] = { fc1w,  (uint32_t)PK_FC1_HI,  (uint32_t)PK_FC1_LO,  384, 1536, 12 };
    jobs.j[2] = { fc2w,  (uint32_t)PK_FC2_HI,  (uint32_t)PK_FC2_LO,  1536, 384, 12 };
    jobs.j[3] = { projw, (uint32_t)PK_PROJ_HI, (uint32_t)PK_PROJ_LO, 384, 384, 12 };
    jobs.j[4] = { w2,    (uint32_t)PK_W2_HI,   (uint32_t)PK_W2_LO,   128, 256, 1 };
    jobs.j[5] = { w3,    (uint32_t)PK_W3_HI,   (uint32_t)PK_W3_LO,   512, 512, 1 };
    jobs.j[6] = { w4,    (uint32_t)PK_W4_HI,   (uint32_t)PK_W4_LO,   512, 384, 1 };
    wprep_all_kernel<<<dim3(144, 12, 7), 256>>>(jobs, PK);

    fps_kernel<<<NB, 1024>>>(pts, ctr, out_ctr);
    knn_kernel<<<BGc, 256>>>(pts, ctr, out_nbr);

    moments_kernel<<<256, 256>>>(out_nbr, mom);
    bnfin1_kernel<<<1, 128>>>(mom, w1, b1, bn1g, bn1b, scale1, shift1);

    mmagemm_kernel<3, 5, 128><<<dim3(2, 2048), 256, GE_SMEM>>>(
        out_nbr, PK + PK_W2_HI, PK + PK_W2_LO, b2, nullptr, f,
        M1, 256, 128, scale1, shift1, fg, w1, b1);
    mmagemm_kernel<0, 0, 128><<<dim3(4, 64), 256, GE_SMEM>>>(
        fg, PK + PK_W3_HI, PK + PK_W3_LO, b3, nullptr, ff,
        BGc, 512, 256, nullptr, nullptr, nullptr, nullptr, nullptr);
    // h3 = f @ w3[256:512] + base[group], with fused BN column stats -> s1b/s2b
    mmagemm_kernel<0, 6, 128><<<dim3(4, 2048), 256, GE_SMEM>>>(
        f, PK + PK_W3_HI + 8 * 512 * 16, PK + PK_W3_LO + 8 * 512 * 16, nullptr, ff, h3,
        M1, 512, 256, s1b, s2b, nullptr, nullptr, nullptr);
    bnfin_kernel<<<1, 512>>>(s1b, s2b, 1.0f / (float)M1, bn2g, bn2b, scale2, shift2);
    mmagemm_kernel<1, 4, 128><<<dim3(3, 2048), 256, GE_SMEM>>>(
        h3, PK + PK_W4_HI, PK + PK_W4_LO, b4, nullptr, x,
        M1, 384, 512, scale2, shift2, nullptr, nullptr, nullptr);

    pos_kernel<<<BGc, 128>>>(ctr, pw1, pb1, pw2, pb2, pos);

    for (int l = 0; l < NL; l++) {
        ln_add_kernel<<<BGc / 8, 256>>>(x, pos, xin, hln, ln1g + l * 384, ln1b + l * 384);
        mmagemm_kernel<0, 0, 128><<<dim3(9, 64), 256, GE_SMEM>>>(
            hln, PK + PK_QKV_HI + (size_t)l * (384 * 1152 / 2),
            PK + PK_QKV_LO + (size_t)l * (384 * 1152 / 2), nullptr, nullptr, qkv,
            BGc, 1152, 384, nullptr, nullptr, nullptr, nullptr, nullptr);
        attn_qk_mma<<<dim3(4, 4, NB * NH), 256, QK_SMEM>>>(qkv, sc);
        softmax_kernel<<<NB * NH * 512 / 8, 256>>>(sc);
        attn_av_mma<<<dim3(4, NB * NH), 256, AV_SMEM>>>(sc, qkv, ob);
        mmagemm_kernel<0, 1, 64><<<dim3(6, 64), 256, GE_SMEM64>>>(
            ob, PK + PK_PROJ_HI + (size_t)l * (384 * 384 / 2),
            PK + PK_PROJ_LO + (size_t)l * (384 * 384 / 2), projb + l * 384, xin, x,
            BGc, 384, 384, nullptr, nullptr, nullptr, nullptr, nullptr);
        ln_kernel<<<BGc / 8, 256>>>(x, hln, ln2g + l * 384, ln2b + l * 384);
        mmagemm_kernel<0, 2, 128><<<dim3(12, 64), 256, GE_SMEM>>>(
            hln, PK + PK_FC1_HI + (size_t)l * (384 * 1536 / 2),
            PK + PK_FC1_LO + (size_t)l * (384 * 1536 / 2), fc1b + l * 1536, nullptr, ff,
            BGc, 1536, 384, nullptr, nullptr, nullptr, nullptr, nullptr);
        mmagemm_kernel<0, 1, 64><<<dim3(6, 64), 256, GE_SMEM64>>>(
            ff, PK + PK_FC2_HI + (size_t)l * (1536 * 384 / 2),
            PK + PK_FC2_LO + (size_t)l * (1536 * 384 / 2), fc2b + l * 384, x, x,
            BGc, 384, 1536, nullptr, nullptr, nullptr, nullptr, nullptr);
    }
    ln_kernel<<<BGc / 8, 256>>>(x, out_x, nfg, nfb);
}

// round 17
// speedup vs baseline: 1.0785x; 1.0225x over previous
#include <cuda_runtime.h>
#include <math.h>
#include <stdint.h>

// Problem dims
#define NB 16
#define NP 8192
#define NG 512
#define NK 32
#define ND 384
#define NL 12
#define NH 6
#define BGc (NB*NG)      /* 8192 */
#define M1  (BGc*NK)     /* 262144 */

// ---------------- scratch layout ----------------
constexpr size_t O_PK  = 0;
constexpr size_t O_F   = O_PK  + (size_t)M1*128;
constexpr size_t O_H3  = O_F   + (size_t)M1*256;
constexpr size_t O_F4  = O_H3  + (size_t)M1*512;
constexpr size_t O_FG  = O_F4  + (size_t)M1*384;
constexpr size_t O_X   = O_FG  + (size_t)BGc*256;
constexpr size_t O_XIN = O_X   + (size_t)BGc*384;
constexpr size_t O_HLN = O_XIN + (size_t)BGc*384;
constexpr size_t O_OB  = O_HLN + (size_t)BGc*384;
constexpr size_t O_POS = O_OB  + (size_t)BGc*384;
constexpr size_t O_QKV = O_POS + (size_t)BGc*384;
constexpr size_t O_SC  = O_QKV + (size_t)BGc*1152;
constexpr size_t O_FF  = O_SC  + (size_t)96*512*512;
constexpr size_t O_CTR = O_FF  + (size_t)BGc*1536;
constexpr size_t O_ST  = O_CTR + (size_t)BGc*3;
constexpr size_t SCRATCH_TOTAL = O_ST + 4096;

__device__ float g_scratch[SCRATCH_TOTAL];

// packed weight sub-offsets (words, within O_PK)
constexpr size_t PK_QKV_HI  = 0;
constexpr size_t PK_QKV_LO  = PK_QKV_HI + (size_t)12*384*1152/2;
constexpr size_t PK_FC1_HI  = PK_QKV_LO + (size_t)12*384*1152/2;
constexpr size_t PK_FC1_LO  = PK_FC1_HI + (size_t)12*384*1536/2;
constexpr size_t PK_FC2_HI  = PK_FC1_LO + (size_t)12*384*1536/2;
constexpr size_t PK_FC2_LO  = PK_FC2_HI + (size_t)12*1536*384/2;
constexpr size_t PK_PROJ_HI = PK_FC2_LO + (size_t)12*1536*384/2;
constexpr size_t PK_PROJ_LO = PK_PROJ_HI + (size_t)12*384*384/2;
constexpr size_t PK_W2_HI   = PK_PROJ_LO + (size_t)12*384*384/2;
constexpr size_t PK_W2_LO   = PK_W2_HI + (size_t)128*256/2;
constexpr size_t PK_W3_HI   = PK_W2_LO + (size_t)128*256/2;
constexpr size_t PK_W3_LO   = PK_W3_HI + (size_t)512*512/2;
constexpr size_t PK_W4_HI   = PK_W3_LO + (size_t)512*512/2;
constexpr size_t PK_W4_LO   = PK_W4_HI + (size_t)512*384/2;

__device__ __forceinline__ float gelu_f(float x) {
    return 0.5f * x * (1.0f + erff(x * 0.70710678118654752f));
}

// ---------------- bf16 helpers ----------------
__device__ __forceinline__ void bf16x2_split(float x0, float x1, uint32_t& hi, uint32_t& lo) {
    uint32_t h;
    asm("cvt.rn.bf16x2.f32 %0, %1, %2;" : "=r"(h) : "f"(x1), "f"(x0));
    float h0 = __uint_as_float(h << 16);
    float h1 = __uint_as_float(h & 0xffff0000u);
    float r0 = x0 - h0, r1 = x1 - h1;
    asm("cvt.rn.bf16x2.f32 %0, %1, %2;" : "=r"(lo) : "f"(r1), "f"(r0));
    hi = h;
}

__device__ __forceinline__ void mma_bf16(float* d, const uint32_t* a, uint32_t b0, uint32_t b1) {
    asm volatile(
        "mma.sync.aligned.m16n8k16.row.col.f32.bf16.bf16.f32 "
        "{%0,%1,%2,%3}, {%4,%5,%6,%7}, {%8,%9}, {%0,%1,%2,%3};"
        : "+f"(d[0]), "+f"(d[1]), "+f"(d[2]), "+f"(d[3])
        : "r"(a[0]), "r"(a[1]), "r"(a[2]), "r"(a[3]), "r"(b0), "r"(b1));
}

#define AW 24
#define BUFW (4 * 128 * AW)
static constexpr int GE_SMEM   = 2 * BUFW * 4;                 /* 98304 B (NT=128) */
static constexpr int GE_SMEM64 = 2 * (6144 + 2 * 64 * AW) * 4; /* 73728 B (NT=64) */
static constexpr int QK_SMEM = BUFW * 4;
static constexpr int AV_SMEM = (3 * 128 * AW + 2 * 64 * AW) * 4;

// ---------------- merged weight prep ----------------
struct WJob { const float* W; uint32_t hi; uint32_t lo; int K; int N; int L; };
struct WJobs { WJob j[7]; };

__global__ void wprep_all_kernel(WJobs jobs, uint32_t* __restrict__ PK) {
    const WJob& jb = jobs.j[blockIdx.z];
    if ((int)blockIdx.y >= jb.L) return;
    const int K = jb.K, N = jb.N;
    int units = (K >> 5) * 2 * N;
    int u = blockIdx.x * 256 + threadIdx.x;
    if (u >= units) return;
    size_t lw = (size_t)blockIdx.y * K * N;
    size_t lp = lw >> 1;
    int n = u % N;
    int rem = u / N;
    int half = rem & 1;
    int kb = rem >> 1;
    const float* src = jb.W + lw + (size_t)(kb * 32 + half * 16) * N + n;
    uint32_t hw[8], lwd[8];
#pragma unroll
    for (int w = 0; w < 8; w++) {
        uint32_t h, l;
        bf16x2_split(src[(size_t)(2 * w) * N], src[(size_t)(2 * w + 1) * N], h, l);
        int slot = (w & 3) * 2 + (w >> 2);
        hw[slot] = h; lwd[slot] = l;
    }
    size_t off = lp + (size_t)kb * N * 16 + (size_t)half * N * 8 + (size_t)n * 8;
    uint32_t* Phi = PK + jb.hi;
    uint32_t* Plo = PK + jb.lo;
    *(uint4*)(Phi + off)     = *(uint4*)hw;
    *(uint4*)(Phi + off + 4) = *(uint4*)(hw + 4);
    *(uint4*)(Plo + off)     = *(uint4*)lwd;
    *(uint4*)(Plo + off + 4) = *(uint4*)(lwd + 4);
}

// ============ BF16x3 mma.sync GEMM, double-buffered, packed-B ============
// EPI 0: +bias; 1: +bias+res[r]; 2: gelu(+bias); 3: +res[(r>>5)];
// EPI 4: group-max only; 5: +bias write C AND group-max -> gout;
// EPI 6: like 3, plus fused BN column stats -> atomicAdd((float*)q0/q1)
template <int AMODE, int EPI, int NT>
__global__ void __launch_bounds__(256) mmagemm_kernel(
    const float* __restrict__ A,
    const uint32_t* __restrict__ PWhi, const uint32_t* __restrict__ PWlo,
    const float* __restrict__ bias, const float* __restrict__ res,
    float* __restrict__ C, int M, int N, int K,
    const float* __restrict__ q0, const float* __restrict__ q1,
    float* __restrict__ gout,
    const float* __restrict__ e1w, const float* __restrict__ e1b) {
    extern __shared__ uint32_t sm[];
    constexpr int NTT = NT / 16;
    constexpr int BUFN = 6144 + 2 * NT * AW;

    const int tid = threadIdx.x;
    const int warp = tid >> 5, lane = tid & 31;
    const int row0 = blockIdx.y << 7, col0 = blockIdx.x * NT;
    const int wr = (warp & 3) << 5;
    const int wc = (warp >> 2) * (NT / 2);

    float d[2][NTT][4];
#pragma unroll
    for (int mt = 0; mt < 2; mt++)
#pragma unroll
        for (int nt = 0; nt < NTT; nt++)
#pragma unroll
            for (int i = 0; i < 4; i++) d[mt][nt][i] = 0.f;

    const int arow = tid >> 1;
    const int akoff = (tid & 1) << 4;
    const int grow = row0 + arow;
    const int lg = lane >> 2;
    const int lt = lane & 3;

    auto stage = [&](int kb, uint32_t* base) {
        uint32_t* Ahi = base;
        uint32_t* Alo = base + 3072;
        uint32_t* Bhi = base + 6144;
        uint32_t* Blo = base + 6144 + NT * AW;
        const int kbase = kb << 5;
        {
            float v[16];
            const int kg = kbase + akoff;
            if (AMODE == 3) {
                float x0 = A[(size_t)grow * 3], x1 = A[(size_t)grow * 3 + 1],
                      x2 = A[(size_t)grow * 3 + 2];
#pragma unroll
                for (int c = 0; c < 16; c++) {
                    float h = fmaf(x2, e1w[256 + kg + c],
                              fmaf(x1, e1w[128 + kg + c],
                              fmaf(x0, e1w[kg + c], e1b[kg + c])));
                    v[c] = fmaxf(fmaf(h, q0[kg + c], q1[kg + c]), 0.f);
                }
            } else {
                const float* src = A + (size_t)grow * K + kg;
#pragma unroll
                for (int i = 0; i < 4; i++) *(float4*)&v[i * 4] = *(const float4*)&src[i * 4];
                if (AMODE == 1) {
#pragma unroll
                    for (int c = 0; c < 16; c++)
                        v[c] = fmaxf(fmaf(v[c], q0[kg + c], q1[kg + c]), 0.f);
                }
            }
            uint32_t* ah = Ahi + arow * AW + (akoff >> 4) * 8;
            uint32_t* al = Alo + arow * AW + (akoff >> 4) * 8;
#pragma unroll
            for (int u = 0; u < 4; u++) {
                uint32_t h1, l1, h2, l2;
                bf16x2_split(v[2 * u], v[2 * u + 1], h1, l1);
                bf16x2_split(v[2 * u + 8], v[2 * u + 9], h2, l2);
                *(uint2*)(ah + 2 * u) = make_uint2(h1, h2);
                *(uint2*)(al + 2 * u) = make_uint2(l1, l2);
            }
        }
        if (NT == 128) {
            const int bn = tid & 127;
            const int bkhalf = tid >> 7;
            size_t off = (size_t)kb * ((size_t)N * 16) + (size_t)bkhalf * N * 8 +
                         (size_t)(col0 + bn) * 8;
            const uint32_t* ph = PWhi + off;
            const uint32_t* pl = PWlo + off;
            uint32_t* bh = Bhi + bn * AW + bkhalf * 8;
            uint32_t* bl = Blo + bn * AW + bkhalf * 8;
            *(uint4*)bh       = *(const uint4*)ph;
            *(uint4*)(bh + 4) = *(const uint4*)(ph + 4);
            *(uint4*)bl       = *(const uint4*)pl;
            *(uint4*)(bl + 4) = *(const uint4*)(pl + 4);
        } else {
            const int bn = tid & 63;
            const int bkhalf = (tid >> 6) & 1;
            const int bq = tid >> 7;
            size_t off = (size_t)kb * ((size_t)N * 16) + (size_t)bkhalf * N * 8 +
                         (size_t)(col0 + bn) * 8 + bq * 4;
            uint32_t* bh = Bhi + bn * AW + bkhalf * 8 + bq * 4;
            uint32_t* bl = Blo + bn * AW + bkhalf * 8 + bq * 4;
            *(uint4*)bh = *(const uint4*)(PWhi + off);
            *(uint4*)bl = *(const uint4*)(PWlo + off);
        }
    };

    auto compute = [&](const uint32_t* base) {
        const uint32_t* Ahi = base;
        const uint32_t* Alo = base + 3072;
        const uint32_t* Bhi = base + 6144;
        const uint32_t* Blo = base + 6144 + NT * AW;
#pragma unroll
        for (int b16 = 0; b16 < 2; b16++) {
            const int bo = b16 * 8 + 2 * lt;
            uint32_t ah[2][4], al[2][4];
#pragma unroll
            for (int mt = 0; mt < 2; mt++) {
                const int r1 = wr + mt * 16 + lg;
                uint2 t0 = *(const uint2*)(Ahi + r1 * AW + bo);
                uint2 t1 = *(const uint2*)(Ahi + (r1 + 8) * AW + bo);
                ah[mt][0] = t0.x; ah[mt][1] = t1.x; ah[mt][2] = t0.y; ah[mt][3] = t1.y;
                uint2 s0 = *(const uint2*)(Alo + r1 * AW + bo);
                uint2 s1 = *(const uint2*)(Alo + (r1 + 8) * AW + bo);
                al[mt][0] = s0.x; al[mt][1] = s1.x; al[mt][2] = s0.y; al[mt][3] = s1.y;
            }
#pragma unroll
            for (int nt = 0; nt < NTT; nt++) {
                const int n = wc + nt * 8 + lg;
                uint2 bh = *(const uint2*)(Bhi + n * AW + bo);
                uint2 bl = *(const uint2*)(Blo + n * AW + bo);
#pragma unroll
                for (int mt = 0; mt < 2; mt++) {
                    mma_bf16(d[mt][nt], ah[mt], bh.x, bh.y);
                    mma_bf16(d[mt][nt], al[mt], bh.x, bh.y);
                    mma_bf16(d[mt][nt], ah[mt], bl.x, bl.y);
                }
            }
        }
    };

    const int nblk = K >> 5;
    stage(0, sm);
    __syncthreads();
    for (int kb = 0; kb < nblk; kb++) {
        compute(sm + (kb & 1) * BUFN);
        if (kb + 1 < nblk) stage(kb + 1, sm + ((kb + 1) & 1) * BUFN);
        __syncthreads();
    }

    const int g = (row0 + wr) >> 5;

    if (EPI <= 3 || EPI == 5 || EPI == 6) {
#pragma unroll
        for (int mt = 0; mt < 2; mt++) {
            const int r1 = row0 + wr + mt * 16 + lg;
            const int r2 = r1 + 8;
#pragma unroll
            for (int nt = 0; nt < NTT; nt++) {
                const int c = col0 + wc + nt * 8 + lt * 2;
                float v0 = d[mt][nt][0], v1 = d[mt][nt][1];
                float v2 = d[mt][nt][2], v3 = d[mt][nt][3];
                if (bias) {
                    float b0 = bias[c], b1 = bias[c + 1];
                    v0 += b0; v1 += b1; v2 += b0; v3 += b1;
                }
                if (EPI == 1) {
                    v0 += res[(size_t)r1 * N + c];
                    v1 += res[(size_t)r1 * N + c + 1];
                    v2 += res[(size_t)r2 * N + c];
                    v3 += res[(size_t)r2 * N + c + 1];
                } else if (EPI == 3 || EPI == 6) {
                    float g0 = res[(size_t)g * N + c];
                    float g1 = res[(size_t)g * N + c + 1];
                    v0 += g0; v1 += g1; v2 += g0; v3 += g1;
                } else if (EPI == 2) {
                    v0 = gelu_f(v0); v1 = gelu_f(v1); v2 = gelu_f(v2); v3 = gelu_f(v3);
                }
                C[(size_t)r1 * N + c]     = v0;
                C[(size_t)r1 * N + c + 1] = v1;
                C[(size_t)r2 * N + c]     = v2;
                C[(size_t)r2 * N + c + 1] = v3;
                if (EPI == 6) {
                    float ss0 = v0 + v2,           ss1 = v1 + v3;
                    float qq0 = v0 * v0 + v2 * v2, qq1 = v1 * v1 + v3 * v3;
#pragma unroll
                    for (int o = 4; o <= 16; o <<= 1) {
                        ss0 += __shfl_xor_sync(0xFFFFFFFFu, ss0, o);
                        ss1 += __shfl_xor_sync(0xFFFFFFFFu, ss1, o);
                        qq0 += __shfl_xor_sync(0xFFFFFFFFu, qq0, o);
                        qq1 += __shfl_xor_sync(0xFFFFFFFFu, qq1, o);
                    }
                    if (lane < 4) {
                        float* s1p = (float*)q0;
                        float* s2p = (float*)q1;
                        atomicAdd(s1p + c,     ss0);
                        atomicAdd(s1p + c + 1, ss1);
                        atomicAdd(s2p + c,     qq0);
                        atomicAdd(s2p + c + 1, qq1);
                    }
                }
            }
        }
    }

    if (EPI == 4 || EPI == 5) {
#pragma unroll
        for (int nt = 0; nt < NTT; nt++) {
            const int c = col0 + wc + nt * 8 + lt * 2;
            float m0v = fmaxf(fmaxf(d[0][nt][0], d[0][nt][2]),
                              fmaxf(d[1][nt][0], d[1][nt][2]));
            float m1v = fmaxf(fmaxf(d[0][nt][1], d[0][nt][3]),
                              fmaxf(d[1][nt][1], d[1][nt][3]));
#pragma unroll
            for (int o = 4; o <= 16; o <<= 1) {
                m0v = fmaxf(m0v, __shfl_xor_sync(0xFFFFFFFFu, m0v, o));
                m1v = fmaxf(m1v, __shfl_xor_sync(0xFFFFFFFFu, m1v, o));
            }
            if (lane < 4) {
                if (bias) { m0v += bias[c]; m1v += bias[c + 1]; }
                float* gp = (EPI == 5) ? gout : C;
                gp[(size_t)g * N + c]     = m0v;
                gp[(size_t)g * N + c + 1] = m1v;
            }
        }
    }
}

// ============ attention QK ============
__global__ void __launch_bounds__(256) attn_qk_mma(const float* __restrict__ qkv,
                                                   float* __restrict__ S) {
    extern __shared__ uint32_t sm[];
    uint32_t* Ahi = sm;
    uint32_t* Alo = sm + 3072;
    uint32_t* Bhi = sm + 6144;
    uint32_t* Blo = sm + 9216;
    const int z = blockIdx.z;
    const int b = z / NH, h = z - b * NH;
    const float* Qb = qkv + (size_t)b * NG * 1152 + h * 64;
    const float* Kb = Qb + 384;
    const int m0 = blockIdx.y << 7, n0 = blockIdx.x << 7;
    const int tid = threadIdx.x;
    const int warp = tid >> 5, lane = tid & 31;
    const int wr = (warp & 3) << 5, wc = (warp >> 2) << 6;
    const int arow = tid >> 1, akoff = (tid & 1) << 4;
    const int lg = lane >> 2, lt = lane & 3;

    float d[2][8][4];
#pragma unroll
    for (int mt = 0; mt < 2; mt++)
#pragma unroll
        for (int nt = 0; nt < 8; nt++)
#pragma unroll
            for (int i = 0; i < 4; i++) d[mt][nt][i] = 0.f;

#pragma unroll
    for (int kb = 0; kb < 2; kb++) {
        const int kg = (kb << 5) + akoff;
        {
            const float* src = Qb + (size_t)(m0 + arow) * 1152 + kg;
            uint32_t* ah = Ahi + arow * AW + (akoff >> 4) * 8;
            uint32_t* al = Alo + arow * AW + (akoff >> 4) * 8;
            float v[16];
#pragma unroll
            for (int i = 0; i < 4; i++) *(float4*)&v[i * 4] = *(const float4*)&src[i * 4];
#pragma unroll
            for (int u = 0; u < 4; u++) {
                uint32_t h1, l1, h2, l2;
                bf16x2_split(v[2 * u], v[2 * u + 1], h1, l1);
                bf16x2_split(v[2 * u + 8], v[2 * u + 9], h2, l2);
                *(uint2*)(ah + 2 * u) = make_uint2(h1, h2);
                *(uint2*)(al + 2 * u) = make_uint2(l1, l2);
            }
        }
        {
            const float* src = Kb + (size_t)(n0 + arow) * 1152 + kg;
            uint32_t* bh = Bhi + arow * AW + (akoff >> 4) * 8;
            uint32_t* bl = Blo + arow * AW + (akoff >> 4) * 8;
            float v[16];
#pragma unroll
            for (int i = 0; i < 4; i++) *(float4*)&v[i * 4] = *(const float4*)&src[i * 4];
#pragma unroll
            for (int u = 0; u < 4; u++) {
                uint32_t h1, l1, h2, l2;
                bf16x2_split(v[2 * u], v[2 * u + 1], h1, l1);
                bf16x2_split(v[2 * u + 8], v[2 * u + 9], h2, l2);
                *(uint2*)(bh + 2 * u) = make_uint2(h1, h2);
                *(uint2*)(bl + 2 * u) = make_uint2(l1, l2);
            }
        }
        __syncthreads();
#pragma unroll
        for (int b16 = 0; b16 < 2; b16++) {
            const int bo = b16 * 8 + 2 * lt;
            uint32_t ah[2][4], al[2][4];
#pragma unroll
            for (int mt = 0; mt < 2; mt++) {
                const int r1 = wr + mt * 16 + lg;
                uint2 t0 = *(const uint2*)(Ahi + r1 * AW + bo);
                uint2 t1 = *(const uint2*)(Ahi + (r1 + 8) * AW + bo);
                ah[mt][0] = t0.x; ah[mt][1] = t1.x; ah[mt][2] = t0.y; ah[mt][3] = t1.y;
                uint2 s0 = *(const uint2*)(Alo + r1 * AW + bo);
                uint2 s1 = *(const uint2*)(Alo + (r1 + 8) * AW + bo);
                al[mt][0] = s0.x; al[mt][1] = s1.x; al[mt][2] = s0.y; al[mt][3] = s1.y;
            }
#pragma unroll
            for (int nt = 0; nt < 8; nt++) {
                const int n = wc + nt * 8 + lg;
                uint2 bh = *(const uint2*)(Bhi + n * AW + bo);
                uint2 bl = *(const uint2*)(Blo + n * AW + bo);
#pragma unroll
                for (int mt = 0; mt < 2; mt++) {
                    mma_bf16(d[mt][nt], ah[mt], bh.x, bh.y);
                    mma_bf16(d[mt][nt], al[mt], bh.x, bh.y);
                    mma_bf16(d[mt][nt], ah[mt], bl.x, bl.y);
                }
            }
        }
        __syncthreads();
    }
    float* out = S + (size_t)z * 512 * 512;
#pragma unroll
    for (int mt = 0; mt < 2; mt++) {
        const int r1 = m0 + wr + mt * 16 + lg;
        const int r2 = r1 + 8;
#pragma unroll
        for (int nt = 0; nt < 8; nt++) {
            const int c = n0 + wc + nt * 8 + lt * 2;
            out[(size_t)r1 * 512 + c]     = d[mt][nt][0] * 0.125f;
            out[(size_t)r1 * 512 + c + 1] = d[mt][nt][1] * 0.125f;
            out[(size_t)r2 * 512 + c]     = d[mt][nt][2] * 0.125f;
            out[(size_t)r2 * 512 + c + 1] = d[mt][nt][3] * 0.125f;
        }
    }
}

// ============ softmax: one warp per 512-col row ============
__global__ void __launch_bounds__(256) softmax_kernel(float* __restrict__ S) {
    const int warp = threadIdx.x >> 5, lane = threadIdx.x & 31;
    const size_t row = (size_t)blockIdx.x * 8 + warp;
    float* p = S + row * 512;
    float v[16];
#pragma unroll
    for (int j = 0; j < 4; j++)
        *(float4*)&v[j * 4] = *(const float4*)&p[lane * 4 + j * 128];
    float m = v[0];
#pragma unroll
    for (int j = 1; j < 16; j++) m = fmaxf(m, v[j]);
#pragma unroll
    for (int o = 16; o; o >>= 1) m = fmaxf(m, __shfl_xor_sync(0xFFFFFFFFu, m, o));
    float s = 0.f;
#pragma unroll
    for (int j = 0; j < 16; j++) { v[j] = expf(v[j] - m); s += v[j]; }
#pragma unroll
    for (int o = 16; o; o >>= 1) s += __shfl_xor_sync(0xFFFFFFFFu, s, o);
    float inv = 1.0f / s;
#pragma unroll
    for (int j = 0; j < 16; j++) v[j] *= inv;
#pragma unroll
    for (int j = 0; j < 4; j++)
        *(float4*)&p[lane * 4 + j * 128] = *(float4*)&v[j * 4];
}

// ============ attention AV ============
__global__ void __launch_bounds__(256) attn_av_mma(const float* __restrict__ S,
                                                   const float* __restrict__ qkv,
                                                   float* __restrict__ O) {
    extern __shared__ uint32_t sm[];
    uint32_t* Ahi = sm;
    uint32_t* Alo = sm + 3072;
    uint32_t* Bhi = sm + 6144;
    uint32_t* Blo = sm + 6144 + 64 * AW;
    const int z = blockIdx.y;
    const int b = z / NH, h = z - b * NH;
    const float* A = S + (size_t)z * 512 * 512;
    const float* Vb = qkv + (size_t)b * NG * 1152 + 768 + h * 64;
    const int m0 = blockIdx.x << 7;
    const int tid = threadIdx.x;
    const int warp = tid >> 5, lane = tid & 31;
    const int wr = (warp & 3) << 5, wc = (warp >> 2) << 5;
    const int arow = tid >> 1, akoff = (tid & 1) << 4;
    const int bn = tid & 63, bhalf = (tid >> 6) & 1, brep = tid >> 7;
    const int lg = lane >> 2, lt = lane & 3;

    float d[2][4][4];
#pragma unroll
    for (int mt = 0; mt < 2; mt++)
#pragma unroll
        for (int nt = 0; nt < 4; nt++)
#pragma unroll
            for (int i = 0; i < 4; i++) d[mt][nt][i] = 0.f;

    for (int kb = 0; kb < 16; kb++) {
        const int kbase = kb << 5;
        {
            const float* src = A + (size_t)(m0 + arow) * 512 + kbase + akoff;
            uint32_t* ah = Ahi + arow * AW + (akoff >> 4) * 8;
            uint32_t* al = Alo + arow * AW + (akoff >> 4) * 8;
            float v[16];
#pragma unroll
            for (int i = 0; i < 4; i++) *(float4*)&v[i * 4] = *(const float4*)&src[i * 4];
#pragma unroll
            for (int u = 0; u < 4; u++) {
                uint32_t h1, l1, h2, l2;
                bf16x2_split(v[2 * u], v[2 * u + 1], h1, l1);
                bf16x2_split(v[2 * u + 8], v[2 * u + 9], h2, l2);
                *(uint2*)(ah + 2 * u) = make_uint2(h1, h2);
                *(uint2*)(al + 2 * u) = make_uint2(l1, l2);
            }
        }
        {
            uint32_t* bh = Bhi + bn * AW + bhalf * 8;
            uint32_t* bl = Blo + bn * AW + bhalf * 8;
#pragma unroll
            for (int p = 0; p < 4; p++) {
                const int k0 = kbase + bhalf * 16 + brep * 8 + 2 * p;
                float v0 = Vb[(size_t)k0 * 1152 + bn];
                float v1 = Vb[(size_t)(k0 + 1) * 1152 + bn];
                uint32_t hh, ll;
                bf16x2_split(v0, v1, hh, ll);
                bh[2 * p + brep] = hh;
                bl[2 * p + brep] = ll;
            }
        }
        __syncthreads();
#pragma unroll
        for (int b16 = 0; b16 < 2; b16++) {
            const int bo = b16 * 8 + 2 * lt;
            uint32_t ah[2][4], al[2][4];
#pragma unroll
            for (int mt = 0; mt < 2; mt++) {
                const int r1 = wr + mt * 16 + lg;
                uint2 t0 = *(const uint2*)(Ahi + r1 * AW + bo);
                uint2 t1 = *(const uint2*)(Ahi + (r1 + 8) * AW + bo);
                ah[mt][0] = t0.x; ah[mt][1] = t1.x; ah[mt][2] = t0.y; ah[mt][3] = t1.y;
                uint2 s0 = *(const uint2*)(Alo + r1 * AW + bo);
                uint2 s1 = *(const uint2*)(Alo + (r1 + 8) * AW + bo);
                al[mt][0] = s0.x; al[mt][1] = s1.x; al[mt][2] = s0.y; al[mt][3] = s1.y;
            }
#pragma unroll
            for (int nt = 0; nt < 4; nt++) {
                const int n = wc + nt * 8 + lg;
                uint2 bh = *(const uint2*)(Bhi + n * AW + bo);
                uint2 bl = *(const uint2*)(Blo + n * AW + bo);
#pragma unroll
                for (int mt = 0; mt < 2; mt++) {
                    mma_bf16(d[mt][nt], ah[mt], bh.x, bh.y);
                    mma_bf16(d[mt][nt], al[mt], bh.x, bh.y);
                    mma_bf16(d[mt][nt], ah[mt], bl.x, bl.y);
                }
            }
        }
        __syncthreads();
    }
    float* Ob = O + (size_t)b * NG * 384 + h * 64;
#pragma unroll
    for (int mt = 0; mt < 2; mt++) {
        const int r1 = m0 + wr + mt * 16 + lg;
        const int r2 = r1 + 8;
#pragma unroll
        for (int nt = 0; nt < 4; nt++) {
            const int c = wc + nt * 8 + lt * 2;
            Ob[(size_t)r1 * 384 + c]     = d[mt][nt][0];
            Ob[(size_t)r1 * 384 + c + 1] = d[mt][nt][1];
            Ob[(size_t)r2 * 384 + c]     = d[mt][nt][2];
            Ob[(size_t)r2 * 384 + c + 1] = d[mt][nt][3];
        }
    }
}

// ---------------- zero ----------------
__global__ void zero_kernel(float* p, int n) {
    int i = blockIdx.x * blockDim.x + threadIdx.x;
    if (i < n) p[i] = 0.0f;
}

// ---------------- FPS ----------------
__global__ void __launch_bounds__(1024) fps_kernel(const float* __restrict__ pts,
                                                   float* __restrict__ ctr,
                                                   float* __restrict__ ctr_out) {
    int b = blockIdx.x;
    int tid = threadIdx.x, wid = tid >> 5, lane = tid & 31;
    const float* P = pts + (size_t)b * NP * 3;
    float px[8], py[8], pz[8], dl[8];
#pragma unroll
    for (int t = 0; t < 8; t++) {
        int j = tid + t * 1024;
        px[t] = P[j * 3 + 0]; py[t] = P[j * 3 + 1]; pz[t] = P[j * 3 + 2];
        dl[t] = 1e10f;
    }
    __shared__ float lastp[3];
    __shared__ float wv_s[32];
    __shared__ int   wi_s[32];
    if (tid == 0) {
        lastp[0] = P[0]; lastp[1] = P[1]; lastp[2] = P[2];
        size_t co = (size_t)b * NG * 3;
        ctr[co] = P[0]; ctr[co + 1] = P[1]; ctr[co + 2] = P[2];
        ctr_out[co] = P[0]; ctr_out[co + 1] = P[1]; ctr_out[co + 2] = P[2];
    }
    __syncthreads();
    for (int s = 1; s < NG; s++) {
        float lx = lastp[0], ly = lastp[1], lz = lastp[2];
        float bv = -1.0f; int bi = 0;
#pragma unroll
        for (int t = 0; t < 8; t++) {
            float dx = __fsub_rn(px[t], lx);
            float dy = __fsub_rn(py[t], ly);
            float dz = __fsub_rn(pz[t], lz);
            float d = __fadd_rn(__fadd_rn(__fmul_rn(dx, dx), __fmul_rn(dy, dy)),
                                __fmul_rn(dz, dz));
            float nd = fminf(dl[t], d);
            dl[t] = nd;
            if (nd > bv) { bv = nd; bi = tid + t * 1024; }
        }
#pragma unroll
        for (int o = 16; o; o >>= 1) {
            float v2 = __shfl_xor_sync(0xFFFFFFFFu, bv, o);
            int   i2 = __shfl_xor_sync(0xFFFFFFFFu, bi, o);
            if (v2 > bv || (v2 == bv && i2 < bi)) { bv = v2; bi = i2; }
        }
        if (lane == 0) { wv_s[wid] = bv; wi_s[wid] = bi; }
        __syncthreads();
        if (wid == 0) {
            bv = wv_s[lane]; bi = wi_s[lane];
#pragma unroll
            for (int o = 16; o; o >>= 1) {
                float v2 = __shfl_xor_sync(0xFFFFFFFFu, bv, o);
                int   i2 = __shfl_xor_sync(0xFFFFFFFFu, bi, o);
                if (v2 > bv || (v2 == bv && i2 < bi)) { bv = v2; bi = i2; }
            }
            if (lane == 0) {
                float qx = P[bi * 3], qy = P[bi * 3 + 1], qz = P[bi * 3 + 2];
                lastp[0] = qx; lastp[1] = qy; lastp[2] = qz;
                size_t co = ((size_t)b * NG + s) * 3;
                ctr[co] = qx; ctr[co + 1] = qy; ctr[co + 2] = qz;
                ctr_out[co] = qx; ctr_out[co + 1] = qy; ctr_out[co + 2] = qz;
            }
        }
        __syncthreads();
    }
}

// ---------------- KNN: cached tournament argmin, warp-assisted updates ----------------
__device__ __forceinline__ unsigned long long knn_key(float v, int idx) {
    uint32_t b = __float_as_uint(v);
    b = (b & 0x80000000u) ? ~b : (b | 0x80000000u);
    return ((unsigned long long)b << 32) | (uint32_t)idx;
}

__global__ void __launch_bounds__(256) knn_kernel(const float* __restrict__ pts,
                                                  const float* __restrict__ ctr,
                                                  float* __restrict__ nbr_out) {
    int bg = blockIdx.x;
    int b = bg >> 9;
    const float* P = pts + (size_t)b * NP * 3;
    float cx = ctr[bg * 3 + 0], cy = ctr[bg * 3 + 1], cz = ctr[bg * 3 + 2];
    float c2 = __fadd_rn(__fadd_rn(__fmul_rn(cx, cx), __fmul_rn(cy, cy)), __fmul_rn(cz, cz));
    __shared__ float d2s[NP];
    int tid = threadIdx.x;
    for (int j = tid; j < NP; j += 256) {
        float px = P[j * 3], py = P[j * 3 + 1], pz = P[j * 3 + 2];
        float p2 = __fadd_rn(__fadd_rn(__fmul_rn(px, px), __fmul_rn(py, py)), __fmul_rn(pz, pz));
        float dot = __fmaf_rn(cz, pz, __fmaf_rn(cy, py, __fmul_rn(cx, px)));
        d2s[j] = __fsub_rn(__fadd_rn(c2, p2), __fmul_rn(2.0f, dot));
    }
    __syncthreads();

    // per-thread cached min over its strided 32 elements
    unsigned long long mykey = ~0ull;
#pragma unroll
    for (int t = 0; t < 32; t++) {
        int j = tid + t * 256;
        unsigned long long k = knn_key(d2s[j], j);
        if (k < mykey) mykey = k;
    }

    __shared__ unsigned long long wmin[8];
    __shared__ unsigned long long winner;
    __shared__ int chosen[NK];
    const int warp = tid >> 5, lane = tid & 31;

    // initial per-warp reduce (cached across rounds)
    {
        unsigned long long k = mykey;
#pragma unroll
        for (int o = 16; o; o >>= 1) {
            unsigned long long k2 = __shfl_xor_sync(0xFFFFFFFFu, k, o);
            if (k2 < k) k = k2;
        }
        if (lane == 0) wmin[warp] = k;
    }
    __syncthreads();

    for (int sel = 0; sel < NK; sel++) {
        if (tid == 0) {
            unsigned long long w = wmin[0];
#pragma unroll
            for (int i = 1; i < 8; i++) if (wmin[i] < w) w = wmin[i];
            winner = w;
            chosen[sel] = (int)(w & 0xffffffffu);
        }
        __syncthreads();
        const int widx = (int)(winner & 0xffffffffu);
        const int owner = widx & 255;
        if ((owner >> 5) == warp) {
            // winner's warp: invalidate, then cooperatively rescan owner's 32 elems
            if (owner == tid) d2s[widx] = 3.4e38f;
            __syncwarp();
            const int j = owner + lane * 256;
            unsigned long long k1 = knn_key(d2s[j], j);
#pragma unroll
            for (int o = 16; o; o >>= 1) {
                unsigned long long k2 = __shfl_xor_sync(0xFFFFFFFFu, k1, o);
                if (k2 < k1) k1 = k2;
            }
            if (owner == tid) mykey = k1;
            // re-reduce this warp's cached minima
            unsigned long long k3 = mykey;
#pragma unroll
            for (int o = 16; o; o >>= 1) {
                unsigned long long k4 = __shfl_xor_sync(0xFFFFFFFFu, k3, o);
                if (k4 < k3) k3 = k4;
            }
            if (lane == 0) wmin[warp] = k3;
        }
        __syncthreads();
    }
    if (tid < NK) {
        int j = chosen[tid];
        size_t o = ((size_t)bg * NK + tid) * 3;
        nbr_out[o + 0] = P[j * 3 + 0] - cx;
        nbr_out[o + 1] = P[j * 3 + 1] - cy;
        nbr_out[o + 2] = P[j * 3 + 2] - cz;
    }
}

// ---------------- nbr moments (analytic BN1) ----------------
__global__ void __launch_bounds__(256) moments_kernel(const float* __restrict__ nbr,
                                                      float* __restrict__ mom) {
    int t = blockIdx.x * 256 + threadIdx.x;
    float s[9];
#pragma unroll
    for (int i = 0; i < 9; i++) s[i] = 0.f;
    for (int r = t; r < M1; r += 65536) {
        float a = nbr[(size_t)r * 3], b = nbr[(size_t)r * 3 + 1], c = nbr[(size_t)r * 3 + 2];
        s[0] += a; s[1] += b; s[2] += c;
        s[3] += a * a; s[4] += b * b; s[5] += c * c;
        s[6] += a * b; s[7] += a * c; s[8] += b * c;
    }
#pragma unroll
    for (int i = 0; i < 9; i++)
#pragma unroll
        for (int o = 16; o; o >>= 1) s[i] += __shfl_xor_sync(0xFFFFFFFFu, s[i], o);
    __shared__ float sh[8][9];
    int wid = threadIdx.x >> 5, lane = threadIdx.x & 31;
    if (lane == 0)
#pragma unroll
        for (int i = 0; i < 9; i++) sh[wid][i] = s[i];
    __syncthreads();
    if (threadIdx.x < 9) {
        float a = 0.f;
#pragma unroll
        for (int w = 0; w < 8; w++) a += sh[w][threadIdx.x];
        atomicAdd(&mom[threadIdx.x], a);
    }
}

__global__ void bnfin1_kernel(const float* __restrict__ mom,
                              const float* __restrict__ w1, const float* __restrict__ b1,
                              const float* __restrict__ g, const float* __restrict__ bb,
                              float* __restrict__ scale, float* __restrict__ shift) {
    int c = threadIdx.x;
    float inv = 1.0f / (float)M1;
    float m0 = mom[0] * inv, m1 = mom[1] * inv, m2 = mom[2] * inv;
    float C00 = mom[3] * inv - m0 * m0;
    float C11 = mom[4] * inv - m1 * m1;
    float C22 = mom[5] * inv - m2 * m2;
    float C01 = mom[6] * inv - m0 * m1;
    float C02 = mom[7] * inv - m0 * m2;
    float C12 = mom[8] * inv - m1 * m2;
    float w0 = w1[c], wv1 = w1[128 + c], wv2 = w1[256 + c];
    float var = C00 * w0 * w0 + C11 * wv1 * wv1 + C22 * wv2 * wv2 +
                2.0f * (C01 * w0 * wv1 + C02 * w0 * wv2 + C12 * wv1 * wv2);
    float mean = m0 * w0 + m1 * wv1 + m2 * wv2 + b1[c];
    float r = rsqrtf(var + 1e-5f);
    float sc = g[c] * r;
    scale[c] = sc;
    shift[c] = bb[c] - mean * sc;
}

__global__ void bnfin_kernel(const float* __restrict__ s1, const float* __restrict__ s2,
                             float invM, const float* __restrict__ g, const float* __restrict__ b,
                             float* __restrict__ scale, float* __restrict__ shift) {
    int c = threadIdx.x;
    float mean = s1[c] * invM;
    float var = s2[c] * invM - mean * mean;
    float r = rsqrtf(var + 1e-5f);
    float sc = g[c] * r;
    scale[c] = sc;
    shift[c] = b[c] - mean * sc;
}

// ---------------- layernorm: one warp per 384-col row ----------------
__global__ void __launch_bounds__(256) ln_kernel(const float* __restrict__ in,
                                                 float* __restrict__ out,
                                                 const float* __restrict__ gg,
                                                 const float* __restrict__ bb) {
    const int warp = threadIdx.x >> 5, lane = threadIdx.x & 31;
    const size_t row = (size_t)blockIdx.x * 8 + warp;
    const float* p = in + row * 384;
    float v[12];
#pragma unroll
    for (int j = 0; j < 3; j++)
        *(float4*)&v[j * 4] = *(const float4*)&p[lane * 4 + j * 128];
    float s = 0.f;
#pragma unroll
    for (int j = 0; j < 12; j++) s += v[j];
#pragma unroll
    for (int o = 16; o; o >>= 1) s += __shfl_xor_sync(0xFFFFFFFFu, s, o);
    float mean = s * (1.0f / 384.0f);
    float q = 0.f;
#pragma unroll
    for (int j = 0; j < 12; j++) { v[j] -= mean; q += v[j] * v[j]; }
#pragma unroll
    for (int o = 16; o; o >>= 1) q += __shfl_xor_sync(0xFFFFFFFFu, q, o);
    float rstd = rsqrtf(q * (1.0f / 384.0f) + 1e-5f);
    float* op = out + row * 384;
#pragma unroll
    for (int j = 0; j < 3; j++) {
        float4 gv = *(const float4*)&gg[lane * 4 + j * 128];
        float4 bv = *(const float4*)&bb[lane * 4 + j * 128];
        float4 o4;
        o4.x = v[j * 4 + 0] * rstd * gv.x + bv.x;
        o4.y = v[j * 4 + 1] * rstd * gv.y + bv.y;
        o4.z = v[j * 4 + 2] * rstd * gv.z + bv.z;
        o4.w = v[j * 4 + 3] * rstd * gv.w + bv.w;
        *(float4*)&op[lane * 4 + j * 128] = o4;
    }
}

// xin = x + pos; out = LN(xin); one warp per row
__global__ void __launch_bounds__(256) ln_add_kernel(const float* __restrict__ x,
                                                     const float* __restrict__ pos,
                                                     float* __restrict__ xin,
                                                     float* __restrict__ out,
                                                     const float* __restrict__ gg,
                                                     const float* __restrict__ bb) {
    const int warp = threadIdx.x >> 5, lane = threadIdx.x & 31;
    const size_t row = (size_t)blockIdx.x * 8 + warp;
    const float* p = x + row * 384;
    const float* pp = pos + row * 384;
    float v[12];
#pragma unroll
    for (int j = 0; j < 3; j++) {
        float4 a = *(const float4*)&p[lane * 4 + j * 128];
        float4 b = *(const float4*)&pp[lane * 4 + j * 128];
        a.x += b.x; a.y += b.y; a.z += b.z; a.w += b.w;
        *(float4*)&v[j * 4] = a;
        *(float4*)&xin[row * 384 + lane * 4 + j * 128] = a;
    }
    float s = 0.f;
#pragma unroll
    for (int j = 0; j < 12; j++) s += v[j];
#pragma unroll
    for (int o = 16; o; o >>= 1) s += __shfl_xor_sync(0xFFFFFFFFu, s, o);
    float mean = s * (1.0f / 384.0f);
    float q = 0.f;
#pragma unroll
    for (int j = 0; j < 12; j++) { v[j] -= mean; q += v[j] * v[j]; }
#pragma unroll
    for (int o = 16; o; o >>= 1) q += __shfl_xor_sync(0xFFFFFFFFu, q, o);
    float rstd = rsqrtf(q * (1.0f / 384.0f) + 1e-5f);
    float* op = out + row * 384;
#pragma unroll
    for (int j = 0; j < 3; j++) {
        float4 gv = *(const float4*)&gg[lane * 4 + j * 128];
        float4 bv = *(const float4*)&bb[lane * 4 + j * 128];
        float4 o4;
        o4.x = v[j * 4 + 0] * rstd * gv.x + bv.x;
        o4.y = v[j * 4 + 1] * rstd * gv.y + bv.y;
        o4.z = v[j * 4 + 2] * rstd * gv.z + bv.z;
        o4.w = v[j * 4 + 3] * rstd * gv.w + bv.w;
        *(float4*)&op[lane * 4 + j * 128] = o4;
    }
}

// ---------------- pos embed ----------------
__global__ void __launch_bounds__(128) pos_kernel(const float* __restrict__ ctr,
                                                  const float* __restrict__ pw1,
                                                  const float* __restrict__ pb1,
                                                  const float* __restrict__ pw2,
                                                  const float* __restrict__ pb2,
                                                  float* __restrict__ pos) {
    int row = blockIdx.x;
    int tid = threadIdx.x;
    float cx = ctr[row * 3], cy = ctr[row * 3 + 1], cz = ctr[row * 3 + 2];
    __shared__ float t[128];
    float u = cx * pw1[tid] + cy * pw1[128 + tid] + cz * pw1[256 + tid] + pb1[tid];
    t[tid] = gelu_f(u);
    __syncthreads();
    for (int j = tid; j < 384; j += 128) {
        float s = pb2[j];
#pragma unroll 8
        for (int k = 0; k < 128; k++) s = fmaf(t[k], pw2[k * 384 + j], s);
        pos[(size_t)row * 384 + j] = s;
    }
}

// ---------------- host ----------------
extern "C" void kernel_launch(void* const* d_in, const int* in_sizes, int n_in,
                              void* d_out, int out_size) {
    const float* pts   = (const float*)d_in[0];
    const float* w1    = (const float*)d_in[1];
    const float* b1    = (const float*)d_in[2];
    const float* bn1g  = (const float*)d_in[3];
    const float* bn1b  = (const float*)d_in[4];
    const float* w2    = (const float*)d_in[5];
    const float* b2    = (const float*)d_in[6];
    const float* w3    = (const float*)d_in[7];
    const float* b3    = (const float*)d_in[8];
    const float* bn2g  = (const float*)d_in[9];
    const float* bn2b  = (const float*)d_in[10];
    const float* w4    = (const float*)d_in[11];
    const float* b4    = (const float*)d_in[12];
    const float* pw1   = (const float*)d_in[13];
    const float* pb1   = (const float*)d_in[14];
    const float* pw2   = (const float*)d_in[15];
    const float* pb2   = (const float*)d_in[16];
    const float* ln1g  = (const float*)d_in[17];
    const float* ln1b  = (const float*)d_in[18];
    const float* qkvw  = (const float*)d_in[19];
    const float* projw = (const float*)d_in[20];
    const float* projb = (const float*)d_in[21];
    const float* ln2g  = (const float*)d_in[22];
    const float* ln2b  = (const float*)d_in[23];
    const float* fc1w  = (const float*)d_in[24];
    const float* fc1b  = (const float*)d_in[25];
    const float* fc2w  = (const float*)d_in[26];
    const float* fc2b  = (const float*)d_in[27];
    const float* nfg   = (const float*)d_in[28];
    const float* nfb   = (const float*)d_in[29];

    static float* S = nullptr;
    if (!S) {
        cudaGetSymbolAddress((void**)&S, g_scratch);
        cudaFuncSetAttribute(mmagemm_kernel<3, 5, 128>, cudaFuncAttributeMaxDynamicSharedMemorySize, GE_SMEM);
        cudaFuncSetAttribute(mmagemm_kernel<0, 0, 128>, cudaFuncAttributeMaxDynamicSharedMemorySize, GE_SMEM);
        cudaFuncSetAttribute(mmagemm_kernel<0, 6, 128>, cudaFuncAttributeMaxDynamicSharedMemorySize, GE_SMEM);
        cudaFuncSetAttribute(mmagemm_kernel<1, 4, 128>, cudaFuncAttributeMaxDynamicSharedMemorySize, GE_SMEM);
        cudaFuncSetAttribute(mmagemm_kernel<0, 2, 128>, cudaFuncAttributeMaxDynamicSharedMemorySize, GE_SMEM);
        cudaFuncSetAttribute(mmagemm_kernel<0, 1, 64>,  cudaFuncAttributeMaxDynamicSharedMemorySize, GE_SMEM64);
        cudaFuncSetAttribute(attn_qk_mma, cudaFuncAttributeMaxDynamicSharedMemorySize, QK_SMEM);
        cudaFuncSetAttribute(attn_av_mma, cudaFuncAttributeMaxDynamicSharedMemorySize, AV_SMEM);
    }

    uint32_t* PK = (uint32_t*)(S + O_PK);
    float* f    = S + O_F;
    float* h3   = S + O_H3;
    float* fg   = S + O_FG;
    float* x    = S + O_X;
    float* xin  = S + O_XIN;
    float* hln  = S + O_HLN;
    float* ob   = S + O_OB;
    float* pos  = S + O_POS;
    float* qkv  = S + O_QKV;
    float* sc   = S + O_SC;
    float* ff   = S + O_FF;
    float* ctr  = S + O_CTR;
    float* st   = S + O_ST;
    float* mom = st;
    float* s1b = st + 256, *s2b = st + 768;
    float* scale1 = st + 1280, *shift1 = st + 1408;
    float* scale2 = st + 1536, *shift2 = st + 2048;

    float* out     = (float*)d_out;
    float* out_x   = out;
    float* out_nbr = out + (size_t)BGc * 384;
    float* out_ctr = out_nbr + (size_t)BGc * NK * 3;

    zero_kernel<<<16, 256>>>(st, 4096);

    WJobs jobs;
    jobs.j[0] = { qkvw,  (uint32_t)PK_QKV_HI,  (uint32_t)PK_QKV_LO,  384, 1152, 12 };
    jobs.j[1] = { fc1w,  (uint32_t)PK_FC1_HI,  (uint32_t)PK_FC1_LO,  384, 1536, 12 };
    jobs.j[2] = { fc2w,  (uint32_t)PK_FC2_HI,  (uint32_t)PK_FC2_LO,  1536, 384, 12 };
    jobs.j[3] = { projw, (uint32_t)PK_PROJ_HI, (uint32_t)PK_PROJ_LO, 384, 384, 12 };
    jobs.j[4] = { w2,    (uint32_t)PK_W2_HI,   (uint32_t)PK_W2_LO,   128, 256, 1 };
    jobs.j[5] = { w3,    (uint32_t)PK_W3_HI,   (uint32_t)PK_W3_LO,   512, 512, 1 };
    jobs.j[6] = { w4,    (uint32_t)PK_W4_HI,   (uint32_t)PK_W4_LO,   512, 384, 1 };
    wprep_all_kernel<<<dim3(144, 12, 7), 256>>>(jobs, PK);

    fps_kernel<<<NB, 1024>>>(pts, ctr, out_ctr);
    knn_kernel<<<BGc, 256>>>(pts, ctr, out_nbr);

    moments_kernel<<<256, 256>>>(out_nbr, mom);
    bnfin1_kernel<<<1, 128>>>(mom, w1, b1, bn1g, bn1b, scale1, shift1);

    mmagemm_kernel<3, 5, 128><<<dim3(2, 2048), 256, GE_SMEM>>>(
        out_nbr, PK + PK_W2_HI, PK + PK_W2_LO, b2, nullptr, f,
        M1, 256, 128, scale1, shift1, fg, w1, b1);
    mmagemm_kernel<0, 0, 128><<<dim3(4, 64), 256, GE_SMEM>>>(
        fg, PK + PK_W3_HI, PK + PK_W3_LO, b3, nullptr, ff,
        BGc, 512, 256, nullptr, nullptr, nullptr, nullptr, nullptr);
    mmagemm_kernel<0, 6, 128><<<dim3(4, 2048), 256, GE_SMEM>>>(
        f, PK + PK_W3_HI + 8 * 512 * 16, PK + PK_W3_LO + 8 * 512 * 16, nullptr, ff, h3,
        M1, 512, 256, s1b, s2b, nullptr, nullptr, nullptr);
    bnfin_kernel<<<1, 512>>>(s1b, s2b, 1.0f / (float)M1, bn2g, bn2b, scale2, shift2);
    mmagemm_kernel<1, 4, 128><<<dim3(3, 2048), 256, GE_SMEM>>>(
        h3, PK + PK_W4_HI, PK + PK_W4_LO, b4, nullptr, x,
        M1, 384, 512, scale2, shift2, nullptr, nullptr, nullptr);

    pos_kernel<<<BGc, 128>>>(ctr, pw1, pb1, pw2, pb2, pos);

    for (int l = 0; l < NL; l++) {
        ln_add_kernel<<<BGc / 8, 256>>>(x, pos, xin, hln, ln1g + l * 384, ln1b + l * 384);
        mmagemm_kernel<0, 0, 128><<<dim3(9, 64), 256, GE_SMEM>>>(
            hln, PK + PK_QKV_HI + (size_t)l * (384 * 1152 / 2),
            PK + PK_QKV_LO + (size_t)l * (384 * 1152 / 2), nullptr, nullptr, qkv,
            BGc, 1152, 384, nullptr, nullptr, nullptr, nullptr, nullptr);
        attn_qk_mma<<<dim3(4, 4, NB * NH), 256, QK_SMEM>>>(qkv, sc);
        softmax_kernel<<<NB * NH * 512 / 8, 256>>>(sc);
        attn_av_mma<<<dim3(4, NB * NH), 256, AV_SMEM>>>(sc, qkv, ob);
        mmagemm_kernel<0, 1, 64><<<dim3(6, 64), 256, GE_SMEM64>>>(
            ob, PK + PK_PROJ_HI + (size_t)l * (384 * 384 / 2),
            PK + PK_PROJ_LO + (size_t)l * (384 * 384 / 2), projb + l * 384, xin, x,
            BGc, 384, 384, nullptr, nullptr, nullptr, nullptr, nullptr);
        ln_kernel<<<BGc / 8, 256>>>(x, hln, ln2g + l * 384, ln2b + l * 384);
        mmagemm_kernel<0, 2, 128><<<dim3(12, 64), 256, GE_SMEM>>>(
            hln, PK + PK_FC1_HI + (size_t)l * (384 * 1536 / 2),
            PK + PK_FC1_LO + (size_t)l * (384 * 1536 / 2), fc1b + l * 1536, nullptr, ff,
            BGc, 1536, 384, nullptr, nullptr, nullptr, nullptr, nullptr);
        mmagemm_kernel<0, 1, 64><<<dim3(6, 64), 256, GE_SMEM64>>>(
            ff, PK + PK_FC2_HI + (size_t)l * (1536 * 384 / 2),
            PK + PK_FC2_LO + (size_t)l * (1536 * 384 / 2), fc2b + l * 384, x, x,
            BGc, 384, 1536, nullptr, nullptr, nullptr, nullptr, nullptr);
    }
    ln_kernel<<<BGc / 8, 256>>>(x, out_x, nfg, nfb);
}